// round 1
// baseline (speedup 1.0000x reference)
#include <cuda_runtime.h>
#include <cuda_bf16.h>
#include <math.h>

// Problem constants
#define BATCH 16
#define NX 512
#define NY 1024
#define DMODEL 256
#define NHEAD 4
#define DK 64
#define MX (BATCH * NX)   // 8192
#define MY (BATCH * NY)   // 16384

// Output layout offsets (x2, y2, gx, gy flattened in order)
#define OFF_X2 0
#define OFF_Y2 (MX * DMODEL)                  // 2097152
#define OFF_GX (OFF_Y2 + MY * DMODEL)         // 6291456
#define OFF_GY (OFF_GX + MX)                  // 6299648

// ---------------------------------------------------------------------------
// Scratch (static device globals; no allocation allowed)
// ---------------------------------------------------------------------------
__device__ float g_qx[MX * DMODEL];
__device__ float g_kx[MX * DMODEL];
__device__ float g_vx[MX * DMODEL];
__device__ float g_qy[MY * DMODEL];
__device__ float g_ky[MY * DMODEL];
__device__ float g_vy[MY * DMODEL];
__device__ float g_ax[MX * DMODEL];   // attention out (x-query)
__device__ float g_ay[MY * DMODEL];   // attention out (y-query)
__device__ float g_t1[MY * DMODEL];   // temp (oproj / ff), max size
__device__ float g_x2a[MX * DMODEL];
__device__ float g_y2a[MY * DMODEL];
__device__ float g_lgx[MX];
__device__ float g_lgy[MY];

// ---------------------------------------------------------------------------
// GEMM: C[M,N] = act(A[M,K] @ W[N,K]^T + bias)
// BM=128, BN=64, BK=16, 256 threads, 8x4 microtile.
// ---------------------------------------------------------------------------
#define BM 128
#define BN 64
#define BK 16

template <int ACT>  // 0 = none, 1 = silu
__global__ __launch_bounds__(256) void gemm_kernel(
    const float* __restrict__ A, const float* __restrict__ W,
    const float* __restrict__ bias, float* __restrict__ C,
    int M, int N, int K)
{
    __shared__ float As[BK][BM];
    __shared__ float Bs[BK][BN];

    const int tid = threadIdx.x;
    const int bm = blockIdx.y * BM;
    const int bn = blockIdx.x * BN;
    const int ty = tid >> 4;          // 0..15
    const int tx = tid & 15;          // 0..15
    const int m0 = ty * 8;
    const int n0 = tx * 4;

    float acc[8][4] = {};

    for (int k0 = 0; k0 < K; k0 += BK) {
        // A tile: 128 x 16 = 512 float4, 2 per thread
        #pragma unroll
        for (int i = 0; i < 2; i++) {
            int idx = tid + i * 256;        // 0..511
            int r   = idx >> 2;             // 0..127
            int c4  = idx & 3;              // 0..3
            float4 a = *(const float4*)&A[(size_t)(bm + r) * K + k0 + c4 * 4];
            As[c4 * 4 + 0][r] = a.x;
            As[c4 * 4 + 1][r] = a.y;
            As[c4 * 4 + 2][r] = a.z;
            As[c4 * 4 + 3][r] = a.w;
        }
        // B tile: 64 x 16 = 256 float4, 1 per thread
        {
            int r  = tid >> 2;              // 0..63 (n)
            int c4 = tid & 3;
            float4 b = *(const float4*)&W[(size_t)(bn + r) * K + k0 + c4 * 4];
            Bs[c4 * 4 + 0][r] = b.x;
            Bs[c4 * 4 + 1][r] = b.y;
            Bs[c4 * 4 + 2][r] = b.z;
            Bs[c4 * 4 + 3][r] = b.w;
        }
        __syncthreads();

        #pragma unroll
        for (int k = 0; k < BK; k++) {
            float4 a0 = *(const float4*)&As[k][m0];
            float4 a1 = *(const float4*)&As[k][m0 + 4];
            float4 b  = *(const float4*)&Bs[k][n0];
            float av[8] = {a0.x, a0.y, a0.z, a0.w, a1.x, a1.y, a1.z, a1.w};
            float bv[4] = {b.x, b.y, b.z, b.w};
            #pragma unroll
            for (int i = 0; i < 8; i++)
                #pragma unroll
                for (int j = 0; j < 4; j++)
                    acc[i][j] += av[i] * bv[j];
        }
        __syncthreads();
    }

    float bb[4] = {0.f, 0.f, 0.f, 0.f};
    if (bias) {
        #pragma unroll
        for (int j = 0; j < 4; j++) bb[j] = bias[bn + n0 + j];
    }
    #pragma unroll
    for (int i = 0; i < 8; i++) {
        float4 c;
        float cv[4];
        #pragma unroll
        for (int j = 0; j < 4; j++) {
            float v = acc[i][j] + bb[j];
            if (ACT == 1) v = v / (1.0f + __expf(-v));   // silu
            cv[j] = v;
        }
        c.x = cv[0]; c.y = cv[1]; c.z = cv[2]; c.w = cv[3];
        *(float4*)&C[(size_t)(bm + m0 + i) * N + bn + n0] = c;
    }
}

// ---------------------------------------------------------------------------
// Evidential gate: per token, h = t @ gW^T + gb (4 outputs), then NIG gate.
// Writes g to g_out and log(g) to lg_out.
// One warp per token, 8 tokens per 256-thread block.
// ---------------------------------------------------------------------------
__device__ __forceinline__ float softplusf(float x) {
    return (x > 20.f) ? x : log1pf(expf(x));
}

__global__ __launch_bounds__(256) void gate_kernel(
    const float* __restrict__ t, const float* __restrict__ gW,
    const float* __restrict__ gb, float* __restrict__ g_out,
    float* __restrict__ lg_out, int ntok)
{
    const int warp = threadIdx.x >> 5;
    const int lane = threadIdx.x & 31;
    const int token = blockIdx.x * 8 + warp;
    if (token >= ntok) return;

    const float* tp = t + (size_t)token * DMODEL;
    float p0 = 0.f, p1 = 0.f, p2 = 0.f, p3 = 0.f;
    #pragma unroll
    for (int i = 0; i < 8; i++) {
        int d = lane + i * 32;
        float xv = tp[d];
        p0 += xv * gW[0 * DMODEL + d];
        p1 += xv * gW[1 * DMODEL + d];
        p2 += xv * gW[2 * DMODEL + d];
        p3 += xv * gW[3 * DMODEL + d];
    }
    #pragma unroll
    for (int o = 16; o > 0; o >>= 1) {
        p0 += __shfl_xor_sync(0xffffffffu, p0, o);
        p1 += __shfl_xor_sync(0xffffffffu, p1, o);
        p2 += __shfl_xor_sync(0xffffffffu, p2, o);
        p3 += __shfl_xor_sync(0xffffffffu, p3, o);
    }
    if (lane == 0) {
        float mu    = p0 + gb[0];
        float v     = softplusf(p1 + gb[1]) + 1e-6f;
        float alpha = softplusf(p2 + gb[2]) + 1.0f + 1e-6f;
        float beta  = softplusf(p3 + gb[3]) + 1e-6f;
        float var_ep = beta / (v * (alpha - 1.0f));
        float g = (1.0f / (1.0f + expf(-mu))) * expf(-2.0f * var_ep);
        g = fmaxf(g, 1e-6f);
        g_out[token]  = g;
        lg_out[token] = logf(g);
    }
}

// ---------------------------------------------------------------------------
// Flash-style gated cross attention.
// q: [B, Tq, 256] (head h columns h*64..), k/v: [B, Tk, 256], lgk: [B, Tk].
// One thread per query; blocks of 128 queries per (b, h).
// lg_q dropped (constant over the softmax axis). Mask all-true -> ignored.
// ---------------------------------------------------------------------------
#define KT 32

__global__ __launch_bounds__(128) void attn_kernel(
    const float* __restrict__ q, const float* __restrict__ k,
    const float* __restrict__ v, const float* __restrict__ lgk,
    float* __restrict__ out, int Tq, int Tk)
{
    __shared__ float4 ks4[KT * 16];
    __shared__ float4 vs4[KT * 16];
    __shared__ float  lgs[KT];

    const int tid = threadIdx.x;
    const int b = blockIdx.z;
    const int h = blockIdx.y;
    const int qi = blockIdx.x * 128 + tid;
    if (qi >= Tq) return;

    const float scale = 0.125f;  // 1/sqrt(64)

    float qreg[DK];
    {
        const float4* qp = (const float4*)(q + ((size_t)(b * Tq + qi) * DMODEL + h * DK));
        #pragma unroll
        for (int i = 0; i < 16; i++) {
            float4 t = qp[i];
            qreg[4 * i + 0] = t.x; qreg[4 * i + 1] = t.y;
            qreg[4 * i + 2] = t.z; qreg[4 * i + 3] = t.w;
        }
    }

    float m = -INFINITY, l = 0.f;
    float acc[DK];
    #pragma unroll
    for (int d = 0; d < DK; d++) acc[d] = 0.f;

    for (int kb = 0; kb < Tk; kb += KT) {
        // load k/v tile (KT x 64 each) = 512 float4 each, 4 per thread
        #pragma unroll
        for (int i = 0; i < 4; i++) {
            int idx = tid + i * 128;        // 0..511
            int j = idx >> 4;               // key in tile
            int d4 = idx & 15;
            size_t base = (size_t)(b * Tk + kb + j) * 64 + h * 16 + d4;  // float4 units
            ks4[idx] = ((const float4*)k)[base];
            vs4[idx] = ((const float4*)v)[base];
        }
        if (tid < KT) lgs[tid] = lgk[b * Tk + kb + tid];
        __syncthreads();

        float snew[KT];
        float mt = m;
        #pragma unroll
        for (int j = 0; j < KT; j++) {
            float s = 0.f;
            #pragma unroll
            for (int d4 = 0; d4 < 16; d4++) {
                float4 kk = ks4[j * 16 + d4];
                s += qreg[4 * d4 + 0] * kk.x + qreg[4 * d4 + 1] * kk.y
                   + qreg[4 * d4 + 2] * kk.z + qreg[4 * d4 + 3] * kk.w;
            }
            s = s * scale + lgs[j];
            snew[j] = s;
            mt = fmaxf(mt, s);
        }
        float corr = __expf(m - mt);
        l *= corr;
        #pragma unroll
        for (int d = 0; d < DK; d++) acc[d] *= corr;
        #pragma unroll
        for (int j = 0; j < KT; j++) {
            float p = __expf(snew[j] - mt);
            l += p;
            #pragma unroll
            for (int d4 = 0; d4 < 16; d4++) {
                float4 vv = vs4[j * 16 + d4];
                acc[4 * d4 + 0] += p * vv.x;
                acc[4 * d4 + 1] += p * vv.y;
                acc[4 * d4 + 2] += p * vv.z;
                acc[4 * d4 + 3] += p * vv.w;
            }
        }
        m = mt;
        __syncthreads();
    }

    float invl = 1.0f / l;
    float4* op = (float4*)(out + ((size_t)(b * Tq + qi) * DMODEL + h * DK));
    #pragma unroll
    for (int d4 = 0; d4 < 16; d4++) {
        float4 o;
        o.x = acc[4 * d4 + 0] * invl;
        o.y = acc[4 * d4 + 1] * invl;
        o.z = acc[4 * d4 + 2] * invl;
        o.w = acc[4 * d4 + 3] * invl;
        op[d4] = o;
    }
}

// ---------------------------------------------------------------------------
// Fused residual add + LayerNorm: out = LN(a + b) * gamma + beta
// One warp per token (d=256 -> 8 elems/lane), 8 tokens per block.
// ---------------------------------------------------------------------------
__global__ __launch_bounds__(256) void add_ln_kernel(
    const float* __restrict__ a, const float* __restrict__ b,
    const float* __restrict__ gamma, const float* __restrict__ beta,
    float* __restrict__ out, int ntok)
{
    const int warp = threadIdx.x >> 5;
    const int lane = threadIdx.x & 31;
    const int token = blockIdx.x * 8 + warp;
    if (token >= ntok) return;

    const float* pa = a + (size_t)token * DMODEL;
    const float* pb = b + (size_t)token * DMODEL;
    float v[8];
    float s = 0.f, s2 = 0.f;
    #pragma unroll
    for (int i = 0; i < 8; i++) {
        int d = lane + i * 32;
        float x = pa[d] + pb[d];
        v[i] = x;
        s += x;
        s2 += x * x;
    }
    #pragma unroll
    for (int o = 16; o > 0; o >>= 1) {
        s  += __shfl_xor_sync(0xffffffffu, s, o);
        s2 += __shfl_xor_sync(0xffffffffu, s2, o);
    }
    float mean = s * (1.0f / DMODEL);
    float var  = s2 * (1.0f / DMODEL) - mean * mean;
    float inv  = rsqrtf(var + 1e-5f);
    float* po = out + (size_t)token * DMODEL;
    #pragma unroll
    for (int i = 0; i < 8; i++) {
        int d = lane + i * 32;
        po[d] = (v[i] - mean) * inv * gamma[d] + beta[d];
    }
}

// ---------------------------------------------------------------------------
// Launch
// ---------------------------------------------------------------------------
extern "C" void kernel_launch(void* const* d_in, const int* in_sizes, int n_in,
                              void* d_out, int out_size)
{
    const float* x    = (const float*)d_in[0];
    const float* y    = (const float*)d_in[1];
    // d_in[2], d_in[3]: x_mask / y_mask (all-true; unused)
    const float* Wqx  = (const float*)d_in[4];
    const float* Wkx  = (const float*)d_in[5];
    const float* Wvx  = (const float*)d_in[6];
    const float* Wqy  = (const float*)d_in[7];
    const float* Wky  = (const float*)d_in[8];
    const float* Wvy  = (const float*)d_in[9];
    const float* gWx  = (const float*)d_in[10];
    const float* gbx  = (const float*)d_in[11];
    const float* gWy  = (const float*)d_in[12];
    const float* gby  = (const float*)d_in[13];
    const float* Wox  = (const float*)d_in[14];
    const float* Woy  = (const float*)d_in[15];
    const float* lnxg = (const float*)d_in[16];
    const float* lnxb = (const float*)d_in[17];
    const float* lnyg = (const float*)d_in[18];
    const float* lnyb = (const float*)d_in[19];
    const float* ffxW = (const float*)d_in[20];
    const float* ffxb = (const float*)d_in[21];
    const float* ffyW = (const float*)d_in[22];
    const float* ffyb = (const float*)d_in[23];
    float* out = (float*)d_out;

    float *qx, *kx, *vx, *qy, *ky, *vy, *ax, *ay, *t1, *x2a, *y2a, *lgx, *lgy;
    cudaGetSymbolAddress((void**)&qx,  g_qx);
    cudaGetSymbolAddress((void**)&kx,  g_kx);
    cudaGetSymbolAddress((void**)&vx,  g_vx);
    cudaGetSymbolAddress((void**)&qy,  g_qy);
    cudaGetSymbolAddress((void**)&ky,  g_ky);
    cudaGetSymbolAddress((void**)&vy,  g_vy);
    cudaGetSymbolAddress((void**)&ax,  g_ax);
    cudaGetSymbolAddress((void**)&ay,  g_ay);
    cudaGetSymbolAddress((void**)&t1,  g_t1);
    cudaGetSymbolAddress((void**)&x2a, g_x2a);
    cudaGetSymbolAddress((void**)&y2a, g_y2a);
    cudaGetSymbolAddress((void**)&lgx, g_lgx);
    cudaGetSymbolAddress((void**)&lgy, g_lgy);

    const dim3 gemm_blk(256);
    const dim3 gemm_grid_x(DMODEL / BN, MX / BM);   // (4, 64)
    const dim3 gemm_grid_y(DMODEL / BN, MY / BM);   // (4, 128)

    // Gates (g to d_out, log g to scratch)
    gate_kernel<<<MX / 8, 256>>>(x, gWx, gbx, out + OFF_GX, lgx, MX);
    gate_kernel<<<MY / 8, 256>>>(y, gWy, gby, out + OFF_GY, lgy, MY);

    // QKV projections
    gemm_kernel<0><<<gemm_grid_x, gemm_blk>>>(x, Wqx, nullptr, qx, MX, DMODEL, DMODEL);
    gemm_kernel<0><<<gemm_grid_x, gemm_blk>>>(x, Wkx, nullptr, kx, MX, DMODEL, DMODEL);
    gemm_kernel<0><<<gemm_grid_x, gemm_blk>>>(x, Wvx, nullptr, vx, MX, DMODEL, DMODEL);
    gemm_kernel<0><<<gemm_grid_y, gemm_blk>>>(y, Wqy, nullptr, qy, MY, DMODEL, DMODEL);
    gemm_kernel<0><<<gemm_grid_y, gemm_blk>>>(y, Wky, nullptr, ky, MY, DMODEL, DMODEL);
    gemm_kernel<0><<<gemm_grid_y, gemm_blk>>>(y, Wvy, nullptr, vy, MY, DMODEL, DMODEL);

    // Attention: x queries attend to y; y queries attend to x
    attn_kernel<<<dim3(NX / 128, NHEAD, BATCH), 128>>>(qx, ky, vy, lgy, ax, NX, NY);
    attn_kernel<<<dim3(NY / 128, NHEAD, BATCH), 128>>>(qy, kx, vx, lgx, ay, NY, NX);

    // x branch: oproj -> add+LN -> FF(silu) -> add+LN -> out
    gemm_kernel<0><<<gemm_grid_x, gemm_blk>>>(ax, Wox, nullptr, t1, MX, DMODEL, DMODEL);
    add_ln_kernel<<<MX / 8, 256>>>(x, t1, lnxg, lnxb, x2a, MX);
    gemm_kernel<1><<<gemm_grid_x, gemm_blk>>>(x2a, ffxW, ffxb, t1, MX, DMODEL, DMODEL);
    add_ln_kernel<<<MX / 8, 256>>>(x2a, t1, lnxg, lnxb, out + OFF_X2, MX);

    // y branch
    gemm_kernel<0><<<gemm_grid_y, gemm_blk>>>(ay, Woy, nullptr, t1, MY, DMODEL, DMODEL);
    add_ln_kernel<<<MY / 8, 256>>>(y, t1, lnyg, lnyb, y2a, MY);
    gemm_kernel<1><<<gemm_grid_y, gemm_blk>>>(y2a, ffyW, ffyb, t1, MY, DMODEL, DMODEL);
    add_ln_kernel<<<MY / 8, 256>>>(y2a, t1, lnyg, lnyb, out + OFF_Y2, MY);
}

// round 3
// speedup vs baseline: 1.1462x; 1.1462x over previous
#include <cuda_runtime.h>
#include <cuda_bf16.h>
#include <math.h>
#include <stdint.h>

// ---------------- problem constants ----------------
#define BATCH 16
#define NX 512
#define NY 1024
#define DMODEL 256
#define NHEAD 4
#define DK 64
#define MX (BATCH * NX)   // 8192
#define MY (BATCH * NY)   // 16384

#define OFF_X2 0
#define OFF_Y2 (MX * DMODEL)
#define OFF_GX (OFF_Y2 + MY * DMODEL)
#define OFF_GY (OFF_GX + MX)

// ---------------- scratch ----------------
__device__ float g_qx[MX * DMODEL];
__device__ float g_kx[MX * DMODEL];
__device__ float g_vx[MX * DMODEL];
__device__ float g_qy[MY * DMODEL];
__device__ float g_ky[MY * DMODEL];
__device__ float g_vy[MY * DMODEL];
__device__ float g_t1[MY * DMODEL];
__device__ float g_x2a[MX * DMODEL];
__device__ float g_y2a[MY * DMODEL];
__device__ float g_lgx[MX];
__device__ float g_lgy[MY];

__device__ __nv_bfloat16 g_xhi[MX * DMODEL];
__device__ __nv_bfloat16 g_xlo[MX * DMODEL];
__device__ __nv_bfloat16 g_yhi[MY * DMODEL];
__device__ __nv_bfloat16 g_ylo[MY * DMODEL];
__device__ __nv_bfloat16 g_axhi[MX * DMODEL];
__device__ __nv_bfloat16 g_axlo[MX * DMODEL];
__device__ __nv_bfloat16 g_ayhi[MY * DMODEL];
__device__ __nv_bfloat16 g_aylo[MY * DMODEL];
__device__ __nv_bfloat16 g_x2ahi[MX * DMODEL];
__device__ __nv_bfloat16 g_x2alo[MX * DMODEL];
__device__ __nv_bfloat16 g_y2ahi[MY * DMODEL];
__device__ __nv_bfloat16 g_y2alo[MY * DMODEL];
__device__ __nv_bfloat16 g_whi[10 * DMODEL * DMODEL];
__device__ __nv_bfloat16 g_wlo[10 * DMODEL * DMODEL];

// ---------------- helpers ----------------
__device__ __forceinline__ uint32_t smem_u32(const void* p) {
    uint32_t a;
    asm("{ .reg .u64 t; cvta.to.shared.u64 t, %1; cvt.u32.u64 %0, t; }"
        : "=r"(a) : "l"(p));
    return a;
}

#define SMEM_SWIZZLE_128B(off) ((off) ^ (((off) >> 3) & 0x70))

__device__ __forceinline__ void ldsm_x4(uint32_t* r, uint32_t addr) {
    asm volatile("ldmatrix.sync.aligned.m8n8.x4.shared.b16 {%0,%1,%2,%3}, [%4];"
                 : "=r"(r[0]), "=r"(r[1]), "=r"(r[2]), "=r"(r[3]) : "r"(addr));
}

__device__ __forceinline__ void mma16816(float* d, const uint32_t* a, const uint32_t* b) {
    asm volatile(
        "mma.sync.aligned.m16n8k16.row.col.f32.bf16.bf16.f32 "
        "{%0,%1,%2,%3}, {%4,%5,%6,%7}, {%8,%9}, {%0,%1,%2,%3};"
        : "+f"(d[0]), "+f"(d[1]), "+f"(d[2]), "+f"(d[3])
        : "r"(a[0]), "r"(a[1]), "r"(a[2]), "r"(a[3]), "r"(b[0]), "r"(b[1]));
}

__device__ __forceinline__ void split2(float v, __nv_bfloat16& hi, __nv_bfloat16& lo) {
    hi = __float2bfloat16(v);
    lo = __float2bfloat16(v - __bfloat162float(hi));
}

// ---------------- conversion kernels ----------------
__global__ __launch_bounds__(256) void split_kernel(
    const float* __restrict__ src, __nv_bfloat16* __restrict__ hi,
    __nv_bfloat16* __restrict__ lo, int n4)
{
    int i = blockIdx.x * 256 + threadIdx.x;
    if (i >= n4) return;
    float4 v = ((const float4*)src)[i];
    __nv_bfloat16 h0, h1, h2, h3, l0, l1, l2, l3;
    split2(v.x, h0, l0); split2(v.y, h1, l1); split2(v.z, h2, l2); split2(v.w, h3, l3);
    ((__nv_bfloat162*)hi)[2 * i]     = __nv_bfloat162(h0, h1);
    ((__nv_bfloat162*)hi)[2 * i + 1] = __nv_bfloat162(h2, h3);
    ((__nv_bfloat162*)lo)[2 * i]     = __nv_bfloat162(l0, l1);
    ((__nv_bfloat162*)lo)[2 * i + 1] = __nv_bfloat162(l2, l3);
}

struct WSrc { const float* s[10]; };

__global__ __launch_bounds__(256) void wsplit_kernel(
    WSrc ws, __nv_bfloat16* __restrict__ hi, __nv_bfloat16* __restrict__ lo)
{
    int m = blockIdx.y;
    int i = blockIdx.x * 256 + threadIdx.x;
    float4 v = ((const float4*)ws.s[m])[i];
    __nv_bfloat16 h0, h1, h2, h3, l0, l1, l2, l3;
    split2(v.x, h0, l0); split2(v.y, h1, l1); split2(v.z, h2, l2); split2(v.w, h3, l3);
    size_t base = (size_t)m * DMODEL * DMODEL / 2 + 2 * i;
    ((__nv_bfloat162*)hi)[base]     = __nv_bfloat162(h0, h1);
    ((__nv_bfloat162*)hi)[base + 1] = __nv_bfloat162(h2, h3);
    ((__nv_bfloat162*)lo)[base]     = __nv_bfloat162(l0, l1);
    ((__nv_bfloat162*)lo)[base + 1] = __nv_bfloat162(l2, l3);
}

// ---------------- HMMA GEMM ----------------
// C[M,256] = act(A[M,256] @ W[256,256]^T + bias)
// bf16-split (3 terms), fp32 accum, mma.sync m16n8k16.
// CTA tile 128x128, K-chunks of 64, 8 warps (2x4), warp tile 64x32.
#define KC 64
#define TILE_B 16384   // 128 rows * 128 bytes

struct GemmArgs {
    const __nv_bfloat16* Ahi;
    const __nv_bfloat16* Alo;
    const __nv_bfloat16* Whi[3];
    const __nv_bfloat16* Wlo[3];
    const float* bias[3];
    float* C[3];
};

template <int ACT>
__global__ __launch_bounds__(256) void mma_gemm(GemmArgs args)
{
    extern __shared__ char smem[];
    char* tAhi = smem + 0 * TILE_B;
    char* tAlo = smem + 1 * TILE_B;
    char* tBhi = smem + 2 * TILE_B;
    char* tBlo = smem + 3 * TILE_B;
    const uint32_t sAhi = smem_u32(tAhi);
    const uint32_t sAlo = sAhi + TILE_B;
    const uint32_t sBhi = sAhi + 2 * TILE_B;
    const uint32_t sBlo = sAhi + 3 * TILE_B;

    const int tid = threadIdx.x;
    const int wid = tid >> 5;
    const int lane = tid & 31;
    const int z = blockIdx.z;
    const int bm = blockIdx.y * 128;
    const int bn = blockIdx.x * 128;
    const int wm = (wid & 1) * 64;        // warp m offset in tile
    const int wn = (wid >> 1) * 32;       // warp n offset in tile

    const __nv_bfloat16* __restrict__ Ahi = args.Ahi;
    const __nv_bfloat16* __restrict__ Alo = args.Alo;
    const __nv_bfloat16* __restrict__ Whi = args.Whi[z];
    const __nv_bfloat16* __restrict__ Wlo = args.Wlo[z];

    float acc[4][4][4];
    #pragma unroll
    for (int i = 0; i < 4; i++)
        #pragma unroll
        for (int j = 0; j < 4; j++)
            #pragma unroll
            for (int c = 0; c < 4; c++) acc[i][j][c] = 0.f;

    // ldmatrix per-lane address components (shared by A and B 16x16 frags)
    const int rofs = ((lane >> 3) & 1) * 8 + (lane & 7);   // row within 16-row frag
    const int kofs = ((lane >> 4) & 1) * 16;               // 16B chunk within k16

    for (int kc = 0; kc < 4; kc++) {
        const int k0 = kc * KC;
        // stage 4 tiles: 128 rows x 64 bf16 each, uint4 (8 bf16) grain
        #pragma unroll
        for (int i = 0; i < 4; i++) {
            int idx = tid + i * 256;          // 0..1023
            int r = idx >> 3;                 // row 0..127
            int f = idx & 7;                  // 16B chunk 0..7
            uint32_t so = SMEM_SWIZZLE_128B((uint32_t)(r * 128 + f * 16));
            *(uint4*)(tAhi + so) = ((const uint4*)(Ahi + (size_t)(bm + r) * DMODEL + k0))[f];
            *(uint4*)(tAlo + so) = ((const uint4*)(Alo + (size_t)(bm + r) * DMODEL + k0))[f];
            *(uint4*)(tBhi + so) = ((const uint4*)(Whi + (size_t)(bn + r) * DMODEL + k0))[f];
            *(uint4*)(tBlo + so) = ((const uint4*)(Wlo + (size_t)(bn + r) * DMODEL + k0))[f];
        }
        __syncthreads();

        #pragma unroll
        for (int ks = 0; ks < 4; ks++) {
            const int kb = ks * 32 + kofs;    // byte col within 128B row
            uint32_t ah[4][4], al[4][4], bh[4][2], bl[4][2];
            #pragma unroll
            for (int mt = 0; mt < 4; mt++) {
                int row = wm + mt * 16 + rofs;
                uint32_t so = SMEM_SWIZZLE_128B((uint32_t)(row * 128 + kb));
                ldsm_x4(ah[mt], sAhi + so);
                ldsm_x4(al[mt], sAlo + so);
            }
            #pragma unroll
            for (int p = 0; p < 2; p++) {
                int row = wn + p * 16 + rofs;
                uint32_t so = SMEM_SWIZZLE_128B((uint32_t)(row * 128 + kb));
                uint32_t t[4];
                ldsm_x4(t, sBhi + so);
                bh[2 * p][0] = t[0]; bh[2 * p][1] = t[2];
                bh[2 * p + 1][0] = t[1]; bh[2 * p + 1][1] = t[3];
                ldsm_x4(t, sBlo + so);
                bl[2 * p][0] = t[0]; bl[2 * p][1] = t[2];
                bl[2 * p + 1][0] = t[1]; bl[2 * p + 1][1] = t[3];
            }
            // term 1: hi*hi
            #pragma unroll
            for (int mt = 0; mt < 4; mt++)
                #pragma unroll
                for (int nt = 0; nt < 4; nt++)
                    mma16816(acc[mt][nt], ah[mt], bh[nt]);
            // term 2: hi*lo
            #pragma unroll
            for (int mt = 0; mt < 4; mt++)
                #pragma unroll
                for (int nt = 0; nt < 4; nt++)
                    mma16816(acc[mt][nt], ah[mt], bl[nt]);
            // term 3: lo*hi
            #pragma unroll
            for (int mt = 0; mt < 4; mt++)
                #pragma unroll
                for (int nt = 0; nt < 4; nt++)
                    mma16816(acc[mt][nt], al[mt], bh[nt]);
        }
        __syncthreads();
    }

    // epilogue: registers -> global (float2 per frag quadrant)
    float* __restrict__ Cz = args.C[z];
    const float* __restrict__ bz = args.bias[z];
    const int rbase = bm + wm + (lane >> 2);
    const int cbase = bn + wn + (lane & 3) * 2;
    #pragma unroll
    for (int mt = 0; mt < 4; mt++) {
        #pragma unroll
        for (int nt = 0; nt < 4; nt++) {
            int col = cbase + nt * 8;
            float v0 = acc[mt][nt][0], v1 = acc[mt][nt][1];
            float v2 = acc[mt][nt][2], v3 = acc[mt][nt][3];
            if (ACT == 1) {
                float b0 = bz[col], b1 = bz[col + 1];
                v0 += b0; v1 += b1; v2 += b0; v3 += b1;
                v0 = v0 / (1.0f + __expf(-v0));
                v1 = v1 / (1.0f + __expf(-v1));
                v2 = v2 / (1.0f + __expf(-v2));
                v3 = v3 / (1.0f + __expf(-v3));
            }
            int r0 = rbase + mt * 16;
            *(float2*)&Cz[(size_t)r0 * DMODEL + col]       = make_float2(v0, v1);
            *(float2*)&Cz[(size_t)(r0 + 8) * DMODEL + col] = make_float2(v2, v3);
        }
    }
}

// ---------------- evidential gate ----------------
__device__ __forceinline__ float softplusf(float x) {
    return (x > 20.f) ? x : log1pf(expf(x));
}

__global__ __launch_bounds__(256) void gate_kernel(
    const float* __restrict__ t, const float* __restrict__ gW,
    const float* __restrict__ gb, float* __restrict__ g_out,
    float* __restrict__ lg_out, int ntok)
{
    const int warp = threadIdx.x >> 5;
    const int lane = threadIdx.x & 31;
    const int token = blockIdx.x * 8 + warp;
    if (token >= ntok) return;

    const float* tp = t + (size_t)token * DMODEL;
    float p0 = 0.f, p1 = 0.f, p2 = 0.f, p3 = 0.f;
    #pragma unroll
    for (int i = 0; i < 8; i++) {
        int d = lane + i * 32;
        float xv = tp[d];
        p0 += xv * gW[0 * DMODEL + d];
        p1 += xv * gW[1 * DMODEL + d];
        p2 += xv * gW[2 * DMODEL + d];
        p3 += xv * gW[3 * DMODEL + d];
    }
    #pragma unroll
    for (int o = 16; o > 0; o >>= 1) {
        p0 += __shfl_xor_sync(0xffffffffu, p0, o);
        p1 += __shfl_xor_sync(0xffffffffu, p1, o);
        p2 += __shfl_xor_sync(0xffffffffu, p2, o);
        p3 += __shfl_xor_sync(0xffffffffu, p3, o);
    }
    if (lane == 0) {
        float mu    = p0 + gb[0];
        float v     = softplusf(p1 + gb[1]) + 1e-6f;
        float alpha = softplusf(p2 + gb[2]) + 1.0f + 1e-6f;
        float beta  = softplusf(p3 + gb[3]) + 1e-6f;
        float var_ep = beta / (v * (alpha - 1.0f));
        float g = (1.0f / (1.0f + expf(-mu))) * expf(-2.0f * var_ep);
        g = fmaxf(g, 1e-6f);
        g_out[token]  = g;
        lg_out[token] = logf(g);
    }
}

// ---------------- flash attention (fp32 SIMT), emits bf16 splits ----------------
#define KT 32

__global__ __launch_bounds__(128) void attn_kernel(
    const float* __restrict__ q, const float* __restrict__ k,
    const float* __restrict__ v, const float* __restrict__ lgk,
    __nv_bfloat16* __restrict__ ohi, __nv_bfloat16* __restrict__ olo,
    int Tq, int Tk)
{
    __shared__ float4 ks4[KT * 16];
    __shared__ float4 vs4[KT * 16];
    __shared__ float  lgs[KT];

    const int tid = threadIdx.x;
    const int b = blockIdx.z;
    const int h = blockIdx.y;
    const int qi = blockIdx.x * 128 + tid;
    if (qi >= Tq) return;

    const float scale = 0.125f;

    float qreg[DK];
    {
        const float4* qp = (const float4*)(q + ((size_t)(b * Tq + qi) * DMODEL + h * DK));
        #pragma unroll
        for (int i = 0; i < 16; i++) {
            float4 t = qp[i];
            qreg[4 * i + 0] = t.x; qreg[4 * i + 1] = t.y;
            qreg[4 * i + 2] = t.z; qreg[4 * i + 3] = t.w;
        }
    }

    float m = -INFINITY, l = 0.f;
    float acc[DK];
    #pragma unroll
    for (int d = 0; d < DK; d++) acc[d] = 0.f;

    for (int kb = 0; kb < Tk; kb += KT) {
        #pragma unroll
        for (int i = 0; i < 4; i++) {
            int idx = tid + i * 128;
            int j = idx >> 4;
            int d4 = idx & 15;
            size_t base = (size_t)(b * Tk + kb + j) * 64 + h * 16 + d4;
            ks4[idx] = ((const float4*)k)[base];
            vs4[idx] = ((const float4*)v)[base];
        }
        if (tid < KT) lgs[tid] = lgk[b * Tk + kb + tid];
        __syncthreads();

        float snew[KT];
        float mt = m;
        #pragma unroll
        for (int j = 0; j < KT; j++) {
            float s = 0.f;
            #pragma unroll
            for (int d4 = 0; d4 < 16; d4++) {
                float4 kk = ks4[j * 16 + d4];
                s += qreg[4 * d4 + 0] * kk.x + qreg[4 * d4 + 1] * kk.y
                   + qreg[4 * d4 + 2] * kk.z + qreg[4 * d4 + 3] * kk.w;
            }
            s = s * scale + lgs[j];
            snew[j] = s;
            mt = fmaxf(mt, s);
        }
        float corr = __expf(m - mt);
        l *= corr;
        #pragma unroll
        for (int d = 0; d < DK; d++) acc[d] *= corr;
        #pragma unroll
        for (int j = 0; j < KT; j++) {
            float p = __expf(snew[j] - mt);
            l += p;
            #pragma unroll
            for (int d4 = 0; d4 < 16; d4++) {
                float4 vv = vs4[j * 16 + d4];
                acc[4 * d4 + 0] += p * vv.x;
                acc[4 * d4 + 1] += p * vv.y;
                acc[4 * d4 + 2] += p * vv.z;
                acc[4 * d4 + 3] += p * vv.w;
            }
        }
        m = mt;
        __syncthreads();
    }

    float invl = 1.0f / l;
    size_t obase = (size_t)(b * Tq + qi) * DMODEL + h * DK;
    __nv_bfloat162* ph = (__nv_bfloat162*)(ohi + obase);
    __nv_bfloat162* pl = (__nv_bfloat162*)(olo + obase);
    #pragma unroll
    for (int d2 = 0; d2 < 32; d2++) {
        float v0 = acc[2 * d2] * invl;
        float v1 = acc[2 * d2 + 1] * invl;
        __nv_bfloat16 h0, h1, l0, l1;
        split2(v0, h0, l0);
        split2(v1, h1, l1);
        ph[d2] = __nv_bfloat162(h0, h1);
        pl[d2] = __nv_bfloat162(l0, l1);
    }
}

// ---------------- residual add + LayerNorm (optional split emit) ----------------
template <int EMIT>
__global__ __launch_bounds__(256) void add_ln_kernel(
    const float* __restrict__ a, const float* __restrict__ b,
    const float* __restrict__ gamma, const float* __restrict__ beta,
    float* __restrict__ out, __nv_bfloat16* __restrict__ ohi,
    __nv_bfloat16* __restrict__ olo, int ntok)
{
    const int warp = threadIdx.x >> 5;
    const int lane = threadIdx.x & 31;
    const int token = blockIdx.x * 8 + warp;
    if (token >= ntok) return;

    const float* pa = a + (size_t)token * DMODEL;
    const float* pb = b + (size_t)token * DMODEL;
    float v[8];
    float s = 0.f, s2 = 0.f;
    #pragma unroll
    for (int i = 0; i < 8; i++) {
        int d = lane + i * 32;
        float x = pa[d] + pb[d];
        v[i] = x;
        s += x;
        s2 += x * x;
    }
    #pragma unroll
    for (int o = 16; o > 0; o >>= 1) {
        s  += __shfl_xor_sync(0xffffffffu, s, o);
        s2 += __shfl_xor_sync(0xffffffffu, s2, o);
    }
    float mean = s * (1.0f / DMODEL);
    float var  = s2 * (1.0f / DMODEL) - mean * mean;
    float inv  = rsqrtf(var + 1e-5f);
    float* po = out + (size_t)token * DMODEL;
    #pragma unroll
    for (int i = 0; i < 8; i++) {
        int d = lane + i * 32;
        float o = (v[i] - mean) * inv * gamma[d] + beta[d];
        po[d] = o;
        if (EMIT) {
            __nv_bfloat16 h, lo;
            split2(o, h, lo);
            ohi[(size_t)token * DMODEL + d] = h;
            olo[(size_t)token * DMODEL + d] = lo;
        }
    }
}

// ---------------- launch ----------------
#define SMEM_GEMM_DYN (4 * TILE_B)   // 64 KB

extern "C" void kernel_launch(void* const* d_in, const int* in_sizes, int n_in,
                              void* d_out, int out_size)
{
    const float* x    = (const float*)d_in[0];
    const float* y    = (const float*)d_in[1];
    const float* Wqx  = (const float*)d_in[4];
    const float* Wkx  = (const float*)d_in[5];
    const float* Wvx  = (const float*)d_in[6];
    const float* Wqy  = (const float*)d_in[7];
    const float* Wky  = (const float*)d_in[8];
    const float* Wvy  = (const float*)d_in[9];
    const float* gWx  = (const float*)d_in[10];
    const float* gbx  = (const float*)d_in[11];
    const float* gWy  = (const float*)d_in[12];
    const float* gby  = (const float*)d_in[13];
    const float* Wox  = (const float*)d_in[14];
    const float* Woy  = (const float*)d_in[15];
    const float* lnxg = (const float*)d_in[16];
    const float* lnxb = (const float*)d_in[17];
    const float* lnyg = (const float*)d_in[18];
    const float* lnyb = (const float*)d_in[19];
    const float* ffxW = (const float*)d_in[20];
    const float* ffxb = (const float*)d_in[21];
    const float* ffyW = (const float*)d_in[22];
    const float* ffyb = (const float*)d_in[23];
    float* out = (float*)d_out;

    float *qx, *kx, *vx, *qy, *ky, *vy, *t1, *x2a, *y2a, *lgx, *lgy;
    __nv_bfloat16 *xhi, *xlo, *yhi, *ylo, *axhi, *axlo, *ayhi, *aylo;
    __nv_bfloat16 *x2ahi, *x2alo, *y2ahi, *y2alo, *whi, *wlo;
    cudaGetSymbolAddress((void**)&qx,  g_qx);
    cudaGetSymbolAddress((void**)&kx,  g_kx);
    cudaGetSymbolAddress((void**)&vx,  g_vx);
    cudaGetSymbolAddress((void**)&qy,  g_qy);
    cudaGetSymbolAddress((void**)&ky,  g_ky);
    cudaGetSymbolAddress((void**)&vy,  g_vy);
    cudaGetSymbolAddress((void**)&t1,  g_t1);
    cudaGetSymbolAddress((void**)&x2a, g_x2a);
    cudaGetSymbolAddress((void**)&y2a, g_y2a);
    cudaGetSymbolAddress((void**)&lgx, g_lgx);
    cudaGetSymbolAddress((void**)&lgy, g_lgy);
    cudaGetSymbolAddress((void**)&xhi, g_xhi);
    cudaGetSymbolAddress((void**)&xlo, g_xlo);
    cudaGetSymbolAddress((void**)&yhi, g_yhi);
    cudaGetSymbolAddress((void**)&ylo, g_ylo);
    cudaGetSymbolAddress((void**)&axhi, g_axhi);
    cudaGetSymbolAddress((void**)&axlo, g_axlo);
    cudaGetSymbolAddress((void**)&ayhi, g_ayhi);
    cudaGetSymbolAddress((void**)&aylo, g_aylo);
    cudaGetSymbolAddress((void**)&x2ahi, g_x2ahi);
    cudaGetSymbolAddress((void**)&x2alo, g_x2alo);
    cudaGetSymbolAddress((void**)&y2ahi, g_y2ahi);
    cudaGetSymbolAddress((void**)&y2alo, g_y2alo);
    cudaGetSymbolAddress((void**)&whi, g_whi);
    cudaGetSymbolAddress((void**)&wlo, g_wlo);

    cudaFuncSetAttribute(mma_gemm<0>, cudaFuncAttributeMaxDynamicSharedMemorySize, SMEM_GEMM_DYN);
    cudaFuncSetAttribute(mma_gemm<1>, cudaFuncAttributeMaxDynamicSharedMemorySize, SMEM_GEMM_DYN);

    const int WSZ = DMODEL * DMODEL;  // 65536

    // 1) conversions
    split_kernel<<<MX * DMODEL / 4 / 256, 256>>>(x, xhi, xlo, MX * DMODEL / 4);
    split_kernel<<<MY * DMODEL / 4 / 256, 256>>>(y, yhi, ylo, MY * DMODEL / 4);
    WSrc ws;
    ws.s[0] = Wqx; ws.s[1] = Wkx; ws.s[2] = Wvx;
    ws.s[3] = Wqy; ws.s[4] = Wky; ws.s[5] = Wvy;
    ws.s[6] = Wox; ws.s[7] = Woy; ws.s[8] = ffxW; ws.s[9] = ffyW;
    wsplit_kernel<<<dim3(WSZ / 4 / 256, 10), 256>>>(ws, whi, wlo);

    // 2) gates
    gate_kernel<<<MX / 8, 256>>>(x, gWx, gbx, out + OFF_GX, lgx, MX);
    gate_kernel<<<MY / 8, 256>>>(y, gWy, gby, out + OFF_GY, lgy, MY);

    // 3) QKV projections (batched z=3)
    {
        GemmArgs a = {};
        a.Ahi = xhi; a.Alo = xlo;
        a.Whi[0] = whi + 0 * WSZ; a.Wlo[0] = wlo + 0 * WSZ; a.C[0] = qx;
        a.Whi[1] = whi + 1 * WSZ; a.Wlo[1] = wlo + 1 * WSZ; a.C[1] = kx;
        a.Whi[2] = whi + 2 * WSZ; a.Wlo[2] = wlo + 2 * WSZ; a.C[2] = vx;
        mma_gemm<0><<<dim3(2, MX / 128, 3), 256, SMEM_GEMM_DYN>>>(a);
    }
    {
        GemmArgs a = {};
        a.Ahi = yhi; a.Alo = ylo;
        a.Whi[0] = whi + 3 * WSZ; a.Wlo[0] = wlo + 3 * WSZ; a.C[0] = qy;
        a.Whi[1] = whi + 4 * WSZ; a.Wlo[1] = wlo + 4 * WSZ; a.C[1] = ky;
        a.Whi[2] = whi + 5 * WSZ; a.Wlo[2] = wlo + 5 * WSZ; a.C[2] = vy;
        mma_gemm<0><<<dim3(2, MY / 128, 3), 256, SMEM_GEMM_DYN>>>(a);
    }

    // 4) attention
    attn_kernel<<<dim3(NX / 128, NHEAD, BATCH), 128>>>(qx, ky, vy, lgy, axhi, axlo, NX, NY);
    attn_kernel<<<dim3(NY / 128, NHEAD, BATCH), 128>>>(qy, kx, vx, lgx, ayhi, aylo, NY, NX);

    // 5) x branch
    {
        GemmArgs a = {};
        a.Ahi = axhi; a.Alo = axlo;
        a.Whi[0] = whi + 6 * WSZ; a.Wlo[0] = wlo + 6 * WSZ; a.C[0] = t1;
        mma_gemm<0><<<dim3(2, MX / 128, 1), 256, SMEM_GEMM_DYN>>>(a);
    }
    add_ln_kernel<1><<<MX / 8, 256>>>(x, t1, lnxg, lnxb, x2a, x2ahi, x2alo, MX);
    {
        GemmArgs a = {};
        a.Ahi = x2ahi; a.Alo = x2alo;
        a.Whi[0] = whi + 8 * WSZ; a.Wlo[0] = wlo + 8 * WSZ; a.C[0] = t1; a.bias[0] = ffxb;
        mma_gemm<1><<<dim3(2, MX / 128, 1), 256, SMEM_GEMM_DYN>>>(a);
    }
    add_ln_kernel<0><<<MX / 8, 256>>>(x2a, t1, lnxg, lnxb, out + OFF_X2, nullptr, nullptr, MX);

    // 6) y branch
    {
        GemmArgs a = {};
        a.Ahi = ayhi; a.Alo = aylo;
        a.Whi[0] = whi + 7 * WSZ; a.Wlo[0] = wlo + 7 * WSZ; a.C[0] = t1;
        mma_gemm<0><<<dim3(2, MY / 128, 1), 256, SMEM_GEMM_DYN>>>(a);
    }
    add_ln_kernel<1><<<MY / 8, 256>>>(y, t1, lnyg, lnyb, y2a, y2ahi, y2alo, MY);
    {
        GemmArgs a = {};
        a.Ahi = y2ahi; a.Alo = y2alo;
        a.Whi[0] = whi + 9 * WSZ; a.Wlo[0] = wlo + 9 * WSZ; a.C[0] = t1; a.bias[0] = ffyb;
        mma_gemm<1><<<dim3(2, MY / 128, 1), 256, SMEM_GEMM_DYN>>>(a);
    }
    add_ln_kernel<0><<<MY / 8, 256>>>(y2a, t1, lnyg, lnyb, out + OFF_Y2, nullptr, nullptr, MY);
}

// round 4
// speedup vs baseline: 2.5308x; 2.2081x over previous
#include <cuda_runtime.h>
#include <cuda_bf16.h>
#include <math.h>
#include <stdint.h>

// ---------------- problem constants ----------------
#define BATCH 16
#define NX 512
#define NY 1024
#define DMODEL 256
#define NHEAD 4
#define DK 64
#define MX (BATCH * NX)   // 8192
#define MY (BATCH * NY)   // 16384

#define OFF_X2 0
#define OFF_Y2 (MX * DMODEL)
#define OFF_GX (OFF_Y2 + MY * DMODEL)
#define OFF_GY (OFF_GX + MX)

// ---------------- scratch ----------------
__device__ float g_t1[MY * DMODEL];
__device__ float g_x2a[MX * DMODEL];
__device__ float g_y2a[MY * DMODEL];
__device__ float g_lgx[MX];
__device__ float g_lgy[MY];

__device__ __nv_bfloat16 g_xhi[MX * DMODEL];
__device__ __nv_bfloat16 g_xlo[MX * DMODEL];
__device__ __nv_bfloat16 g_yhi[MY * DMODEL];
__device__ __nv_bfloat16 g_ylo[MY * DMODEL];
__device__ __nv_bfloat16 g_qxhi[MX * DMODEL];
__device__ __nv_bfloat16 g_qxlo[MX * DMODEL];
__device__ __nv_bfloat16 g_kxhi[MX * DMODEL];
__device__ __nv_bfloat16 g_kxlo[MX * DMODEL];
__device__ __nv_bfloat16 g_vxhi[MX * DMODEL];
__device__ __nv_bfloat16 g_vxlo[MX * DMODEL];
__device__ __nv_bfloat16 g_qyhi[MY * DMODEL];
__device__ __nv_bfloat16 g_qylo[MY * DMODEL];
__device__ __nv_bfloat16 g_kyhi[MY * DMODEL];
__device__ __nv_bfloat16 g_kylo[MY * DMODEL];
__device__ __nv_bfloat16 g_vyhi[MY * DMODEL];
__device__ __nv_bfloat16 g_vylo[MY * DMODEL];
__device__ __nv_bfloat16 g_axhi[MX * DMODEL];
__device__ __nv_bfloat16 g_axlo[MX * DMODEL];
__device__ __nv_bfloat16 g_ayhi[MY * DMODEL];
__device__ __nv_bfloat16 g_aylo[MY * DMODEL];
__device__ __nv_bfloat16 g_x2ahi[MX * DMODEL];
__device__ __nv_bfloat16 g_x2alo[MX * DMODEL];
__device__ __nv_bfloat16 g_y2ahi[MY * DMODEL];
__device__ __nv_bfloat16 g_y2alo[MY * DMODEL];
__device__ __nv_bfloat16 g_whi[10 * DMODEL * DMODEL];
__device__ __nv_bfloat16 g_wlo[10 * DMODEL * DMODEL];

// ---------------- helpers ----------------
__device__ __forceinline__ uint32_t smem_u32(const void* p) {
    uint32_t a;
    asm("{ .reg .u64 t; cvta.to.shared.u64 t, %1; cvt.u32.u64 %0, t; }"
        : "=r"(a) : "l"(p));
    return a;
}

#define SMEM_SWIZZLE_128B(off) ((off) ^ (((off) >> 3) & 0x70))

__device__ __forceinline__ void ldsm_x4(uint32_t* r, uint32_t addr) {
    asm volatile("ldmatrix.sync.aligned.m8n8.x4.shared.b16 {%0,%1,%2,%3}, [%4];"
                 : "=r"(r[0]), "=r"(r[1]), "=r"(r[2]), "=r"(r[3]) : "r"(addr));
}

__device__ __forceinline__ void ldsm_x4_t(uint32_t* r, uint32_t addr) {
    asm volatile("ldmatrix.sync.aligned.m8n8.x4.trans.shared.b16 {%0,%1,%2,%3}, [%4];"
                 : "=r"(r[0]), "=r"(r[1]), "=r"(r[2]), "=r"(r[3]) : "r"(addr));
}

__device__ __forceinline__ void mma16816(float* d, const uint32_t* a, const uint32_t* b) {
    asm volatile(
        "mma.sync.aligned.m16n8k16.row.col.f32.bf16.bf16.f32 "
        "{%0,%1,%2,%3}, {%4,%5,%6,%7}, {%8,%9}, {%0,%1,%2,%3};"
        : "+f"(d[0]), "+f"(d[1]), "+f"(d[2]), "+f"(d[3])
        : "r"(a[0]), "r"(a[1]), "r"(a[2]), "r"(a[3]), "r"(b[0]), "r"(b[1]));
}

__device__ __forceinline__ void cpa16(uint32_t dst, const void* src) {
    asm volatile("cp.async.cg.shared.global [%0], [%1], 16;" :: "r"(dst), "l"(src));
}
#define CP_COMMIT() asm volatile("cp.async.commit_group;" ::: "memory")
#define CP_WAIT0()  asm volatile("cp.async.wait_group 0;" ::: "memory")

__device__ __forceinline__ void split2(float v, __nv_bfloat16& hi, __nv_bfloat16& lo) {
    hi = __float2bfloat16(v);
    lo = __float2bfloat16(v - __bfloat162float(hi));
}

// pack two floats to bf16x2 hi, return lo via out-param
__device__ __forceinline__ uint32_t pack_split(float a, float b, uint32_t& lo) {
    __nv_bfloat16 ha = __float2bfloat16(a), hb = __float2bfloat16(b);
    __nv_bfloat16 la = __float2bfloat16(a - __bfloat162float(ha));
    __nv_bfloat16 lb = __float2bfloat16(b - __bfloat162float(hb));
    __nv_bfloat162 H(ha, hb), L(la, lb);
    lo = *(uint32_t*)&L;
    return *(uint32_t*)&H;
}

// ---------------- conversion kernels ----------------
__global__ __launch_bounds__(256) void split_kernel(
    const float* __restrict__ src, __nv_bfloat16* __restrict__ hi,
    __nv_bfloat16* __restrict__ lo, int n4)
{
    int i = blockIdx.x * 256 + threadIdx.x;
    if (i >= n4) return;
    float4 v = ((const float4*)src)[i];
    uint32_t l0, l1;
    uint32_t h0 = pack_split(v.x, v.y, l0);
    uint32_t h1 = pack_split(v.z, v.w, l1);
    ((uint32_t*)hi)[2 * i]     = h0;
    ((uint32_t*)hi)[2 * i + 1] = h1;
    ((uint32_t*)lo)[2 * i]     = l0;
    ((uint32_t*)lo)[2 * i + 1] = l1;
}

struct WSrc { const float* s[10]; };

__global__ __launch_bounds__(256) void wsplit_kernel(
    WSrc ws, __nv_bfloat16* __restrict__ hi, __nv_bfloat16* __restrict__ lo)
{
    int m = blockIdx.y;
    int i = blockIdx.x * 256 + threadIdx.x;
    float4 v = ((const float4*)ws.s[m])[i];
    uint32_t l0, l1;
    uint32_t h0 = pack_split(v.x, v.y, l0);
    uint32_t h1 = pack_split(v.z, v.w, l1);
    size_t base = (size_t)m * DMODEL * DMODEL / 2 + 2 * i;
    ((uint32_t*)hi)[base]     = h0;
    ((uint32_t*)hi)[base + 1] = h1;
    ((uint32_t*)lo)[base]     = l0;
    ((uint32_t*)lo)[base + 1] = l1;
}

// ---------------- HMMA GEMM ----------------
// C[M,256] = act(A[M,256] @ W[256,256]^T + bias)
// bf16-split (3 terms), fp32 accum, mma.sync m16n8k16.
// CTA tile 128x128, K-chunks of 64, 8 warps (2x4), warp tile 64x32.
#define TILE_B 16384   // 128 rows * 128 bytes

struct GemmArgs {
    const __nv_bfloat16* Ahi;
    const __nv_bfloat16* Alo;
    const __nv_bfloat16* Whi[3];
    const __nv_bfloat16* Wlo[3];
    const float* bias[3];
    float* C[3];
    __nv_bfloat16* Chi[3];
    __nv_bfloat16* Clo[3];
    float scl[3];
};

template <int ACT, int EMIT>
__global__ __launch_bounds__(256) void mma_gemm(GemmArgs args)
{
    extern __shared__ char smem[];
    char* tAhi = smem + 0 * TILE_B;
    char* tAlo = smem + 1 * TILE_B;
    char* tBhi = smem + 2 * TILE_B;
    char* tBlo = smem + 3 * TILE_B;
    const uint32_t sAhi = smem_u32(tAhi);
    const uint32_t sAlo = sAhi + TILE_B;
    const uint32_t sBhi = sAhi + 2 * TILE_B;
    const uint32_t sBlo = sAhi + 3 * TILE_B;

    const int tid = threadIdx.x;
    const int wid = tid >> 5;
    const int lane = tid & 31;
    const int z = blockIdx.z;
    const int bm = blockIdx.y * 128;
    const int bn = blockIdx.x * 128;
    const int wm = (wid & 1) * 64;
    const int wn = (wid >> 1) * 32;

    const __nv_bfloat16* __restrict__ Ahi = args.Ahi;
    const __nv_bfloat16* __restrict__ Alo = args.Alo;
    const __nv_bfloat16* __restrict__ Whi = args.Whi[z];
    const __nv_bfloat16* __restrict__ Wlo = args.Wlo[z];

    float acc[4][4][4];
    #pragma unroll
    for (int i = 0; i < 4; i++)
        #pragma unroll
        for (int j = 0; j < 4; j++)
            #pragma unroll
            for (int c = 0; c < 4; c++) acc[i][j][c] = 0.f;

    const int rofs = ((lane >> 3) & 1) * 8 + (lane & 7);
    const int kofs = ((lane >> 4) & 1) * 16;

    for (int kc = 0; kc < 4; kc++) {
        const int k0 = kc * 64;
        #pragma unroll
        for (int i = 0; i < 4; i++) {
            int idx = tid + i * 256;
            int r = idx >> 3;
            int f = idx & 7;
            uint32_t so = SMEM_SWIZZLE_128B((uint32_t)(r * 128 + f * 16));
            *(uint4*)(tAhi + so) = ((const uint4*)(Ahi + (size_t)(bm + r) * DMODEL + k0))[f];
            *(uint4*)(tAlo + so) = ((const uint4*)(Alo + (size_t)(bm + r) * DMODEL + k0))[f];
            *(uint4*)(tBhi + so) = ((const uint4*)(Whi + (size_t)(bn + r) * DMODEL + k0))[f];
            *(uint4*)(tBlo + so) = ((const uint4*)(Wlo + (size_t)(bn + r) * DMODEL + k0))[f];
        }
        __syncthreads();

        #pragma unroll
        for (int ks = 0; ks < 4; ks++) {
            const int kb = ks * 32 + kofs;
            uint32_t ah[4][4], al[4][4], bh[4][2], bl[4][2];
            #pragma unroll
            for (int mt = 0; mt < 4; mt++) {
                int row = wm + mt * 16 + rofs;
                uint32_t so = SMEM_SWIZZLE_128B((uint32_t)(row * 128 + kb));
                ldsm_x4(ah[mt], sAhi + so);
                ldsm_x4(al[mt], sAlo + so);
            }
            #pragma unroll
            for (int p = 0; p < 2; p++) {
                int row = wn + p * 16 + rofs;
                uint32_t so = SMEM_SWIZZLE_128B((uint32_t)(row * 128 + kb));
                uint32_t t[4];
                ldsm_x4(t, sBhi + so);
                bh[2 * p][0] = t[0]; bh[2 * p][1] = t[2];
                bh[2 * p + 1][0] = t[1]; bh[2 * p + 1][1] = t[3];
                ldsm_x4(t, sBlo + so);
                bl[2 * p][0] = t[0]; bl[2 * p][1] = t[2];
                bl[2 * p + 1][0] = t[1]; bl[2 * p + 1][1] = t[3];
            }
            #pragma unroll
            for (int mt = 0; mt < 4; mt++)
                #pragma unroll
                for (int nt = 0; nt < 4; nt++)
                    mma16816(acc[mt][nt], ah[mt], bh[nt]);
            #pragma unroll
            for (int mt = 0; mt < 4; mt++)
                #pragma unroll
                for (int nt = 0; nt < 4; nt++)
                    mma16816(acc[mt][nt], ah[mt], bl[nt]);
            #pragma unroll
            for (int mt = 0; mt < 4; mt++)
                #pragma unroll
                for (int nt = 0; nt < 4; nt++)
                    mma16816(acc[mt][nt], al[mt], bh[nt]);
        }
        __syncthreads();
    }

    const int rbase = bm + wm + (lane >> 2);
    const int cbase = bn + wn + (lane & 3) * 2;
    if (EMIT == 0) {
        float* __restrict__ Cz = args.C[z];
        const float* __restrict__ bz = args.bias[z];
        #pragma unroll
        for (int mt = 0; mt < 4; mt++) {
            #pragma unroll
            for (int nt = 0; nt < 4; nt++) {
                int col = cbase + nt * 8;
                float v0 = acc[mt][nt][0], v1 = acc[mt][nt][1];
                float v2 = acc[mt][nt][2], v3 = acc[mt][nt][3];
                if (ACT == 1) {
                    float b0 = bz[col], b1 = bz[col + 1];
                    v0 += b0; v1 += b1; v2 += b0; v3 += b1;
                    v0 = v0 / (1.0f + __expf(-v0));
                    v1 = v1 / (1.0f + __expf(-v1));
                    v2 = v2 / (1.0f + __expf(-v2));
                    v3 = v3 / (1.0f + __expf(-v3));
                }
                int r0 = rbase + mt * 16;
                *(float2*)&Cz[(size_t)r0 * DMODEL + col]       = make_float2(v0, v1);
                *(float2*)&Cz[(size_t)(r0 + 8) * DMODEL + col] = make_float2(v2, v3);
            }
        }
    } else {
        const float s = args.scl[z];
        __nv_bfloat16* __restrict__ Chi = args.Chi[z];
        __nv_bfloat16* __restrict__ Clo = args.Clo[z];
        #pragma unroll
        for (int mt = 0; mt < 4; mt++) {
            #pragma unroll
            for (int nt = 0; nt < 4; nt++) {
                int col = cbase + nt * 8;
                int r0 = rbase + mt * 16;
                uint32_t l0, l1;
                uint32_t h0 = pack_split(acc[mt][nt][0] * s, acc[mt][nt][1] * s, l0);
                uint32_t h1 = pack_split(acc[mt][nt][2] * s, acc[mt][nt][3] * s, l1);
                *(uint32_t*)&Chi[(size_t)r0 * DMODEL + col]       = h0;
                *(uint32_t*)&Clo[(size_t)r0 * DMODEL + col]       = l0;
                *(uint32_t*)&Chi[(size_t)(r0 + 8) * DMODEL + col] = h1;
                *(uint32_t*)&Clo[(size_t)(r0 + 8) * DMODEL + col] = l1;
            }
        }
    }
}

// ---------------- HMMA flash attention ----------------
// CTA: 128 queries for one (b,h). 8 warps x 16 query rows.
// K/V tiles of 64 keys, cp.async double buffered.
// smem layout (bytes):
//   Qhi 0..16K, Qlo 16K..32K
//   stage s (0/1) at 32K + s*32K: Khi +0, Klo +8K, Vhi +16K, Vlo +24K
//   lgs at 96K + s*256
#define ATT_SMEM (98304 + 512)

__device__ __forceinline__ void att_load_kv(
    char* smem, uint32_t sb, int stage, int kt, int b, int h, int Tk,
    const __nv_bfloat16* kh, const __nv_bfloat16* kl,
    const __nv_bfloat16* vh, const __nv_bfloat16* vl,
    const float* lg, int tid)
{
    const __nv_bfloat16* srcs[4] = {kh, kl, vh, vl};
    uint32_t base = sb + 32768 + stage * 32768;
    #pragma unroll
    for (int i = 0; i < 8; i++) {
        int idx = tid + i * 256;
        int arr = idx >> 9;               // constant per unrolled i
        int rem = idx & 511;
        int r = rem >> 3, f = rem & 7;
        uint32_t dst = base + arr * 8192 + SMEM_SWIZZLE_128B((uint32_t)(r * 128 + f * 16));
        const __nv_bfloat16* src = srcs[arr] +
            ((size_t)(b * Tk + kt * 64 + r) * DMODEL + h * DK) + f * 8;
        cpa16(dst, src);
    }
    if (tid < 16)
        cpa16(sb + 98304 + stage * 256 + tid * 16, lg + b * Tk + kt * 64 + tid * 4);
}

__global__ __launch_bounds__(256) void mma_attn(
    const __nv_bfloat16* __restrict__ qhi, const __nv_bfloat16* __restrict__ qlo,
    const __nv_bfloat16* __restrict__ khi, const __nv_bfloat16* __restrict__ klo,
    const __nv_bfloat16* __restrict__ vhi, const __nv_bfloat16* __restrict__ vlo,
    const float* __restrict__ lgk,
    __nv_bfloat16* __restrict__ ohi, __nv_bfloat16* __restrict__ olo,
    int Tq, int Tk)
{
    extern __shared__ char smem[];
    const uint32_t sb = smem_u32(smem);
    const int tid = threadIdx.x;
    const int wid = tid >> 5;
    const int lane = tid & 31;
    const int b = blockIdx.z;
    const int h = blockIdx.y;
    const int bq = blockIdx.x * 128;
    const int wm = wid * 16;
    const int rofs = ((lane >> 3) & 1) * 8 + (lane & 7);
    const int kofs = ((lane >> 4) & 1) * 16;

    // stage Q (sync), prefetch tile 0 (async)
    #pragma unroll
    for (int i = 0; i < 4; i++) {
        int idx = tid + i * 256;
        int r = idx >> 3, f = idx & 7;
        uint32_t so = SMEM_SWIZZLE_128B((uint32_t)(r * 128 + f * 16));
        size_t g = (size_t)(b * Tq + bq + r) * DMODEL + h * DK;
        *(uint4*)(smem + so)         = ((const uint4*)(qhi + g))[f];
        *(uint4*)(smem + 16384 + so) = ((const uint4*)(qlo + g))[f];
    }
    att_load_kv(smem, sb, 0, 0, b, h, Tk, khi, klo, vhi, vlo, lgk, tid);
    CP_COMMIT();
    __syncthreads();

    // Q fragments (resident)
    uint32_t qfh[4][4], qfl[4][4];
    #pragma unroll
    for (int ks = 0; ks < 4; ks++) {
        uint32_t so = SMEM_SWIZZLE_128B((uint32_t)((wm + rofs) * 128 + ks * 32 + kofs));
        ldsm_x4(qfh[ks], sb + so);
        ldsm_x4(qfl[ks], sb + 16384 + so);
    }

    float o[8][4];
    #pragma unroll
    for (int t = 0; t < 8; t++)
        #pragma unroll
        for (int c = 0; c < 4; c++) o[t][c] = 0.f;
    float m0 = -INFINITY, m1 = -INFINITY, l0 = 0.f, l1 = 0.f;

    const int ntile = Tk / 64;
    for (int kt = 0; kt < ntile; kt++) {
        const int s = kt & 1;
        CP_WAIT0();
        __syncthreads();
        if (kt + 1 < ntile) {
            att_load_kv(smem, sb, s ^ 1, kt + 1, b, h, Tk, khi, klo, vhi, vlo, lgk, tid);
            CP_COMMIT();
        }
        const uint32_t sKh = sb + 32768 + s * 32768;
        const uint32_t sKl = sKh + 8192;
        const uint32_t sVh = sKh + 16384;
        const uint32_t sVl = sKh + 24576;
        const float* lgs = (const float*)(smem + 98304 + s * 256);

        // ---- S = Q K^T (3-term split) ----
        float sd[8][4];
        #pragma unroll
        for (int nt = 0; nt < 8; nt++)
            #pragma unroll
            for (int c = 0; c < 4; c++) sd[nt][c] = 0.f;

        #pragma unroll
        for (int ks = 0; ks < 4; ks++) {
            uint32_t bh[8][2], bl[8][2];
            #pragma unroll
            for (int p = 0; p < 4; p++) {
                uint32_t so = SMEM_SWIZZLE_128B((uint32_t)((p * 16 + rofs) * 128 + ks * 32 + kofs));
                uint32_t t[4];
                ldsm_x4(t, sKh + so);
                bh[2 * p][0] = t[0]; bh[2 * p][1] = t[2];
                bh[2 * p + 1][0] = t[1]; bh[2 * p + 1][1] = t[3];
                ldsm_x4(t, sKl + so);
                bl[2 * p][0] = t[0]; bl[2 * p][1] = t[2];
                bl[2 * p + 1][0] = t[1]; bl[2 * p + 1][1] = t[3];
            }
            #pragma unroll
            for (int nt = 0; nt < 8; nt++) {
                mma16816(sd[nt], qfh[ks], bh[nt]);
                mma16816(sd[nt], qfh[ks], bl[nt]);
                mma16816(sd[nt], qfl[ks], bh[nt]);
            }
        }

        // ---- bias + online softmax ----
        float mt0 = m0, mt1 = m1;
        #pragma unroll
        for (int nt = 0; nt < 8; nt++) {
            int col = nt * 8 + (lane & 3) * 2;
            float lg0 = lgs[col], lg1 = lgs[col + 1];
            sd[nt][0] += lg0; sd[nt][1] += lg1;
            sd[nt][2] += lg0; sd[nt][3] += lg1;
            mt0 = fmaxf(mt0, fmaxf(sd[nt][0], sd[nt][1]));
            mt1 = fmaxf(mt1, fmaxf(sd[nt][2], sd[nt][3]));
        }
        mt0 = fmaxf(mt0, __shfl_xor_sync(0xffffffffu, mt0, 1));
        mt0 = fmaxf(mt0, __shfl_xor_sync(0xffffffffu, mt0, 2));
        mt1 = fmaxf(mt1, __shfl_xor_sync(0xffffffffu, mt1, 1));
        mt1 = fmaxf(mt1, __shfl_xor_sync(0xffffffffu, mt1, 2));
        float c0 = __expf(m0 - mt0);
        float c1 = __expf(m1 - mt1);
        m0 = mt0; m1 = mt1;
        l0 *= c0; l1 *= c1;
        #pragma unroll
        for (int t = 0; t < 8; t++) {
            o[t][0] *= c0; o[t][1] *= c0; o[t][2] *= c1; o[t][3] *= c1;
        }
        #pragma unroll
        for (int nt = 0; nt < 8; nt++) {
            sd[nt][0] = __expf(sd[nt][0] - m0);
            sd[nt][1] = __expf(sd[nt][1] - m0);
            sd[nt][2] = __expf(sd[nt][2] - m1);
            sd[nt][3] = __expf(sd[nt][3] - m1);
            l0 += sd[nt][0] + sd[nt][1];
            l1 += sd[nt][2] + sd[nt][3];
        }

        // ---- O += P V (3-term split) ----
        #pragma unroll
        for (int kb = 0; kb < 4; kb++) {
            uint32_t pah[4], pal[4];
            pah[0] = pack_split(sd[2 * kb][0],     sd[2 * kb][1],     pal[0]);
            pah[1] = pack_split(sd[2 * kb][2],     sd[2 * kb][3],     pal[1]);
            pah[2] = pack_split(sd[2 * kb + 1][0], sd[2 * kb + 1][1], pal[2]);
            pah[3] = pack_split(sd[2 * kb + 1][2], sd[2 * kb + 1][3], pal[3]);
            const int t4 = lane >> 3;
            #pragma unroll
            for (int dp = 0; dp < 4; dp++) {
                uint32_t so = SMEM_SWIZZLE_128B((uint32_t)(
                    (kb * 16 + (t4 & 1) * 8 + (lane & 7)) * 128 +
                    (dp * 16 + (t4 >> 1) * 8) * 2));
                uint32_t vh4[4], vl4[4];
                ldsm_x4_t(vh4, sVh + so);
                ldsm_x4_t(vl4, sVl + so);
                uint32_t b0h[2] = {vh4[0], vh4[1]}, b1h[2] = {vh4[2], vh4[3]};
                uint32_t b0l[2] = {vl4[0], vl4[1]}, b1l[2] = {vl4[2], vl4[3]};
                mma16816(o[2 * dp],     pah, b0h);
                mma16816(o[2 * dp],     pah, b0l);
                mma16816(o[2 * dp],     pal, b0h);
                mma16816(o[2 * dp + 1], pah, b1h);
                mma16816(o[2 * dp + 1], pah, b1l);
                mma16816(o[2 * dp + 1], pal, b1h);
            }
        }
    }

    // ---- finalize ----
    float fl0 = l0 + __shfl_xor_sync(0xffffffffu, l0, 1);
    fl0 += __shfl_xor_sync(0xffffffffu, fl0, 2);
    float fl1 = l1 + __shfl_xor_sync(0xffffffffu, l1, 1);
    fl1 += __shfl_xor_sync(0xffffffffu, fl1, 2);
    float inv0 = 1.0f / fl0, inv1 = 1.0f / fl1;

    const int r0 = bq + wm + (lane >> 2);
    size_t base0 = (size_t)(b * Tq + r0) * DMODEL + h * DK;
    size_t base1 = base0 + (size_t)8 * DMODEL;
    #pragma unroll
    for (int t = 0; t < 8; t++) {
        int col = t * 8 + (lane & 3) * 2;
        uint32_t lo0, lo1;
        uint32_t h0 = pack_split(o[t][0] * inv0, o[t][1] * inv0, lo0);
        uint32_t h1 = pack_split(o[t][2] * inv1, o[t][3] * inv1, lo1);
        *(uint32_t*)&ohi[base0 + col] = h0;
        *(uint32_t*)&olo[base0 + col] = lo0;
        *(uint32_t*)&ohi[base1 + col] = h1;
        *(uint32_t*)&olo[base1 + col] = lo1;
    }
}

// ---------------- evidential gate ----------------
__device__ __forceinline__ float softplusf(float x) {
    return (x > 20.f) ? x : log1pf(expf(x));
}

__global__ __launch_bounds__(256) void gate_kernel(
    const float* __restrict__ t, const float* __restrict__ gW,
    const float* __restrict__ gb, float* __restrict__ g_out,
    float* __restrict__ lg_out, int ntok)
{
    const int warp = threadIdx.x >> 5;
    const int lane = threadIdx.x & 31;
    const int token = blockIdx.x * 8 + warp;
    if (token >= ntok) return;

    const float* tp = t + (size_t)token * DMODEL;
    float p0 = 0.f, p1 = 0.f, p2 = 0.f, p3 = 0.f;
    #pragma unroll
    for (int i = 0; i < 8; i++) {
        int d = lane + i * 32;
        float xv = tp[d];
        p0 += xv * gW[0 * DMODEL + d];
        p1 += xv * gW[1 * DMODEL + d];
        p2 += xv * gW[2 * DMODEL + d];
        p3 += xv * gW[3 * DMODEL + d];
    }
    #pragma unroll
    for (int o = 16; o > 0; o >>= 1) {
        p0 += __shfl_xor_sync(0xffffffffu, p0, o);
        p1 += __shfl_xor_sync(0xffffffffu, p1, o);
        p2 += __shfl_xor_sync(0xffffffffu, p2, o);
        p3 += __shfl_xor_sync(0xffffffffu, p3, o);
    }
    if (lane == 0) {
        float mu    = p0 + gb[0];
        float v     = softplusf(p1 + gb[1]) + 1e-6f;
        float alpha = softplusf(p2 + gb[2]) + 1.0f + 1e-6f;
        float beta  = softplusf(p3 + gb[3]) + 1e-6f;
        float var_ep = beta / (v * (alpha - 1.0f));
        float g = (1.0f / (1.0f + expf(-mu))) * expf(-2.0f * var_ep);
        g = fmaxf(g, 1e-6f);
        g_out[token]  = g;
        lg_out[token] = logf(g);
    }
}

// ---------------- residual add + LayerNorm (optional split emit) ----------------
template <int EMIT>
__global__ __launch_bounds__(256) void add_ln_kernel(
    const float* __restrict__ a, const float* __restrict__ b,
    const float* __restrict__ gamma, const float* __restrict__ beta,
    float* __restrict__ out, __nv_bfloat16* __restrict__ ohi,
    __nv_bfloat16* __restrict__ olo, int ntok)
{
    const int warp = threadIdx.x >> 5;
    const int lane = threadIdx.x & 31;
    const int token = blockIdx.x * 8 + warp;
    if (token >= ntok) return;

    const float* pa = a + (size_t)token * DMODEL;
    const float* pb = b + (size_t)token * DMODEL;
    float v[8];
    float s = 0.f, s2 = 0.f;
    #pragma unroll
    for (int i = 0; i < 8; i++) {
        int d = lane + i * 32;
        float x = pa[d] + pb[d];
        v[i] = x;
        s += x;
        s2 += x * x;
    }
    #pragma unroll
    for (int o = 16; o > 0; o >>= 1) {
        s  += __shfl_xor_sync(0xffffffffu, s, o);
        s2 += __shfl_xor_sync(0xffffffffu, s2, o);
    }
    float mean = s * (1.0f / DMODEL);
    float var  = s2 * (1.0f / DMODEL) - mean * mean;
    float inv  = rsqrtf(var + 1e-5f);
    float* po = out + (size_t)token * DMODEL;
    #pragma unroll
    for (int i = 0; i < 8; i++) {
        int d = lane + i * 32;
        float o = (v[i] - mean) * inv * gamma[d] + beta[d];
        po[d] = o;
        if (EMIT) {
            __nv_bfloat16 h, lo;
            split2(o, h, lo);
            ohi[(size_t)token * DMODEL + d] = h;
            olo[(size_t)token * DMODEL + d] = lo;
        }
    }
}

// ---------------- launch ----------------
#define SMEM_GEMM_DYN (4 * TILE_B)   // 64 KB

extern "C" void kernel_launch(void* const* d_in, const int* in_sizes, int n_in,
                              void* d_out, int out_size)
{
    const float* x    = (const float*)d_in[0];
    const float* y    = (const float*)d_in[1];
    const float* Wqx  = (const float*)d_in[4];
    const float* Wkx  = (const float*)d_in[5];
    const float* Wvx  = (const float*)d_in[6];
    const float* Wqy  = (const float*)d_in[7];
    const float* Wky  = (const float*)d_in[8];
    const float* Wvy  = (const float*)d_in[9];
    const float* gWx  = (const float*)d_in[10];
    const float* gbx  = (const float*)d_in[11];
    const float* gWy  = (const float*)d_in[12];
    const float* gby  = (const float*)d_in[13];
    const float* Wox  = (const float*)d_in[14];
    const float* Woy  = (const float*)d_in[15];
    const float* lnxg = (const float*)d_in[16];
    const float* lnxb = (const float*)d_in[17];
    const float* lnyg = (const float*)d_in[18];
    const float* lnyb = (const float*)d_in[19];
    const float* ffxW = (const float*)d_in[20];
    const float* ffxb = (const float*)d_in[21];
    const float* ffyW = (const float*)d_in[22];
    const float* ffyb = (const float*)d_in[23];
    float* out = (float*)d_out;

    float *t1, *x2a, *y2a, *lgx, *lgy;
    __nv_bfloat16 *xhi, *xlo, *yhi, *ylo;
    __nv_bfloat16 *qxhi, *qxlo, *kxhi, *kxlo, *vxhi, *vxlo;
    __nv_bfloat16 *qyhi, *qylo, *kyhi, *kylo, *vyhi, *vylo;
    __nv_bfloat16 *axhi, *axlo, *ayhi, *aylo;
    __nv_bfloat16 *x2ahi, *x2alo, *y2ahi, *y2alo, *whi, *wlo;
    cudaGetSymbolAddress((void**)&t1,  g_t1);
    cudaGetSymbolAddress((void**)&x2a, g_x2a);
    cudaGetSymbolAddress((void**)&y2a, g_y2a);
    cudaGetSymbolAddress((void**)&lgx, g_lgx);
    cudaGetSymbolAddress((void**)&lgy, g_lgy);
    cudaGetSymbolAddress((void**)&xhi, g_xhi);
    cudaGetSymbolAddress((void**)&xlo, g_xlo);
    cudaGetSymbolAddress((void**)&yhi, g_yhi);
    cudaGetSymbolAddress((void**)&ylo, g_ylo);
    cudaGetSymbolAddress((void**)&qxhi, g_qxhi);
    cudaGetSymbolAddress((void**)&qxlo, g_qxlo);
    cudaGetSymbolAddress((void**)&kxhi, g_kxhi);
    cudaGetSymbolAddress((void**)&kxlo, g_kxlo);
    cudaGetSymbolAddress((void**)&vxhi, g_vxhi);
    cudaGetSymbolAddress((void**)&vxlo, g_vxlo);
    cudaGetSymbolAddress((void**)&qyhi, g_qyhi);
    cudaGetSymbolAddress((void**)&qylo, g_qylo);
    cudaGetSymbolAddress((void**)&kyhi, g_kyhi);
    cudaGetSymbolAddress((void**)&kylo, g_kylo);
    cudaGetSymbolAddress((void**)&vyhi, g_vyhi);
    cudaGetSymbolAddress((void**)&vylo, g_vylo);
    cudaGetSymbolAddress((void**)&axhi, g_axhi);
    cudaGetSymbolAddress((void**)&axlo, g_axlo);
    cudaGetSymbolAddress((void**)&ayhi, g_ayhi);
    cudaGetSymbolAddress((void**)&aylo, g_aylo);
    cudaGetSymbolAddress((void**)&x2ahi, g_x2ahi);
    cudaGetSymbolAddress((void**)&x2alo, g_x2alo);
    cudaGetSymbolAddress((void**)&y2ahi, g_y2ahi);
    cudaGetSymbolAddress((void**)&y2alo, g_y2alo);
    cudaGetSymbolAddress((void**)&whi, g_whi);
    cudaGetSymbolAddress((void**)&wlo, g_wlo);

    cudaFuncSetAttribute(mma_gemm<0, 0>, cudaFuncAttributeMaxDynamicSharedMemorySize, SMEM_GEMM_DYN);
    cudaFuncSetAttribute(mma_gemm<1, 0>, cudaFuncAttributeMaxDynamicSharedMemorySize, SMEM_GEMM_DYN);
    cudaFuncSetAttribute(mma_gemm<0, 1>, cudaFuncAttributeMaxDynamicSharedMemorySize, SMEM_GEMM_DYN);
    cudaFuncSetAttribute(mma_attn, cudaFuncAttributeMaxDynamicSharedMemorySize, ATT_SMEM);

    const int WSZ = DMODEL * DMODEL;  // 65536
    const float QSCL = 0.125f;        // 1/sqrt(64)

    // 1) conversions
    split_kernel<<<MX * DMODEL / 4 / 256, 256>>>(x, xhi, xlo, MX * DMODEL / 4);
    split_kernel<<<MY * DMODEL / 4 / 256, 256>>>(y, yhi, ylo, MY * DMODEL / 4);
    WSrc ws;
    ws.s[0] = Wqx; ws.s[1] = Wkx; ws.s[2] = Wvx;
    ws.s[3] = Wqy; ws.s[4] = Wky; ws.s[5] = Wvy;
    ws.s[6] = Wox; ws.s[7] = Woy; ws.s[8] = ffxW; ws.s[9] = ffyW;
    wsplit_kernel<<<dim3(WSZ / 4 / 256, 10), 256>>>(ws, whi, wlo);

    // 2) gates
    gate_kernel<<<MX / 8, 256>>>(x, gWx, gbx, out + OFF_GX, lgx, MX);
    gate_kernel<<<MY / 8, 256>>>(y, gWy, gby, out + OFF_GY, lgy, MY);

    // 3) QKV projections, emit bf16 splits (q pre-scaled)
    {
        GemmArgs a = {};
        a.Ahi = xhi; a.Alo = xlo;
        a.Whi[0] = whi + 0 * WSZ; a.Wlo[0] = wlo + 0 * WSZ;
        a.Chi[0] = qxhi; a.Clo[0] = qxlo; a.scl[0] = QSCL;
        a.Whi[1] = whi + 1 * WSZ; a.Wlo[1] = wlo + 1 * WSZ;
        a.Chi[1] = kxhi; a.Clo[1] = kxlo; a.scl[1] = 1.f;
        a.Whi[2] = whi + 2 * WSZ; a.Wlo[2] = wlo + 2 * WSZ;
        a.Chi[2] = vxhi; a.Clo[2] = vxlo; a.scl[2] = 1.f;
        mma_gemm<0, 1><<<dim3(2, MX / 128, 3), 256, SMEM_GEMM_DYN>>>(a);
    }
    {
        GemmArgs a = {};
        a.Ahi = yhi; a.Alo = ylo;
        a.Whi[0] = whi + 3 * WSZ; a.Wlo[0] = wlo + 3 * WSZ;
        a.Chi[0] = qyhi; a.Clo[0] = qylo; a.scl[0] = QSCL;
        a.Whi[1] = whi + 4 * WSZ; a.Wlo[1] = wlo + 4 * WSZ;
        a.Chi[1] = kyhi; a.Clo[1] = kylo; a.scl[1] = 1.f;
        a.Whi[2] = whi + 5 * WSZ; a.Wlo[2] = wlo + 5 * WSZ;
        a.Chi[2] = vyhi; a.Clo[2] = vylo; a.scl[2] = 1.f;
        mma_gemm<0, 1><<<dim3(2, MY / 128, 3), 256, SMEM_GEMM_DYN>>>(a);
    }

    // 4) attention (tensor cores)
    mma_attn<<<dim3(NX / 128, NHEAD, BATCH), 256, ATT_SMEM>>>(
        qxhi, qxlo, kyhi, kylo, vyhi, vylo, lgy, axhi, axlo, NX, NY);
    mma_attn<<<dim3(NY / 128, NHEAD, BATCH), 256, ATT_SMEM>>>(
        qyhi, qylo, kxhi, kxlo, vxhi, vxlo, lgx, ayhi, aylo, NY, NX);

    // 5) x branch
    {
        GemmArgs a = {};
        a.Ahi = axhi; a.Alo = axlo;
        a.Whi[0] = whi + 6 * WSZ; a.Wlo[0] = wlo + 6 * WSZ; a.C[0] = t1;
        mma_gemm<0, 0><<<dim3(2, MX / 128, 1), 256, SMEM_GEMM_DYN>>>(a);
    }
    add_ln_kernel<1><<<MX / 8, 256>>>(x, t1, lnxg, lnxb, x2a, x2ahi, x2alo, MX);
    {
        GemmArgs a = {};
        a.Ahi = x2ahi; a.Alo = x2alo;
        a.Whi[0] = whi + 8 * WSZ; a.Wlo[0] = wlo + 8 * WSZ; a.C[0] = t1; a.bias[0] = ffxb;
        mma_gemm<1, 0><<<dim3(2, MX / 128, 1), 256, SMEM_GEMM_DYN>>>(a);
    }
    add_ln_kernel<0><<<MX / 8, 256>>>(x2a, t1, lnxg, lnxb, out + OFF_X2, nullptr, nullptr, MX);

    // 6) y branch
    {
        GemmArgs a = {};
        a.Ahi = ayhi; a.Alo = aylo;
        a.Whi[0] = whi + 7 * WSZ; a.Wlo[0] = wlo + 7 * WSZ; a.C[0] = t1;
        mma_gemm<0, 0><<<dim3(2, MY / 128, 1), 256, SMEM_GEMM_DYN>>>(a);
    }
    add_ln_kernel<1><<<MY / 8, 256>>>(y, t1, lnyg, lnyb, y2a, y2ahi, y2alo, MY);
    {
        GemmArgs a = {};
        a.Ahi = y2ahi; a.Alo = y2alo;
        a.Whi[0] = whi + 9 * WSZ; a.Wlo[0] = wlo + 9 * WSZ; a.C[0] = t1; a.bias[0] = ffyb;
        mma_gemm<1, 0><<<dim3(2, MY / 128, 1), 256, SMEM_GEMM_DYN>>>(a);
    }
    add_ln_kernel<0><<<MY / 8, 256>>>(y2a, t1, lnyg, lnyb, out + OFF_Y2, nullptr, nullptr, MY);
}

// round 5
// speedup vs baseline: 2.7467x; 1.0853x over previous
#include <cuda_runtime.h>
#include <cuda_bf16.h>
#include <math.h>
#include <stdint.h>

// ---------------- problem constants ----------------
#define BATCH 16
#define NX 512
#define NY 1024
#define DMODEL 256
#define NHEAD 4
#define DK 64
#define MX (BATCH * NX)   // 8192
#define MY (BATCH * NY)   // 16384

#define OFF_X2 0
#define OFF_Y2 (MX * DMODEL)
#define OFF_GX (OFF_Y2 + MY * DMODEL)
#define OFF_GY (OFF_GX + MX)

// ---------------- scratch ----------------
__device__ float g_t1[MY * DMODEL];
__device__ float g_x2a[MX * DMODEL];
__device__ float g_y2a[MY * DMODEL];
__device__ float g_lgx[MX];
__device__ float g_lgy[MY];

__device__ __nv_bfloat16 g_xhi[MX * DMODEL];
__device__ __nv_bfloat16 g_xlo[MX * DMODEL];
__device__ __nv_bfloat16 g_yhi[MY * DMODEL];
__device__ __nv_bfloat16 g_ylo[MY * DMODEL];
__device__ __nv_bfloat16 g_qxhi[MX * DMODEL];
__device__ __nv_bfloat16 g_qxlo[MX * DMODEL];
__device__ __nv_bfloat16 g_kxhi[MX * DMODEL];
__device__ __nv_bfloat16 g_kxlo[MX * DMODEL];
__device__ __nv_bfloat16 g_vxhi[MX * DMODEL];
__device__ __nv_bfloat16 g_vxlo[MX * DMODEL];
__device__ __nv_bfloat16 g_qyhi[MY * DMODEL];
__device__ __nv_bfloat16 g_qylo[MY * DMODEL];
__device__ __nv_bfloat16 g_kyhi[MY * DMODEL];
__device__ __nv_bfloat16 g_kylo[MY * DMODEL];
__device__ __nv_bfloat16 g_vyhi[MY * DMODEL];
__device__ __nv_bfloat16 g_vylo[MY * DMODEL];
__device__ __nv_bfloat16 g_axhi[MX * DMODEL];
__device__ __nv_bfloat16 g_axlo[MX * DMODEL];
__device__ __nv_bfloat16 g_ayhi[MY * DMODEL];
__device__ __nv_bfloat16 g_aylo[MY * DMODEL];
__device__ __nv_bfloat16 g_x2ahi[MX * DMODEL];
__device__ __nv_bfloat16 g_x2alo[MX * DMODEL];
__device__ __nv_bfloat16 g_y2ahi[MY * DMODEL];
__device__ __nv_bfloat16 g_y2alo[MY * DMODEL];
__device__ __nv_bfloat16 g_whi[10 * DMODEL * DMODEL];
__device__ __nv_bfloat16 g_wlo[10 * DMODEL * DMODEL];

// ---------------- helpers ----------------
__device__ __forceinline__ uint32_t smem_u32(const void* p) {
    uint32_t a;
    asm("{ .reg .u64 t; cvta.to.shared.u64 t, %1; cvt.u32.u64 %0, t; }"
        : "=r"(a) : "l"(p));
    return a;
}

#define SMEM_SWIZZLE_128B(off) ((off) ^ (((off) >> 3) & 0x70))

__device__ __forceinline__ void ldsm_x4(uint32_t* r, uint32_t addr) {
    asm volatile("ldmatrix.sync.aligned.m8n8.x4.shared.b16 {%0,%1,%2,%3}, [%4];"
                 : "=r"(r[0]), "=r"(r[1]), "=r"(r[2]), "=r"(r[3]) : "r"(addr));
}

__device__ __forceinline__ void ldsm_x4_t(uint32_t* r, uint32_t addr) {
    asm volatile("ldmatrix.sync.aligned.m8n8.x4.trans.shared.b16 {%0,%1,%2,%3}, [%4];"
                 : "=r"(r[0]), "=r"(r[1]), "=r"(r[2]), "=r"(r[3]) : "r"(addr));
}

__device__ __forceinline__ void mma16816(float* d, const uint32_t* a, const uint32_t* b) {
    asm volatile(
        "mma.sync.aligned.m16n8k16.row.col.f32.bf16.bf16.f32 "
        "{%0,%1,%2,%3}, {%4,%5,%6,%7}, {%8,%9}, {%0,%1,%2,%3};"
        : "+f"(d[0]), "+f"(d[1]), "+f"(d[2]), "+f"(d[3])
        : "r"(a[0]), "r"(a[1]), "r"(a[2]), "r"(a[3]), "r"(b[0]), "r"(b[1]));
}

__device__ __forceinline__ void cpa16(uint32_t dst, const void* src) {
    asm volatile("cp.async.cg.shared.global [%0], [%1], 16;" :: "r"(dst), "l"(src));
}
#define CP_COMMIT() asm volatile("cp.async.commit_group;" ::: "memory")
#define CP_WAIT0()  asm volatile("cp.async.wait_group 0;" ::: "memory")
#define CP_WAIT1()  asm volatile("cp.async.wait_group 1;" ::: "memory")

__device__ __forceinline__ void split2(float v, __nv_bfloat16& hi, __nv_bfloat16& lo) {
    hi = __float2bfloat16(v);
    lo = __float2bfloat16(v - __bfloat162float(hi));
}

// pack two floats to bf16x2 hi, return lo via out-param
__device__ __forceinline__ uint32_t pack_split(float a, float b, uint32_t& lo) {
    __nv_bfloat16 ha = __float2bfloat16(a), hb = __float2bfloat16(b);
    __nv_bfloat16 la = __float2bfloat16(a - __bfloat162float(ha));
    __nv_bfloat16 lb = __float2bfloat16(b - __bfloat162float(hb));
    __nv_bfloat162 H(ha, hb), L(la, lb);
    lo = *(uint32_t*)&L;
    return *(uint32_t*)&H;
}

// ---------------- conversion kernels ----------------
__global__ __launch_bounds__(256) void split_kernel(
    const float* __restrict__ src, __nv_bfloat16* __restrict__ hi,
    __nv_bfloat16* __restrict__ lo, int n4)
{
    int i = blockIdx.x * 256 + threadIdx.x;
    if (i >= n4) return;
    float4 v = ((const float4*)src)[i];
    uint32_t l0, l1;
    uint32_t h0 = pack_split(v.x, v.y, l0);
    uint32_t h1 = pack_split(v.z, v.w, l1);
    ((uint32_t*)hi)[2 * i]     = h0;
    ((uint32_t*)hi)[2 * i + 1] = h1;
    ((uint32_t*)lo)[2 * i]     = l0;
    ((uint32_t*)lo)[2 * i + 1] = l1;
}

struct WSrc { const float* s[10]; };

__global__ __launch_bounds__(256) void wsplit_kernel(
    WSrc ws, __nv_bfloat16* __restrict__ hi, __nv_bfloat16* __restrict__ lo)
{
    int m = blockIdx.y;
    int i = blockIdx.x * 256 + threadIdx.x;
    float4 v = ((const float4*)ws.s[m])[i];
    uint32_t l0, l1;
    uint32_t h0 = pack_split(v.x, v.y, l0);
    uint32_t h1 = pack_split(v.z, v.w, l1);
    size_t base = (size_t)m * DMODEL * DMODEL / 2 + 2 * i;
    ((uint32_t*)hi)[base]     = h0;
    ((uint32_t*)hi)[base + 1] = h1;
    ((uint32_t*)lo)[base]     = l0;
    ((uint32_t*)lo)[base + 1] = l1;
}

// ---------------- HMMA GEMM (cp.async double-buffered) ----------------
// C[M,256] = act(A[M,256] @ W[256,256]^T + bias)
// bf16-split (3 terms), fp32 accum, mma.sync m16n8k16.
// CTA tile 128x128, K-chunks of 64, 8 warps (2x4), warp tile 64x32.
// 2 smem stages x (Ahi,Alo,Bhi,Blo) x 16KB = 128KB dynamic smem.
#define TILE_B 16384
#define STAGE_B (4 * TILE_B)           // 64KB
#define SMEM_GEMM_DYN (2 * STAGE_B)    // 128KB

struct GemmArgs {
    const __nv_bfloat16* Ahi;
    const __nv_bfloat16* Alo;
    const __nv_bfloat16* Whi[3];
    const __nv_bfloat16* Wlo[3];
    const float* bias[3];
    float* C[3];
    __nv_bfloat16* Chi[3];
    __nv_bfloat16* Clo[3];
    float scl[3];
};

__device__ __forceinline__ void gemm_load_stage(
    uint32_t sb, int stage,
    const __nv_bfloat16* Ahi, const __nv_bfloat16* Alo,
    const __nv_bfloat16* Whi, const __nv_bfloat16* Wlo,
    int bm, int bn, int k0, int tid)
{
    const __nv_bfloat16* srcs[4] = {Ahi, Alo, Whi, Wlo};
    const int rb[4] = {bm, bm, bn, bn};
    const uint32_t base = sb + stage * STAGE_B;
    #pragma unroll
    for (int i = 0; i < 16; i++) {
        int idx = tid + i * 256;          // 0..4095
        int arr = idx >> 10;              // constant per unrolled i
        int rem = idx & 1023;
        int r = rem >> 3, f = rem & 7;
        uint32_t dst = base + arr * TILE_B + SMEM_SWIZZLE_128B((uint32_t)(r * 128 + f * 16));
        cpa16(dst, srcs[arr] + (size_t)(rb[arr] + r) * DMODEL + k0 + f * 8);
    }
}

template <int ACT, int EMIT>
__global__ __launch_bounds__(256) void mma_gemm(GemmArgs args)
{
    extern __shared__ char smem[];
    const uint32_t sb = smem_u32(smem);

    const int tid = threadIdx.x;
    const int wid = tid >> 5;
    const int lane = tid & 31;
    const int z = blockIdx.z;
    const int bm = blockIdx.y * 128;
    const int bn = blockIdx.x * 128;
    const int wm = (wid & 1) * 64;
    const int wn = (wid >> 1) * 32;

    const __nv_bfloat16* __restrict__ Ahi = args.Ahi;
    const __nv_bfloat16* __restrict__ Alo = args.Alo;
    const __nv_bfloat16* __restrict__ Whi = args.Whi[z];
    const __nv_bfloat16* __restrict__ Wlo = args.Wlo[z];

    float acc[4][4][4];
    #pragma unroll
    for (int i = 0; i < 4; i++)
        #pragma unroll
        for (int j = 0; j < 4; j++)
            #pragma unroll
            for (int c = 0; c < 4; c++) acc[i][j][c] = 0.f;

    const int rofs = ((lane >> 3) & 1) * 8 + (lane & 7);
    const int kofs = ((lane >> 4) & 1) * 16;

    gemm_load_stage(sb, 0, Ahi, Alo, Whi, Wlo, bm, bn, 0, tid);
    CP_COMMIT();

    for (int kc = 0; kc < 4; kc++) {
        const int s = kc & 1;
        if (kc + 1 < 4) {
            gemm_load_stage(sb, s ^ 1, Ahi, Alo, Whi, Wlo, bm, bn, (kc + 1) * 64, tid);
            CP_COMMIT();
            CP_WAIT1();
        } else {
            CP_WAIT0();
        }
        __syncthreads();

        const uint32_t sAhi = sb + s * STAGE_B;
        const uint32_t sAlo = sAhi + TILE_B;
        const uint32_t sBhi = sAhi + 2 * TILE_B;
        const uint32_t sBlo = sAhi + 3 * TILE_B;

        #pragma unroll
        for (int ks = 0; ks < 4; ks++) {
            const int kb = ks * 32 + kofs;
            uint32_t ah[4][4], al[4][4], bh[4][2], bl[4][2];
            #pragma unroll
            for (int mt = 0; mt < 4; mt++) {
                int row = wm + mt * 16 + rofs;
                uint32_t so = SMEM_SWIZZLE_128B((uint32_t)(row * 128 + kb));
                ldsm_x4(ah[mt], sAhi + so);
                ldsm_x4(al[mt], sAlo + so);
            }
            #pragma unroll
            for (int p = 0; p < 2; p++) {
                int row = wn + p * 16 + rofs;
                uint32_t so = SMEM_SWIZZLE_128B((uint32_t)(row * 128 + kb));
                uint32_t t[4];
                ldsm_x4(t, sBhi + so);
                bh[2 * p][0] = t[0]; bh[2 * p][1] = t[2];
                bh[2 * p + 1][0] = t[1]; bh[2 * p + 1][1] = t[3];
                ldsm_x4(t, sBlo + so);
                bl[2 * p][0] = t[0]; bl[2 * p][1] = t[2];
                bl[2 * p + 1][0] = t[1]; bl[2 * p + 1][1] = t[3];
            }
            #pragma unroll
            for (int mt = 0; mt < 4; mt++)
                #pragma unroll
                for (int nt = 0; nt < 4; nt++)
                    mma16816(acc[mt][nt], ah[mt], bh[nt]);
            #pragma unroll
            for (int mt = 0; mt < 4; mt++)
                #pragma unroll
                for (int nt = 0; nt < 4; nt++)
                    mma16816(acc[mt][nt], ah[mt], bl[nt]);
            #pragma unroll
            for (int mt = 0; mt < 4; mt++)
                #pragma unroll
                for (int nt = 0; nt < 4; nt++)
                    mma16816(acc[mt][nt], al[mt], bh[nt]);
        }
        __syncthreads();
    }

    const int rbase = bm + wm + (lane >> 2);
    const int cbase = bn + wn + (lane & 3) * 2;
    if (EMIT == 0) {
        float* __restrict__ Cz = args.C[z];
        const float* __restrict__ bz = args.bias[z];
        #pragma unroll
        for (int mt = 0; mt < 4; mt++) {
            #pragma unroll
            for (int nt = 0; nt < 4; nt++) {
                int col = cbase + nt * 8;
                float v0 = acc[mt][nt][0], v1 = acc[mt][nt][1];
                float v2 = acc[mt][nt][2], v3 = acc[mt][nt][3];
                if (ACT == 1) {
                    float b0 = bz[col], b1 = bz[col + 1];
                    v0 += b0; v1 += b1; v2 += b0; v3 += b1;
                    v0 = v0 / (1.0f + __expf(-v0));
                    v1 = v1 / (1.0f + __expf(-v1));
                    v2 = v2 / (1.0f + __expf(-v2));
                    v3 = v3 / (1.0f + __expf(-v3));
                }
                int r0 = rbase + mt * 16;
                *(float2*)&Cz[(size_t)r0 * DMODEL + col]       = make_float2(v0, v1);
                *(float2*)&Cz[(size_t)(r0 + 8) * DMODEL + col] = make_float2(v2, v3);
            }
        }
    } else {
        const float s = args.scl[z];
        __nv_bfloat16* __restrict__ Chi = args.Chi[z];
        __nv_bfloat16* __restrict__ Clo = args.Clo[z];
        #pragma unroll
        for (int mt = 0; mt < 4; mt++) {
            #pragma unroll
            for (int nt = 0; nt < 4; nt++) {
                int col = cbase + nt * 8;
                int r0 = rbase + mt * 16;
                uint32_t l0, l1;
                uint32_t h0 = pack_split(acc[mt][nt][0] * s, acc[mt][nt][1] * s, l0);
                uint32_t h1 = pack_split(acc[mt][nt][2] * s, acc[mt][nt][3] * s, l1);
                *(uint32_t*)&Chi[(size_t)r0 * DMODEL + col]       = h0;
                *(uint32_t*)&Clo[(size_t)r0 * DMODEL + col]       = l0;
                *(uint32_t*)&Chi[(size_t)(r0 + 8) * DMODEL + col] = h1;
                *(uint32_t*)&Clo[(size_t)(r0 + 8) * DMODEL + col] = l1;
            }
        }
    }
}

// ---------------- HMMA flash attention ----------------
// CTA: 128 queries for one (b,h). 8 warps x 16 query rows.
// K/V tiles of 64 keys, cp.async double buffered.
#define ATT_SMEM (98304 + 512)

__device__ __forceinline__ void att_load_kv(
    char* smem, uint32_t sb, int stage, int kt, int b, int h, int Tk,
    const __nv_bfloat16* kh, const __nv_bfloat16* kl,
    const __nv_bfloat16* vh, const __nv_bfloat16* vl,
    const float* lg, int tid)
{
    const __nv_bfloat16* srcs[4] = {kh, kl, vh, vl};
    uint32_t base = sb + 32768 + stage * 32768;
    #pragma unroll
    for (int i = 0; i < 8; i++) {
        int idx = tid + i * 256;
        int arr = idx >> 9;
        int rem = idx & 511;
        int r = rem >> 3, f = rem & 7;
        uint32_t dst = base + arr * 8192 + SMEM_SWIZZLE_128B((uint32_t)(r * 128 + f * 16));
        const __nv_bfloat16* src = srcs[arr] +
            ((size_t)(b * Tk + kt * 64 + r) * DMODEL + h * DK) + f * 8;
        cpa16(dst, src);
    }
    if (tid < 16)
        cpa16(sb + 98304 + stage * 256 + tid * 16, lg + b * Tk + kt * 64 + tid * 4);
}

__global__ __launch_bounds__(256) void mma_attn(
    const __nv_bfloat16* __restrict__ qhi, const __nv_bfloat16* __restrict__ qlo,
    const __nv_bfloat16* __restrict__ khi, const __nv_bfloat16* __restrict__ klo,
    const __nv_bfloat16* __restrict__ vhi, const __nv_bfloat16* __restrict__ vlo,
    const float* __restrict__ lgk,
    __nv_bfloat16* __restrict__ ohi, __nv_bfloat16* __restrict__ olo,
    int Tq, int Tk)
{
    extern __shared__ char smem[];
    const uint32_t sb = smem_u32(smem);
    const int tid = threadIdx.x;
    const int wid = tid >> 5;
    const int lane = tid & 31;
    const int b = blockIdx.z;
    const int h = blockIdx.y;
    const int bq = blockIdx.x * 128;
    const int wm = wid * 16;
    const int rofs = ((lane >> 3) & 1) * 8 + (lane & 7);
    const int kofs = ((lane >> 4) & 1) * 16;

    #pragma unroll
    for (int i = 0; i < 4; i++) {
        int idx = tid + i * 256;
        int r = idx >> 3, f = idx & 7;
        uint32_t so = SMEM_SWIZZLE_128B((uint32_t)(r * 128 + f * 16));
        size_t g = (size_t)(b * Tq + bq + r) * DMODEL + h * DK;
        *(uint4*)(smem + so)         = ((const uint4*)(qhi + g))[f];
        *(uint4*)(smem + 16384 + so) = ((const uint4*)(qlo + g))[f];
    }
    att_load_kv(smem, sb, 0, 0, b, h, Tk, khi, klo, vhi, vlo, lgk, tid);
    CP_COMMIT();
    __syncthreads();

    uint32_t qfh[4][4], qfl[4][4];
    #pragma unroll
    for (int ks = 0; ks < 4; ks++) {
        uint32_t so = SMEM_SWIZZLE_128B((uint32_t)((wm + rofs) * 128 + ks * 32 + kofs));
        ldsm_x4(qfh[ks], sb + so);
        ldsm_x4(qfl[ks], sb + 16384 + so);
    }

    float o[8][4];
    #pragma unroll
    for (int t = 0; t < 8; t++)
        #pragma unroll
        for (int c = 0; c < 4; c++) o[t][c] = 0.f;
    float m0 = -INFINITY, m1 = -INFINITY, l0 = 0.f, l1 = 0.f;

    const int ntile = Tk / 64;
    for (int kt = 0; kt < ntile; kt++) {
        const int s = kt & 1;
        CP_WAIT0();
        __syncthreads();
        if (kt + 1 < ntile) {
            att_load_kv(smem, sb, s ^ 1, kt + 1, b, h, Tk, khi, klo, vhi, vlo, lgk, tid);
            CP_COMMIT();
        }
        const uint32_t sKh = sb + 32768 + s * 32768;
        const uint32_t sKl = sKh + 8192;
        const uint32_t sVh = sKh + 16384;
        const uint32_t sVl = sKh + 24576;
        const float* lgs = (const float*)(smem + 98304 + s * 256);

        float sd[8][4];
        #pragma unroll
        for (int nt = 0; nt < 8; nt++)
            #pragma unroll
            for (int c = 0; c < 4; c++) sd[nt][c] = 0.f;

        #pragma unroll
        for (int ks = 0; ks < 4; ks++) {
            uint32_t bh[8][2], bl[8][2];
            #pragma unroll
            for (int p = 0; p < 4; p++) {
                uint32_t so = SMEM_SWIZZLE_128B((uint32_t)((p * 16 + rofs) * 128 + ks * 32 + kofs));
                uint32_t t[4];
                ldsm_x4(t, sKh + so);
                bh[2 * p][0] = t[0]; bh[2 * p][1] = t[2];
                bh[2 * p + 1][0] = t[1]; bh[2 * p + 1][1] = t[3];
                ldsm_x4(t, sKl + so);
                bl[2 * p][0] = t[0]; bl[2 * p][1] = t[2];
                bl[2 * p + 1][0] = t[1]; bl[2 * p + 1][1] = t[3];
            }
            #pragma unroll
            for (int nt = 0; nt < 8; nt++) {
                mma16816(sd[nt], qfh[ks], bh[nt]);
                mma16816(sd[nt], qfh[ks], bl[nt]);
                mma16816(sd[nt], qfl[ks], bh[nt]);
            }
        }

        float mt0 = m0, mt1 = m1;
        #pragma unroll
        for (int nt = 0; nt < 8; nt++) {
            int col = nt * 8 + (lane & 3) * 2;
            float lg0 = lgs[col], lg1 = lgs[col + 1];
            sd[nt][0] += lg0; sd[nt][1] += lg1;
            sd[nt][2] += lg0; sd[nt][3] += lg1;
            mt0 = fmaxf(mt0, fmaxf(sd[nt][0], sd[nt][1]));
            mt1 = fmaxf(mt1, fmaxf(sd[nt][2], sd[nt][3]));
        }
        mt0 = fmaxf(mt0, __shfl_xor_sync(0xffffffffu, mt0, 1));
        mt0 = fmaxf(mt0, __shfl_xor_sync(0xffffffffu, mt0, 2));
        mt1 = fmaxf(mt1, __shfl_xor_sync(0xffffffffu, mt1, 1));
        mt1 = fmaxf(mt1, __shfl_xor_sync(0xffffffffu, mt1, 2));
        float c0 = __expf(m0 - mt0);
        float c1 = __expf(m1 - mt1);
        m0 = mt0; m1 = mt1;
        l0 *= c0; l1 *= c1;
        #pragma unroll
        for (int t = 0; t < 8; t++) {
            o[t][0] *= c0; o[t][1] *= c0; o[t][2] *= c1; o[t][3] *= c1;
        }
        #pragma unroll
        for (int nt = 0; nt < 8; nt++) {
            sd[nt][0] = __expf(sd[nt][0] - m0);
            sd[nt][1] = __expf(sd[nt][1] - m0);
            sd[nt][2] = __expf(sd[nt][2] - m1);
            sd[nt][3] = __expf(sd[nt][3] - m1);
            l0 += sd[nt][0] + sd[nt][1];
            l1 += sd[nt][2] + sd[nt][3];
        }

        #pragma unroll
        for (int kb = 0; kb < 4; kb++) {
            uint32_t pah[4], pal[4];
            pah[0] = pack_split(sd[2 * kb][0],     sd[2 * kb][1],     pal[0]);
            pah[1] = pack_split(sd[2 * kb][2],     sd[2 * kb][3],     pal[1]);
            pah[2] = pack_split(sd[2 * kb + 1][0], sd[2 * kb + 1][1], pal[2]);
            pah[3] = pack_split(sd[2 * kb + 1][2], sd[2 * kb + 1][3], pal[3]);
            const int t4 = lane >> 3;
            #pragma unroll
            for (int dp = 0; dp < 4; dp++) {
                uint32_t so = SMEM_SWIZZLE_128B((uint32_t)(
                    (kb * 16 + (t4 & 1) * 8 + (lane & 7)) * 128 +
                    (dp * 16 + (t4 >> 1) * 8) * 2));
                uint32_t vh4[4], vl4[4];
                ldsm_x4_t(vh4, sVh + so);
                ldsm_x4_t(vl4, sVl + so);
                uint32_t b0h[2] = {vh4[0], vh4[1]}, b1h[2] = {vh4[2], vh4[3]};
                uint32_t b0l[2] = {vl4[0], vl4[1]}, b1l[2] = {vl4[2], vl4[3]};
                mma16816(o[2 * dp],     pah, b0h);
                mma16816(o[2 * dp],     pah, b0l);
                mma16816(o[2 * dp],     pal, b0h);
                mma16816(o[2 * dp + 1], pah, b1h);
                mma16816(o[2 * dp + 1], pah, b1l);
                mma16816(o[2 * dp + 1], pal, b1h);
            }
        }
    }

    float fl0 = l0 + __shfl_xor_sync(0xffffffffu, l0, 1);
    fl0 += __shfl_xor_sync(0xffffffffu, fl0, 2);
    float fl1 = l1 + __shfl_xor_sync(0xffffffffu, l1, 1);
    fl1 += __shfl_xor_sync(0xffffffffu, fl1, 2);
    float inv0 = 1.0f / fl0, inv1 = 1.0f / fl1;

    const int r0 = bq + wm + (lane >> 2);
    size_t base0 = (size_t)(b * Tq + r0) * DMODEL + h * DK;
    size_t base1 = base0 + (size_t)8 * DMODEL;
    #pragma unroll
    for (int t = 0; t < 8; t++) {
        int col = t * 8 + (lane & 3) * 2;
        uint32_t lo0, lo1;
        uint32_t h0 = pack_split(o[t][0] * inv0, o[t][1] * inv0, lo0);
        uint32_t h1 = pack_split(o[t][2] * inv1, o[t][3] * inv1, lo1);
        *(uint32_t*)&ohi[base0 + col] = h0;
        *(uint32_t*)&olo[base0 + col] = lo0;
        *(uint32_t*)&ohi[base1 + col] = h1;
        *(uint32_t*)&olo[base1 + col] = lo1;
    }
}

// ---------------- evidential gate ----------------
__device__ __forceinline__ float softplusf(float x) {
    return (x > 20.f) ? x : log1pf(expf(x));
}

__global__ __launch_bounds__(256) void gate_kernel(
    const float* __restrict__ t, const float* __restrict__ gW,
    const float* __restrict__ gb, float* __restrict__ g_out,
    float* __restrict__ lg_out, int ntok)
{
    const int warp = threadIdx.x >> 5;
    const int lane = threadIdx.x & 31;
    const int token = blockIdx.x * 8 + warp;
    if (token >= ntok) return;

    const float* tp = t + (size_t)token * DMODEL;
    float p0 = 0.f, p1 = 0.f, p2 = 0.f, p3 = 0.f;
    #pragma unroll
    for (int i = 0; i < 8; i++) {
        int d = lane + i * 32;
        float xv = tp[d];
        p0 += xv * gW[0 * DMODEL + d];
        p1 += xv * gW[1 * DMODEL + d];
        p2 += xv * gW[2 * DMODEL + d];
        p3 += xv * gW[3 * DMODEL + d];
    }
    #pragma unroll
    for (int o = 16; o > 0; o >>= 1) {
        p0 += __shfl_xor_sync(0xffffffffu, p0, o);
        p1 += __shfl_xor_sync(0xffffffffu, p1, o);
        p2 += __shfl_xor_sync(0xffffffffu, p2, o);
        p3 += __shfl_xor_sync(0xffffffffu, p3, o);
    }
    if (lane == 0) {
        float mu    = p0 + gb[0];
        float v     = softplusf(p1 + gb[1]) + 1e-6f;
        float alpha = softplusf(p2 + gb[2]) + 1.0f + 1e-6f;
        float beta  = softplusf(p3 + gb[3]) + 1e-6f;
        float var_ep = beta / (v * (alpha - 1.0f));
        float g = (1.0f / (1.0f + expf(-mu))) * expf(-2.0f * var_ep);
        g = fmaxf(g, 1e-6f);
        g_out[token]  = g;
        lg_out[token] = logf(g);
    }
}

// ---------------- residual add + LayerNorm (optional split emit) ----------------
template <int EMIT>
__global__ __launch_bounds__(256) void add_ln_kernel(
    const float* __restrict__ a, const float* __restrict__ b,
    const float* __restrict__ gamma, const float* __restrict__ beta,
    float* __restrict__ out, __nv_bfloat16* __restrict__ ohi,
    __nv_bfloat16* __restrict__ olo, int ntok)
{
    const int warp = threadIdx.x >> 5;
    const int lane = threadIdx.x & 31;
    const int token = blockIdx.x * 8 + warp;
    if (token >= ntok) return;

    const float* pa = a + (size_t)token * DMODEL;
    const float* pb = b + (size_t)token * DMODEL;
    float v[8];
    float s = 0.f, s2 = 0.f;
    #pragma unroll
    for (int i = 0; i < 8; i++) {
        int d = lane + i * 32;
        float x = pa[d] + pb[d];
        v[i] = x;
        s += x;
        s2 += x * x;
    }
    #pragma unroll
    for (int o = 16; o > 0; o >>= 1) {
        s  += __shfl_xor_sync(0xffffffffu, s, o);
        s2 += __shfl_xor_sync(0xffffffffu, s2, o);
    }
    float mean = s * (1.0f / DMODEL);
    float var  = s2 * (1.0f / DMODEL) - mean * mean;
    float inv  = rsqrtf(var + 1e-5f);
    float* po = out + (size_t)token * DMODEL;
    #pragma unroll
    for (int i = 0; i < 8; i++) {
        int d = lane + i * 32;
        float o = (v[i] - mean) * inv * gamma[d] + beta[d];
        po[d] = o;
        if (EMIT) {
            __nv_bfloat16 h, lo;
            split2(o, h, lo);
            ohi[(size_t)token * DMODEL + d] = h;
            olo[(size_t)token * DMODEL + d] = lo;
        }
    }
}

// ---------------- launch ----------------
extern "C" void kernel_launch(void* const* d_in, const int* in_sizes, int n_in,
                              void* d_out, int out_size)
{
    const float* x    = (const float*)d_in[0];
    const float* y    = (const float*)d_in[1];
    const float* Wqx  = (const float*)d_in[4];
    const float* Wkx  = (const float*)d_in[5];
    const float* Wvx  = (const float*)d_in[6];
    const float* Wqy  = (const float*)d_in[7];
    const float* Wky  = (const float*)d_in[8];
    const float* Wvy  = (const float*)d_in[9];
    const float* gWx  = (const float*)d_in[10];
    const float* gbx  = (const float*)d_in[11];
    const float* gWy  = (const float*)d_in[12];
    const float* gby  = (const float*)d_in[13];
    const float* Wox  = (const float*)d_in[14];
    const float* Woy  = (const float*)d_in[15];
    const float* lnxg = (const float*)d_in[16];
    const float* lnxb = (const float*)d_in[17];
    const float* lnyg = (const float*)d_in[18];
    const float* lnyb = (const float*)d_in[19];
    const float* ffxW = (const float*)d_in[20];
    const float* ffxb = (const float*)d_in[21];
    const float* ffyW = (const float*)d_in[22];
    const float* ffyb = (const float*)d_in[23];
    float* out = (float*)d_out;

    float *t1, *x2a, *y2a, *lgx, *lgy;
    __nv_bfloat16 *xhi, *xlo, *yhi, *ylo;
    __nv_bfloat16 *qxhi, *qxlo, *kxhi, *kxlo, *vxhi, *vxlo;
    __nv_bfloat16 *qyhi, *qylo, *kyhi, *kylo, *vyhi, *vylo;
    __nv_bfloat16 *axhi, *axlo, *ayhi, *aylo;
    __nv_bfloat16 *x2ahi, *x2alo, *y2ahi, *y2alo, *whi, *wlo;
    cudaGetSymbolAddress((void**)&t1,  g_t1);
    cudaGetSymbolAddress((void**)&x2a, g_x2a);
    cudaGetSymbolAddress((void**)&y2a, g_y2a);
    cudaGetSymbolAddress((void**)&lgx, g_lgx);
    cudaGetSymbolAddress((void**)&lgy, g_lgy);
    cudaGetSymbolAddress((void**)&xhi, g_xhi);
    cudaGetSymbolAddress((void**)&xlo, g_xlo);
    cudaGetSymbolAddress((void**)&yhi, g_yhi);
    cudaGetSymbolAddress((void**)&ylo, g_ylo);
    cudaGetSymbolAddress((void**)&qxhi, g_qxhi);
    cudaGetSymbolAddress((void**)&qxlo, g_qxlo);
    cudaGetSymbolAddress((void**)&kxhi, g_kxhi);
    cudaGetSymbolAddress((void**)&kxlo, g_kxlo);
    cudaGetSymbolAddress((void**)&vxhi, g_vxhi);
    cudaGetSymbolAddress((void**)&vxlo, g_vxlo);
    cudaGetSymbolAddress((void**)&qyhi, g_qyhi);
    cudaGetSymbolAddress((void**)&qylo, g_qylo);
    cudaGetSymbolAddress((void**)&kyhi, g_kyhi);
    cudaGetSymbolAddress((void**)&kylo, g_kylo);
    cudaGetSymbolAddress((void**)&vyhi, g_vyhi);
    cudaGetSymbolAddress((void**)&vylo, g_vylo);
    cudaGetSymbolAddress((void**)&axhi, g_axhi);
    cudaGetSymbolAddress((void**)&axlo, g_axlo);
    cudaGetSymbolAddress((void**)&ayhi, g_ayhi);
    cudaGetSymbolAddress((void**)&aylo, g_aylo);
    cudaGetSymbolAddress((void**)&x2ahi, g_x2ahi);
    cudaGetSymbolAddress((void**)&x2alo, g_x2alo);
    cudaGetSymbolAddress((void**)&y2ahi, g_y2ahi);
    cudaGetSymbolAddress((void**)&y2alo, g_y2alo);
    cudaGetSymbolAddress((void**)&whi, g_whi);
    cudaGetSymbolAddress((void**)&wlo, g_wlo);

    cudaFuncSetAttribute(mma_gemm<0, 0>, cudaFuncAttributeMaxDynamicSharedMemorySize, SMEM_GEMM_DYN);
    cudaFuncSetAttribute(mma_gemm<1, 0>, cudaFuncAttributeMaxDynamicSharedMemorySize, SMEM_GEMM_DYN);
    cudaFuncSetAttribute(mma_gemm<0, 1>, cudaFuncAttributeMaxDynamicSharedMemorySize, SMEM_GEMM_DYN);
    cudaFuncSetAttribute(mma_attn, cudaFuncAttributeMaxDynamicSharedMemorySize, ATT_SMEM);

    const int WSZ = DMODEL * DMODEL;  // 65536
    const float QSCL = 0.125f;        // 1/sqrt(64)

    // 1) conversions
    split_kernel<<<MX * DMODEL / 4 / 256, 256>>>(x, xhi, xlo, MX * DMODEL / 4);
    split_kernel<<<MY * DMODEL / 4 / 256, 256>>>(y, yhi, ylo, MY * DMODEL / 4);
    WSrc ws;
    ws.s[0] = Wqx; ws.s[1] = Wkx; ws.s[2] = Wvx;
    ws.s[3] = Wqy; ws.s[4] = Wky; ws.s[5] = Wvy;
    ws.s[6] = Wox; ws.s[7] = Woy; ws.s[8] = ffxW; ws.s[9] = ffyW;
    wsplit_kernel<<<dim3(WSZ / 4 / 256, 10), 256>>>(ws, whi, wlo);

    // 2) gates
    gate_kernel<<<MX / 8, 256>>>(x, gWx, gbx, out + OFF_GX, lgx, MX);
    gate_kernel<<<MY / 8, 256>>>(y, gWy, gby, out + OFF_GY, lgy, MY);

    // 3) QKV projections, emit bf16 splits (q pre-scaled)
    {
        GemmArgs a = {};
        a.Ahi = xhi; a.Alo = xlo;
        a.Whi[0] = whi + 0 * WSZ; a.Wlo[0] = wlo + 0 * WSZ;
        a.Chi[0] = qxhi; a.Clo[0] = qxlo; a.scl[0] = QSCL;
        a.Whi[1] = whi + 1 * WSZ; a.Wlo[1] = wlo + 1 * WSZ;
        a.Chi[1] = kxhi; a.Clo[1] = kxlo; a.scl[1] = 1.f;
        a.Whi[2] = whi + 2 * WSZ; a.Wlo[2] = wlo + 2 * WSZ;
        a.Chi[2] = vxhi; a.Clo[2] = vxlo; a.scl[2] = 1.f;
        mma_gemm<0, 1><<<dim3(2, MX / 128, 3), 256, SMEM_GEMM_DYN>>>(a);
    }
    {
        GemmArgs a = {};
        a.Ahi = yhi; a.Alo = ylo;
        a.Whi[0] = whi + 3 * WSZ; a.Wlo[0] = wlo + 3 * WSZ;
        a.Chi[0] = qyhi; a.Clo[0] = qylo; a.scl[0] = QSCL;
        a.Whi[1] = whi + 4 * WSZ; a.Wlo[1] = wlo + 4 * WSZ;
        a.Chi[1] = kyhi; a.Clo[1] = kylo; a.scl[1] = 1.f;
        a.Whi[2] = whi + 5 * WSZ; a.Wlo[2] = wlo + 5 * WSZ;
        a.Chi[2] = vyhi; a.Clo[2] = vylo; a.scl[2] = 1.f;
        mma_gemm<0, 1><<<dim3(2, MY / 128, 3), 256, SMEM_GEMM_DYN>>>(a);
    }

    // 4) attention (tensor cores)
    mma_attn<<<dim3(NX / 128, NHEAD, BATCH), 256, ATT_SMEM>>>(
        qxhi, qxlo, kyhi, kylo, vyhi, vylo, lgy, axhi, axlo, NX, NY);
    mma_attn<<<dim3(NY / 128, NHEAD, BATCH), 256, ATT_SMEM>>>(
        qyhi, qylo, kxhi, kxlo, vxhi, vxlo, lgx, ayhi, aylo, NY, NX);

    // 5) x branch
    {
        GemmArgs a = {};
        a.Ahi = axhi; a.Alo = axlo;
        a.Whi[0] = whi + 6 * WSZ; a.Wlo[0] = wlo + 6 * WSZ; a.C[0] = t1;
        mma_gemm<0, 0><<<dim3(2, MX / 128, 1), 256, SMEM_GEMM_DYN>>>(a);
    }
    add_ln_kernel<1><<<MX / 8, 256>>>(x, t1, lnxg, lnxb, x2a, x2ahi, x2alo, MX);
    {
        GemmArgs a = {};
        a.Ahi = x2ahi; a.Alo = x2alo;
        a.Whi[0] = whi + 8 * WSZ; a.Wlo[0] = wlo + 8 * WSZ; a.C[0] = t1; a.bias[0] = ffxb;
        mma_gemm<1, 0><<<dim3(2, MX / 128, 1), 256, SMEM_GEMM_DYN>>>(a);
    }
    add_ln_kernel<0><<<MX / 8, 256>>>(x2a, t1, lnxg, lnxb, out + OFF_X2, nullptr, nullptr, MX);

    // 6) y branch
    {
        GemmArgs a = {};
        a.Ahi = ayhi; a.Alo = aylo;
        a.Whi[0] = whi + 7 * WSZ; a.Wlo[0] = wlo + 7 * WSZ; a.C[0] = t1;
        mma_gemm<0, 0><<<dim3(2, MY / 128, 1), 256, SMEM_GEMM_DYN>>>(a);
    }
    add_ln_kernel<1><<<MY / 8, 256>>>(y, t1, lnyg, lnyb, y2a, y2ahi, y2alo, MY);
    {
        GemmArgs a = {};
        a.Ahi = y2ahi; a.Alo = y2alo;
        a.Whi[0] = whi + 9 * WSZ; a.Wlo[0] = wlo + 9 * WSZ; a.C[0] = t1; a.bias[0] = ffyb;
        mma_gemm<1, 0><<<dim3(2, MY / 128, 1), 256, SMEM_GEMM_DYN>>>(a);
    }
    add_ln_kernel<0><<<MY / 8, 256>>>(y2a, t1, lnyg, lnyb, out + OFF_Y2, nullptr, nullptr, MY);
}

// round 6
// speedup vs baseline: 2.8154x; 1.0250x over previous
#include <cuda_runtime.h>
#include <cuda_bf16.h>
#include <math.h>
#include <stdint.h>

// ---------------- problem constants ----------------
#define BATCH 16
#define NX 512
#define NY 1024
#define DMODEL 256
#define NHEAD 4
#define DK 64
#define MX (BATCH * NX)   // 8192
#define MY (BATCH * NY)   // 16384

#define OFF_X2 0
#define OFF_Y2 (MX * DMODEL)
#define OFF_GX (OFF_Y2 + MY * DMODEL)
#define OFF_GY (OFF_GX + MX)

// ---------------- scratch ----------------
__device__ float g_lgx[MX];
__device__ float g_lgy[MY];

__device__ __nv_bfloat16 g_xhi[MX * DMODEL];
__device__ __nv_bfloat16 g_xlo[MX * DMODEL];
__device__ __nv_bfloat16 g_yhi[MY * DMODEL];
__device__ __nv_bfloat16 g_ylo[MY * DMODEL];
__device__ __nv_bfloat16 g_qxhi[MX * DMODEL];
__device__ __nv_bfloat16 g_qxlo[MX * DMODEL];
__device__ __nv_bfloat16 g_kxhi[MX * DMODEL];
__device__ __nv_bfloat16 g_kxlo[MX * DMODEL];
__device__ __nv_bfloat16 g_vxhi[MX * DMODEL];
__device__ __nv_bfloat16 g_vxlo[MX * DMODEL];
__device__ __nv_bfloat16 g_qyhi[MY * DMODEL];
__device__ __nv_bfloat16 g_qylo[MY * DMODEL];
__device__ __nv_bfloat16 g_kyhi[MY * DMODEL];
__device__ __nv_bfloat16 g_kylo[MY * DMODEL];
__device__ __nv_bfloat16 g_vyhi[MY * DMODEL];
__device__ __nv_bfloat16 g_vylo[MY * DMODEL];
__device__ __nv_bfloat16 g_axhi[MX * DMODEL];
__device__ __nv_bfloat16 g_axlo[MX * DMODEL];
__device__ __nv_bfloat16 g_ayhi[MY * DMODEL];
__device__ __nv_bfloat16 g_aylo[MY * DMODEL];
__device__ __nv_bfloat16 g_x2ahi[MX * DMODEL];
__device__ __nv_bfloat16 g_x2alo[MX * DMODEL];
__device__ __nv_bfloat16 g_y2ahi[MY * DMODEL];
__device__ __nv_bfloat16 g_y2alo[MY * DMODEL];
__device__ __nv_bfloat16 g_whi[10 * DMODEL * DMODEL];
__device__ __nv_bfloat16 g_wlo[10 * DMODEL * DMODEL];

// ---------------- helpers ----------------
__device__ __forceinline__ uint32_t smem_u32(const void* p) {
    uint32_t a;
    asm("{ .reg .u64 t; cvta.to.shared.u64 t, %1; cvt.u32.u64 %0, t; }"
        : "=r"(a) : "l"(p));
    return a;
}

#define SMEM_SWIZZLE_128B(off) ((off) ^ (((off) >> 3) & 0x70))

__device__ __forceinline__ void ldsm_x4(uint32_t* r, uint32_t addr) {
    asm volatile("ldmatrix.sync.aligned.m8n8.x4.shared.b16 {%0,%1,%2,%3}, [%4];"
                 : "=r"(r[0]), "=r"(r[1]), "=r"(r[2]), "=r"(r[3]) : "r"(addr));
}

__device__ __forceinline__ void ldsm_x4_t(uint32_t* r, uint32_t addr) {
    asm volatile("ldmatrix.sync.aligned.m8n8.x4.trans.shared.b16 {%0,%1,%2,%3}, [%4];"
                 : "=r"(r[0]), "=r"(r[1]), "=r"(r[2]), "=r"(r[3]) : "r"(addr));
}

__device__ __forceinline__ void mma16816(float* d, const uint32_t* a, const uint32_t* b) {
    asm volatile(
        "mma.sync.aligned.m16n8k16.row.col.f32.bf16.bf16.f32 "
        "{%0,%1,%2,%3}, {%4,%5,%6,%7}, {%8,%9}, {%0,%1,%2,%3};"
        : "+f"(d[0]), "+f"(d[1]), "+f"(d[2]), "+f"(d[3])
        : "r"(a[0]), "r"(a[1]), "r"(a[2]), "r"(a[3]), "r"(b[0]), "r"(b[1]));
}

__device__ __forceinline__ void cpa16(uint32_t dst, const void* src) {
    asm volatile("cp.async.cg.shared.global [%0], [%1], 16;" :: "r"(dst), "l"(src));
}
#define CP_COMMIT() asm volatile("cp.async.commit_group;" ::: "memory")
#define CP_WAIT0()  asm volatile("cp.async.wait_group 0;" ::: "memory")
#define CP_WAIT1()  asm volatile("cp.async.wait_group 1;" ::: "memory")

__device__ __forceinline__ void split2(float v, __nv_bfloat16& hi, __nv_bfloat16& lo) {
    hi = __float2bfloat16(v);
    lo = __float2bfloat16(v - __bfloat162float(hi));
}

__device__ __forceinline__ uint32_t pack_split(float a, float b, uint32_t& lo) {
    __nv_bfloat16 ha = __float2bfloat16(a), hb = __float2bfloat16(b);
    __nv_bfloat16 la = __float2bfloat16(a - __bfloat162float(ha));
    __nv_bfloat16 lb = __float2bfloat16(b - __bfloat162float(hb));
    __nv_bfloat162 H(ha, hb), L(la, lb);
    lo = *(uint32_t*)&L;
    return *(uint32_t*)&H;
}

__device__ __forceinline__ float softplusf(float x) {
    return (x > 20.f) ? x : log1pf(expf(x));
}

// ---------------- fused split + evidential gate ----------------
// One warp per token: emits bf16 hi/lo split of the row AND the NIG gate.
__global__ __launch_bounds__(256) void split_gate_kernel(
    const float* __restrict__ src, __nv_bfloat16* __restrict__ hi,
    __nv_bfloat16* __restrict__ lo,
    const float* __restrict__ gW, const float* __restrict__ gb,
    float* __restrict__ g_out, float* __restrict__ lg_out, int ntok)
{
    const int wid = threadIdx.x >> 5;
    const int lane = threadIdx.x & 31;
    const int token = blockIdx.x * 8 + wid;
    if (token >= ntok) return;

    const float4* row = (const float4*)(src + (size_t)token * DMODEL);
    float4 v0 = row[lane];
    float4 v1 = row[lane + 32];

    uint32_t l0, l1, l2, l3;
    uint32_t h0 = pack_split(v0.x, v0.y, l0);
    uint32_t h1 = pack_split(v0.z, v0.w, l1);
    uint32_t h2 = pack_split(v1.x, v1.y, l2);
    uint32_t h3 = pack_split(v1.z, v1.w, l3);
    uint32_t* hp = (uint32_t*)(hi + (size_t)token * DMODEL);
    uint32_t* lp = (uint32_t*)(lo + (size_t)token * DMODEL);
    hp[2 * lane]      = h0; hp[2 * lane + 1]      = h1;
    hp[64 + 2 * lane] = h2; hp[64 + 2 * lane + 1] = h3;
    lp[2 * lane]      = l0; lp[2 * lane + 1]      = l1;
    lp[64 + 2 * lane] = l2; lp[64 + 2 * lane + 1] = l3;

    float p[4];
    #pragma unroll
    for (int j = 0; j < 4; j++) {
        float4 w0 = ((const float4*)gW)[j * 64 + lane];
        float4 w1 = ((const float4*)gW)[j * 64 + 32 + lane];
        p[j] = v0.x * w0.x + v0.y * w0.y + v0.z * w0.z + v0.w * w0.w
             + v1.x * w1.x + v1.y * w1.y + v1.z * w1.z + v1.w * w1.w;
    }
    #pragma unroll
    for (int o = 16; o > 0; o >>= 1) {
        p[0] += __shfl_xor_sync(0xffffffffu, p[0], o);
        p[1] += __shfl_xor_sync(0xffffffffu, p[1], o);
        p[2] += __shfl_xor_sync(0xffffffffu, p[2], o);
        p[3] += __shfl_xor_sync(0xffffffffu, p[3], o);
    }
    if (lane == 0) {
        float mu    = p[0] + gb[0];
        float v     = softplusf(p[1] + gb[1]) + 1e-6f;
        float alpha = softplusf(p[2] + gb[2]) + 1.0f + 1e-6f;
        float beta  = softplusf(p[3] + gb[3]) + 1e-6f;
        float var_ep = beta / (v * (alpha - 1.0f));
        float g = (1.0f / (1.0f + expf(-mu))) * expf(-2.0f * var_ep);
        g = fmaxf(g, 1e-6f);
        g_out[token]  = g;
        lg_out[token] = logf(g);
    }
}

// ---------------- weight split ----------------
struct WSrc { const float* s[10]; };

__global__ __launch_bounds__(256) void wsplit_kernel(
    WSrc ws, __nv_bfloat16* __restrict__ hi, __nv_bfloat16* __restrict__ lo)
{
    int m = blockIdx.y;
    int i = blockIdx.x * 256 + threadIdx.x;
    float4 v = ((const float4*)ws.s[m])[i];
    uint32_t l0, l1;
    uint32_t h0 = pack_split(v.x, v.y, l0);
    uint32_t h1 = pack_split(v.z, v.w, l1);
    size_t base = (size_t)m * DMODEL * DMODEL / 2 + 2 * i;
    ((uint32_t*)hi)[base]     = h0;
    ((uint32_t*)hi)[base + 1] = h1;
    ((uint32_t*)lo)[base]     = l0;
    ((uint32_t*)lo)[base + 1] = l1;
}

// ---------------- QKV HMMA GEMM (cp.async double-buffered, emits splits) ----------------
#define TILE_B 16384
#define STAGE_B (4 * TILE_B)           // 64KB
#define SMEM_GEMM_DYN (2 * STAGE_B)    // 128KB

struct GemmArgs {
    const __nv_bfloat16* Ahi;
    const __nv_bfloat16* Alo;
    const __nv_bfloat16* Whi[3];
    const __nv_bfloat16* Wlo[3];
    __nv_bfloat16* Chi[3];
    __nv_bfloat16* Clo[3];
    float scl[3];
};

__device__ __forceinline__ void gemm_load_stage(
    uint32_t sb, int stage,
    const __nv_bfloat16* Ahi, const __nv_bfloat16* Alo,
    const __nv_bfloat16* Whi, const __nv_bfloat16* Wlo,
    int bm, int bn, int k0, int tid)
{
    const __nv_bfloat16* srcs[4] = {Ahi, Alo, Whi, Wlo};
    const int rb[4] = {bm, bm, bn, bn};
    const uint32_t base = sb + stage * STAGE_B;
    #pragma unroll
    for (int i = 0; i < 16; i++) {
        int idx = tid + i * 256;
        int arr = idx >> 10;
        int rem = idx & 1023;
        int r = rem >> 3, f = rem & 7;
        uint32_t dst = base + arr * TILE_B + SMEM_SWIZZLE_128B((uint32_t)(r * 128 + f * 16));
        cpa16(dst, srcs[arr] + (size_t)(rb[arr] + r) * DMODEL + k0 + f * 8);
    }
}

__global__ __launch_bounds__(256) void mma_gemm(GemmArgs args)
{
    extern __shared__ char smem[];
    const uint32_t sb = smem_u32(smem);

    const int tid = threadIdx.x;
    const int wid = tid >> 5;
    const int lane = tid & 31;
    const int z = blockIdx.z;
    const int bm = blockIdx.y * 128;
    const int bn = blockIdx.x * 128;
    const int wm = (wid & 1) * 64;
    const int wn = (wid >> 1) * 32;

    const __nv_bfloat16* __restrict__ Ahi = args.Ahi;
    const __nv_bfloat16* __restrict__ Alo = args.Alo;
    const __nv_bfloat16* __restrict__ Whi = args.Whi[z];
    const __nv_bfloat16* __restrict__ Wlo = args.Wlo[z];

    float acc[4][4][4];
    #pragma unroll
    for (int i = 0; i < 4; i++)
        #pragma unroll
        for (int j = 0; j < 4; j++)
            #pragma unroll
            for (int c = 0; c < 4; c++) acc[i][j][c] = 0.f;

    const int rofs = ((lane >> 3) & 1) * 8 + (lane & 7);
    const int kofs = ((lane >> 4) & 1) * 16;

    gemm_load_stage(sb, 0, Ahi, Alo, Whi, Wlo, bm, bn, 0, tid);
    CP_COMMIT();

    for (int kc = 0; kc < 4; kc++) {
        const int s = kc & 1;
        if (kc + 1 < 4) {
            gemm_load_stage(sb, s ^ 1, Ahi, Alo, Whi, Wlo, bm, bn, (kc + 1) * 64, tid);
            CP_COMMIT();
            CP_WAIT1();
        } else {
            CP_WAIT0();
        }
        __syncthreads();

        const uint32_t sAhi = sb + s * STAGE_B;
        const uint32_t sAlo = sAhi + TILE_B;
        const uint32_t sBhi = sAhi + 2 * TILE_B;
        const uint32_t sBlo = sAhi + 3 * TILE_B;

        #pragma unroll
        for (int ks = 0; ks < 4; ks++) {
            const int kb = ks * 32 + kofs;
            uint32_t ah[4][4], al[4][4], bh[4][2], bl[4][2];
            #pragma unroll
            for (int mt = 0; mt < 4; mt++) {
                int row = wm + mt * 16 + rofs;
                uint32_t so = SMEM_SWIZZLE_128B((uint32_t)(row * 128 + kb));
                ldsm_x4(ah[mt], sAhi + so);
                ldsm_x4(al[mt], sAlo + so);
            }
            #pragma unroll
            for (int p = 0; p < 2; p++) {
                int row = wn + p * 16 + rofs;
                uint32_t so = SMEM_SWIZZLE_128B((uint32_t)(row * 128 + kb));
                uint32_t t[4];
                ldsm_x4(t, sBhi + so);
                bh[2 * p][0] = t[0]; bh[2 * p][1] = t[2];
                bh[2 * p + 1][0] = t[1]; bh[2 * p + 1][1] = t[3];
                ldsm_x4(t, sBlo + so);
                bl[2 * p][0] = t[0]; bl[2 * p][1] = t[2];
                bl[2 * p + 1][0] = t[1]; bl[2 * p + 1][1] = t[3];
            }
            #pragma unroll
            for (int mt = 0; mt < 4; mt++)
                #pragma unroll
                for (int nt = 0; nt < 4; nt++)
                    mma16816(acc[mt][nt], ah[mt], bh[nt]);
            #pragma unroll
            for (int mt = 0; mt < 4; mt++)
                #pragma unroll
                for (int nt = 0; nt < 4; nt++)
                    mma16816(acc[mt][nt], ah[mt], bl[nt]);
            #pragma unroll
            for (int mt = 0; mt < 4; mt++)
                #pragma unroll
                for (int nt = 0; nt < 4; nt++)
                    mma16816(acc[mt][nt], al[mt], bh[nt]);
        }
        __syncthreads();
    }

    const int rbase = bm + wm + (lane >> 2);
    const int cbase = bn + wn + (lane & 3) * 2;
    const float s = args.scl[z];
    __nv_bfloat16* __restrict__ Chi = args.Chi[z];
    __nv_bfloat16* __restrict__ Clo = args.Clo[z];
    #pragma unroll
    for (int mt = 0; mt < 4; mt++) {
        #pragma unroll
        for (int nt = 0; nt < 4; nt++) {
            int col = cbase + nt * 8;
            int r0 = rbase + mt * 16;
            uint32_t l0, l1;
            uint32_t h0 = pack_split(acc[mt][nt][0] * s, acc[mt][nt][1] * s, l0);
            uint32_t h1 = pack_split(acc[mt][nt][2] * s, acc[mt][nt][3] * s, l1);
            *(uint32_t*)&Chi[(size_t)r0 * DMODEL + col]       = h0;
            *(uint32_t*)&Clo[(size_t)r0 * DMODEL + col]       = l0;
            *(uint32_t*)&Chi[(size_t)(r0 + 8) * DMODEL + col] = h1;
            *(uint32_t*)&Clo[(size_t)(r0 + 8) * DMODEL + col] = l1;
        }
    }
}

// ---------------- fused GEMM + residual + LayerNorm ----------------
// Tile: 64 rows x 256 cols (full rows), 8 warps (2 m-warps x 4 n-warps),
// warp tile 32x64. K-chunks of 64, cp.async double-buffered.
// PATH 0: C = A @ W^T; val = resid_f32 + C; LN -> emit bf16 hi/lo splits.
// PATH 1: C = silu(A @ W^T + bias); val = (resid_hi+resid_lo) + C; LN -> fp32 out.
#define GLN_A_B 8192                    // 64 rows * 128B
#define GLN_STAGE (2 * GLN_A_B + 2 * 32768)   // Ahi,Alo + Bhi,Blo = 81920
#define GLN_STATS (2 * GLN_STAGE)             // 163840
#define SMEM_GLN (GLN_STATS + 2048)           // + sums/sqs

template <int PATH>
__global__ __launch_bounds__(256) void gemm_ln(
    const __nv_bfloat16* __restrict__ Ahi, const __nv_bfloat16* __restrict__ Alo,
    const __nv_bfloat16* __restrict__ Whi, const __nv_bfloat16* __restrict__ Wlo,
    const float* __restrict__ bias,
    const float* __restrict__ resid_f32,
    const __nv_bfloat16* __restrict__ rhi, const __nv_bfloat16* __restrict__ rlo,
    const float* __restrict__ gamma, const float* __restrict__ beta,
    float* __restrict__ out_f32,
    __nv_bfloat16* __restrict__ ohi, __nv_bfloat16* __restrict__ olo)
{
    extern __shared__ char smem[];
    const uint32_t sb = smem_u32(smem);
    float* stat_sum = (float*)(smem + GLN_STATS);        // [64][4]
    float* stat_sq  = (float*)(smem + GLN_STATS + 1024); // [64][4]

    const int tid = threadIdx.x;
    const int wid = tid >> 5;
    const int lane = tid & 31;
    const int bm = blockIdx.x * 64;
    const int wm = (wid >> 2) * 32;      // m-warp offset (0 or 32)
    const int wn = (wid & 3) * 64;       // n-warp offset (0..192)
    const int nw = wid & 3;

    const int rofs = ((lane >> 3) & 1) * 8 + (lane & 7);
    const int kofs = ((lane >> 4) & 1) * 16;

    float acc[2][8][4];
    #pragma unroll
    for (int i = 0; i < 2; i++)
        #pragma unroll
        for (int j = 0; j < 8; j++)
            #pragma unroll
            for (int c = 0; c < 4; c++) acc[i][j][c] = 0.f;

    // stage loader: 20 cp.async per thread
    auto load_stage = [&](int stage, int k0) {
        const uint32_t base = sb + stage * GLN_STAGE;
        #pragma unroll
        for (int i = 0; i < 20; i++) {
            int idx = tid + i * 256;      // 0..5119
            uint32_t dst;
            const __nv_bfloat16* src;
            if (idx < 512) {              // Ahi: 64 rows
                int r = idx >> 3, f = idx & 7;
                dst = base + SMEM_SWIZZLE_128B((uint32_t)(r * 128 + f * 16));
                src = Ahi + (size_t)(bm + r) * DMODEL + k0 + f * 8;
            } else if (idx < 1024) {      // Alo
                int j = idx - 512;
                int r = j >> 3, f = j & 7;
                dst = base + GLN_A_B + SMEM_SWIZZLE_128B((uint32_t)(r * 128 + f * 16));
                src = Alo + (size_t)(bm + r) * DMODEL + k0 + f * 8;
            } else if (idx < 3072) {      // Bhi: 256 rows
                int j = idx - 1024;
                int r = j >> 3, f = j & 7;
                dst = base + 2 * GLN_A_B + SMEM_SWIZZLE_128B((uint32_t)(r * 128 + f * 16));
                src = Whi + (size_t)r * DMODEL + k0 + f * 8;
            } else {                      // Blo
                int j = idx - 3072;
                int r = j >> 3, f = j & 7;
                dst = base + 2 * GLN_A_B + 32768 + SMEM_SWIZZLE_128B((uint32_t)(r * 128 + f * 16));
                src = Wlo + (size_t)r * DMODEL + k0 + f * 8;
            }
            cpa16(dst, src);
        }
    };

    load_stage(0, 0);
    CP_COMMIT();

    for (int kc = 0; kc < 4; kc++) {
        const int s = kc & 1;
        if (kc + 1 < 4) {
            load_stage(s ^ 1, (kc + 1) * 64);
            CP_COMMIT();
            CP_WAIT1();
        } else {
            CP_WAIT0();
        }
        __syncthreads();

        const uint32_t sAhi = sb + s * GLN_STAGE;
        const uint32_t sAlo = sAhi + GLN_A_B;
        const uint32_t sBhi = sAhi + 2 * GLN_A_B;
        const uint32_t sBlo = sBhi + 32768;

        #pragma unroll
        for (int ks = 0; ks < 4; ks++) {
            const int kb = ks * 32 + kofs;
            uint32_t ah[2][4], al[2][4], bh[8][2], bl[8][2];
            #pragma unroll
            for (int mt = 0; mt < 2; mt++) {
                int row = wm + mt * 16 + rofs;
                uint32_t so = SMEM_SWIZZLE_128B((uint32_t)(row * 128 + kb));
                ldsm_x4(ah[mt], sAhi + so);
                ldsm_x4(al[mt], sAlo + so);
            }
            #pragma unroll
            for (int p = 0; p < 4; p++) {
                int row = wn + p * 16 + rofs;
                uint32_t so = SMEM_SWIZZLE_128B((uint32_t)(row * 128 + kb));
                uint32_t t[4];
                ldsm_x4(t, sBhi + so);
                bh[2 * p][0] = t[0]; bh[2 * p][1] = t[2];
                bh[2 * p + 1][0] = t[1]; bh[2 * p + 1][1] = t[3];
                ldsm_x4(t, sBlo + so);
                bl[2 * p][0] = t[0]; bl[2 * p][1] = t[2];
                bl[2 * p + 1][0] = t[1]; bl[2 * p + 1][1] = t[3];
            }
            #pragma unroll
            for (int mt = 0; mt < 2; mt++)
                #pragma unroll
                for (int nt = 0; nt < 8; nt++)
                    mma16816(acc[mt][nt], ah[mt], bh[nt]);
            #pragma unroll
            for (int mt = 0; mt < 2; mt++)
                #pragma unroll
                for (int nt = 0; nt < 8; nt++)
                    mma16816(acc[mt][nt], ah[mt], bl[nt]);
            #pragma unroll
            for (int mt = 0; mt < 2; mt++)
                #pragma unroll
                for (int nt = 0; nt < 8; nt++)
                    mma16816(acc[mt][nt], al[mt], bh[nt]);
        }
        __syncthreads();
    }

    // ---- epilogue: residual add (+bias/silu), LN stats, normalize, write ----
    const int lr = lane >> 2;          // 0..7
    const int lc = (lane & 3) * 2;
    float rsum[2][2] = {}, rsq[2][2] = {};   // [mt][half]

    #pragma unroll
    for (int mt = 0; mt < 2; mt++) {
        #pragma unroll
        for (int nt = 0; nt < 8; nt++) {
            int c = wn + nt * 8 + lc;
            int gr0 = bm + wm + mt * 16 + lr;
            float v0 = acc[mt][nt][0], v1 = acc[mt][nt][1];
            float v2 = acc[mt][nt][2], v3 = acc[mt][nt][3];
            if (PATH == 1) {
                float b0 = bias[c], b1 = bias[c + 1];
                v0 += b0; v1 += b1; v2 += b0; v3 += b1;
                v0 = v0 / (1.0f + __expf(-v0));
                v1 = v1 / (1.0f + __expf(-v1));
                v2 = v2 / (1.0f + __expf(-v2));
                v3 = v3 / (1.0f + __expf(-v3));
                uint32_t rh0 = *(const uint32_t*)&rhi[(size_t)gr0 * DMODEL + c];
                uint32_t rl0 = *(const uint32_t*)&rlo[(size_t)gr0 * DMODEL + c];
                uint32_t rh1 = *(const uint32_t*)&rhi[(size_t)(gr0 + 8) * DMODEL + c];
                uint32_t rl1 = *(const uint32_t*)&rlo[(size_t)(gr0 + 8) * DMODEL + c];
                __nv_bfloat162 H0 = *(__nv_bfloat162*)&rh0, L0 = *(__nv_bfloat162*)&rl0;
                __nv_bfloat162 H1 = *(__nv_bfloat162*)&rh1, L1 = *(__nv_bfloat162*)&rl1;
                v0 += __bfloat162float(H0.x) + __bfloat162float(L0.x);
                v1 += __bfloat162float(H0.y) + __bfloat162float(L0.y);
                v2 += __bfloat162float(H1.x) + __bfloat162float(L1.x);
                v3 += __bfloat162float(H1.y) + __bfloat162float(L1.y);
            } else {
                float2 rA = *(const float2*)&resid_f32[(size_t)gr0 * DMODEL + c];
                float2 rB = *(const float2*)&resid_f32[(size_t)(gr0 + 8) * DMODEL + c];
                v0 += rA.x; v1 += rA.y; v2 += rB.x; v3 += rB.y;
            }
            acc[mt][nt][0] = v0; acc[mt][nt][1] = v1;
            acc[mt][nt][2] = v2; acc[mt][nt][3] = v3;
            rsum[mt][0] += v0 + v1; rsq[mt][0] += v0 * v0 + v1 * v1;
            rsum[mt][1] += v2 + v3; rsq[mt][1] += v2 * v2 + v3 * v3;
        }
    }

    // quad reduce (lanes differing in bits 0,1 share the row)
    #pragma unroll
    for (int mt = 0; mt < 2; mt++)
        #pragma unroll
        for (int hf = 0; hf < 2; hf++) {
            rsum[mt][hf] += __shfl_xor_sync(0xffffffffu, rsum[mt][hf], 1);
            rsum[mt][hf] += __shfl_xor_sync(0xffffffffu, rsum[mt][hf], 2);
            rsq[mt][hf]  += __shfl_xor_sync(0xffffffffu, rsq[mt][hf], 1);
            rsq[mt][hf]  += __shfl_xor_sync(0xffffffffu, rsq[mt][hf], 2);
        }
    if ((lane & 3) == 0) {
        #pragma unroll
        for (int mt = 0; mt < 2; mt++)
            #pragma unroll
            for (int hf = 0; hf < 2; hf++) {
                int row = wm + mt * 16 + lr + hf * 8;
                stat_sum[row * 4 + nw] = rsum[mt][hf];
                stat_sq[row * 4 + nw]  = rsq[mt][hf];
            }
    }
    __syncthreads();

    float mean[2][2], rstd[2][2];
    #pragma unroll
    for (int mt = 0; mt < 2; mt++)
        #pragma unroll
        for (int hf = 0; hf < 2; hf++) {
            int row = wm + mt * 16 + lr + hf * 8;
            float ts = stat_sum[row * 4 + 0] + stat_sum[row * 4 + 1]
                     + stat_sum[row * 4 + 2] + stat_sum[row * 4 + 3];
            float tq = stat_sq[row * 4 + 0] + stat_sq[row * 4 + 1]
                     + stat_sq[row * 4 + 2] + stat_sq[row * 4 + 3];
            float mu = ts * (1.0f / DMODEL);
            float var = tq * (1.0f / DMODEL) - mu * mu;
            mean[mt][hf] = mu;
            rstd[mt][hf] = rsqrtf(var + 1e-5f);
        }

    #pragma unroll
    for (int mt = 0; mt < 2; mt++) {
        #pragma unroll
        for (int nt = 0; nt < 8; nt++) {
            int c = wn + nt * 8 + lc;
            int gr0 = bm + wm + mt * 16 + lr;
            float g0 = gamma[c], g1 = gamma[c + 1];
            float b0 = beta[c],  b1 = beta[c + 1];
            float o0 = (acc[mt][nt][0] - mean[mt][0]) * rstd[mt][0] * g0 + b0;
            float o1 = (acc[mt][nt][1] - mean[mt][0]) * rstd[mt][0] * g1 + b1;
            float o2 = (acc[mt][nt][2] - mean[mt][1]) * rstd[mt][1] * g0 + b0;
            float o3 = (acc[mt][nt][3] - mean[mt][1]) * rstd[mt][1] * g1 + b1;
            if (PATH == 0) {
                uint32_t l0, l1;
                uint32_t h0 = pack_split(o0, o1, l0);
                uint32_t h1 = pack_split(o2, o3, l1);
                *(uint32_t*)&ohi[(size_t)gr0 * DMODEL + c]       = h0;
                *(uint32_t*)&olo[(size_t)gr0 * DMODEL + c]       = l0;
                *(uint32_t*)&ohi[(size_t)(gr0 + 8) * DMODEL + c] = h1;
                *(uint32_t*)&olo[(size_t)(gr0 + 8) * DMODEL + c] = l1;
            } else {
                *(float2*)&out_f32[(size_t)gr0 * DMODEL + c]       = make_float2(o0, o1);
                *(float2*)&out_f32[(size_t)(gr0 + 8) * DMODEL + c] = make_float2(o2, o3);
            }
        }
    }
}

// ---------------- HMMA flash attention ----------------
#define ATT_SMEM (98304 + 512)

__device__ __forceinline__ void att_load_kv(
    char* smem, uint32_t sb, int stage, int kt, int b, int h, int Tk,
    const __nv_bfloat16* kh, const __nv_bfloat16* kl,
    const __nv_bfloat16* vh, const __nv_bfloat16* vl,
    const float* lg, int tid)
{
    const __nv_bfloat16* srcs[4] = {kh, kl, vh, vl};
    uint32_t base = sb + 32768 + stage * 32768;
    #pragma unroll
    for (int i = 0; i < 8; i++) {
        int idx = tid + i * 256;
        int arr = idx >> 9;
        int rem = idx & 511;
        int r = rem >> 3, f = rem & 7;
        uint32_t dst = base + arr * 8192 + SMEM_SWIZZLE_128B((uint32_t)(r * 128 + f * 16));
        const __nv_bfloat16* src = srcs[arr] +
            ((size_t)(b * Tk + kt * 64 + r) * DMODEL + h * DK) + f * 8;
        cpa16(dst, src);
    }
    if (tid < 16)
        cpa16(sb + 98304 + stage * 256 + tid * 16, lg + b * Tk + kt * 64 + tid * 4);
}

__global__ __launch_bounds__(256) void mma_attn(
    const __nv_bfloat16* __restrict__ qhi, const __nv_bfloat16* __restrict__ qlo,
    const __nv_bfloat16* __restrict__ khi, const __nv_bfloat16* __restrict__ klo,
    const __nv_bfloat16* __restrict__ vhi, const __nv_bfloat16* __restrict__ vlo,
    const float* __restrict__ lgk,
    __nv_bfloat16* __restrict__ ohi, __nv_bfloat16* __restrict__ olo,
    int Tq, int Tk)
{
    extern __shared__ char smem[];
    const uint32_t sb = smem_u32(smem);
    const int tid = threadIdx.x;
    const int wid = tid >> 5;
    const int lane = tid & 31;
    const int b = blockIdx.z;
    const int h = blockIdx.y;
    const int bq = blockIdx.x * 128;
    const int wm = wid * 16;
    const int rofs = ((lane >> 3) & 1) * 8 + (lane & 7);
    const int kofs = ((lane >> 4) & 1) * 16;

    #pragma unroll
    for (int i = 0; i < 4; i++) {
        int idx = tid + i * 256;
        int r = idx >> 3, f = idx & 7;
        uint32_t so = SMEM_SWIZZLE_128B((uint32_t)(r * 128 + f * 16));
        size_t g = (size_t)(b * Tq + bq + r) * DMODEL + h * DK;
        *(uint4*)(smem + so)         = ((const uint4*)(qhi + g))[f];
        *(uint4*)(smem + 16384 + so) = ((const uint4*)(qlo + g))[f];
    }
    att_load_kv(smem, sb, 0, 0, b, h, Tk, khi, klo, vhi, vlo, lgk, tid);
    CP_COMMIT();
    __syncthreads();

    uint32_t qfh[4][4], qfl[4][4];
    #pragma unroll
    for (int ks = 0; ks < 4; ks++) {
        uint32_t so = SMEM_SWIZZLE_128B((uint32_t)((wm + rofs) * 128 + ks * 32 + kofs));
        ldsm_x4(qfh[ks], sb + so);
        ldsm_x4(qfl[ks], sb + 16384 + so);
    }

    float o[8][4];
    #pragma unroll
    for (int t = 0; t < 8; t++)
        #pragma unroll
        for (int c = 0; c < 4; c++) o[t][c] = 0.f;
    float m0 = -INFINITY, m1 = -INFINITY, l0 = 0.f, l1 = 0.f;

    const int ntile = Tk / 64;
    for (int kt = 0; kt < ntile; kt++) {
        const int s = kt & 1;
        CP_WAIT0();
        __syncthreads();
        if (kt + 1 < ntile) {
            att_load_kv(smem, sb, s ^ 1, kt + 1, b, h, Tk, khi, klo, vhi, vlo, lgk, tid);
            CP_COMMIT();
        }
        const uint32_t sKh = sb + 32768 + s * 32768;
        const uint32_t sKl = sKh + 8192;
        const uint32_t sVh = sKh + 16384;
        const uint32_t sVl = sKh + 24576;
        const float* lgs = (const float*)(smem + 98304 + s * 256);

        float sd[8][4];
        #pragma unroll
        for (int nt = 0; nt < 8; nt++)
            #pragma unroll
            for (int c = 0; c < 4; c++) sd[nt][c] = 0.f;

        #pragma unroll
        for (int ks = 0; ks < 4; ks++) {
            uint32_t bh[8][2], bl[8][2];
            #pragma unroll
            for (int p = 0; p < 4; p++) {
                uint32_t so = SMEM_SWIZZLE_128B((uint32_t)((p * 16 + rofs) * 128 + ks * 32 + kofs));
                uint32_t t[4];
                ldsm_x4(t, sKh + so);
                bh[2 * p][0] = t[0]; bh[2 * p][1] = t[2];
                bh[2 * p + 1][0] = t[1]; bh[2 * p + 1][1] = t[3];
                ldsm_x4(t, sKl + so);
                bl[2 * p][0] = t[0]; bl[2 * p][1] = t[2];
                bl[2 * p + 1][0] = t[1]; bl[2 * p + 1][1] = t[3];
            }
            #pragma unroll
            for (int nt = 0; nt < 8; nt++) {
                mma16816(sd[nt], qfh[ks], bh[nt]);
                mma16816(sd[nt], qfh[ks], bl[nt]);
                mma16816(sd[nt], qfl[ks], bh[nt]);
            }
        }

        float mt0 = m0, mt1 = m1;
        #pragma unroll
        for (int nt = 0; nt < 8; nt++) {
            int col = nt * 8 + (lane & 3) * 2;
            float lg0 = lgs[col], lg1 = lgs[col + 1];
            sd[nt][0] += lg0; sd[nt][1] += lg1;
            sd[nt][2] += lg0; sd[nt][3] += lg1;
            mt0 = fmaxf(mt0, fmaxf(sd[nt][0], sd[nt][1]));
            mt1 = fmaxf(mt1, fmaxf(sd[nt][2], sd[nt][3]));
        }
        mt0 = fmaxf(mt0, __shfl_xor_sync(0xffffffffu, mt0, 1));
        mt0 = fmaxf(mt0, __shfl_xor_sync(0xffffffffu, mt0, 2));
        mt1 = fmaxf(mt1, __shfl_xor_sync(0xffffffffu, mt1, 1));
        mt1 = fmaxf(mt1, __shfl_xor_sync(0xffffffffu, mt1, 2));
        float c0 = __expf(m0 - mt0);
        float c1 = __expf(m1 - mt1);
        m0 = mt0; m1 = mt1;
        l0 *= c0; l1 *= c1;
        #pragma unroll
        for (int t = 0; t < 8; t++) {
            o[t][0] *= c0; o[t][1] *= c0; o[t][2] *= c1; o[t][3] *= c1;
        }
        #pragma unroll
        for (int nt = 0; nt < 8; nt++) {
            sd[nt][0] = __expf(sd[nt][0] - m0);
            sd[nt][1] = __expf(sd[nt][1] - m0);
            sd[nt][2] = __expf(sd[nt][2] - m1);
            sd[nt][3] = __expf(sd[nt][3] - m1);
            l0 += sd[nt][0] + sd[nt][1];
            l1 += sd[nt][2] + sd[nt][3];
        }

        #pragma unroll
        for (int kb = 0; kb < 4; kb++) {
            uint32_t pah[4], pal[4];
            pah[0] = pack_split(sd[2 * kb][0],     sd[2 * kb][1],     pal[0]);
            pah[1] = pack_split(sd[2 * kb][2],     sd[2 * kb][3],     pal[1]);
            pah[2] = pack_split(sd[2 * kb + 1][0], sd[2 * kb + 1][1], pal[2]);
            pah[3] = pack_split(sd[2 * kb + 1][2], sd[2 * kb + 1][3], pal[3]);
            const int t4 = lane >> 3;
            #pragma unroll
            for (int dp = 0; dp < 4; dp++) {
                uint32_t so = SMEM_SWIZZLE_128B((uint32_t)(
                    (kb * 16 + (t4 & 1) * 8 + (lane & 7)) * 128 +
                    (dp * 16 + (t4 >> 1) * 8) * 2));
                uint32_t vh4[4], vl4[4];
                ldsm_x4_t(vh4, sVh + so);
                ldsm_x4_t(vl4, sVl + so);
                uint32_t b0h[2] = {vh4[0], vh4[1]}, b1h[2] = {vh4[2], vh4[3]};
                uint32_t b0l[2] = {vl4[0], vl4[1]}, b1l[2] = {vl4[2], vl4[3]};
                mma16816(o[2 * dp],     pah, b0h);
                mma16816(o[2 * dp],     pah, b0l);
                mma16816(o[2 * dp],     pal, b0h);
                mma16816(o[2 * dp + 1], pah, b1h);
                mma16816(o[2 * dp + 1], pah, b1l);
                mma16816(o[2 * dp + 1], pal, b1h);
            }
        }
    }

    float fl0 = l0 + __shfl_xor_sync(0xffffffffu, l0, 1);
    fl0 += __shfl_xor_sync(0xffffffffu, fl0, 2);
    float fl1 = l1 + __shfl_xor_sync(0xffffffffu, l1, 1);
    fl1 += __shfl_xor_sync(0xffffffffu, fl1, 2);
    float inv0 = 1.0f / fl0, inv1 = 1.0f / fl1;

    const int r0 = bq + wm + (lane >> 2);
    size_t base0 = (size_t)(b * Tq + r0) * DMODEL + h * DK;
    size_t base1 = base0 + (size_t)8 * DMODEL;
    #pragma unroll
    for (int t = 0; t < 8; t++) {
        int col = t * 8 + (lane & 3) * 2;
        uint32_t lo0, lo1;
        uint32_t h0 = pack_split(o[t][0] * inv0, o[t][1] * inv0, lo0);
        uint32_t h1 = pack_split(o[t][2] * inv1, o[t][3] * inv1, lo1);
        *(uint32_t*)&ohi[base0 + col] = h0;
        *(uint32_t*)&olo[base0 + col] = lo0;
        *(uint32_t*)&ohi[base1 + col] = h1;
        *(uint32_t*)&olo[base1 + col] = lo1;
    }
}

// ---------------- launch ----------------
extern "C" void kernel_launch(void* const* d_in, const int* in_sizes, int n_in,
                              void* d_out, int out_size)
{
    const float* x    = (const float*)d_in[0];
    const float* y    = (const float*)d_in[1];
    const float* Wqx  = (const float*)d_in[4];
    const float* Wkx  = (const float*)d_in[5];
    const float* Wvx  = (const float*)d_in[6];
    const float* Wqy  = (const float*)d_in[7];
    const float* Wky  = (const float*)d_in[8];
    const float* Wvy  = (const float*)d_in[9];
    const float* gWx  = (const float*)d_in[10];
    const float* gbx  = (const float*)d_in[11];
    const float* gWy  = (const float*)d_in[12];
    const float* gby  = (const float*)d_in[13];
    const float* Wox  = (const float*)d_in[14];
    const float* Woy  = (const float*)d_in[15];
    const float* lnxg = (const float*)d_in[16];
    const float* lnxb = (const float*)d_in[17];
    const float* lnyg = (const float*)d_in[18];
    const float* lnyb = (const float*)d_in[19];
    const float* ffxW = (const float*)d_in[20];
    const float* ffxb = (const float*)d_in[21];
    const float* ffyW = (const float*)d_in[22];
    const float* ffyb = (const float*)d_in[23];
    float* out = (float*)d_out;

    float *lgx, *lgy;
    __nv_bfloat16 *xhi, *xlo, *yhi, *ylo;
    __nv_bfloat16 *qxhi, *qxlo, *kxhi, *kxlo, *vxhi, *vxlo;
    __nv_bfloat16 *qyhi, *qylo, *kyhi, *kylo, *vyhi, *vylo;
    __nv_bfloat16 *axhi, *axlo, *ayhi, *aylo;
    __nv_bfloat16 *x2ahi, *x2alo, *y2ahi, *y2alo, *whi, *wlo;
    cudaGetSymbolAddress((void**)&lgx, g_lgx);
    cudaGetSymbolAddress((void**)&lgy, g_lgy);
    cudaGetSymbolAddress((void**)&xhi, g_xhi);
    cudaGetSymbolAddress((void**)&xlo, g_xlo);
    cudaGetSymbolAddress((void**)&yhi, g_yhi);
    cudaGetSymbolAddress((void**)&ylo, g_ylo);
    cudaGetSymbolAddress((void**)&qxhi, g_qxhi);
    cudaGetSymbolAddress((void**)&qxlo, g_qxlo);
    cudaGetSymbolAddress((void**)&kxhi, g_kxhi);
    cudaGetSymbolAddress((void**)&kxlo, g_kxlo);
    cudaGetSymbolAddress((void**)&vxhi, g_vxhi);
    cudaGetSymbolAddress((void**)&vxlo, g_vxlo);
    cudaGetSymbolAddress((void**)&qyhi, g_qyhi);
    cudaGetSymbolAddress((void**)&qylo, g_qylo);
    cudaGetSymbolAddress((void**)&kyhi, g_kyhi);
    cudaGetSymbolAddress((void**)&kylo, g_kylo);
    cudaGetSymbolAddress((void**)&vyhi, g_vyhi);
    cudaGetSymbolAddress((void**)&vylo, g_vylo);
    cudaGetSymbolAddress((void**)&axhi, g_axhi);
    cudaGetSymbolAddress((void**)&axlo, g_axlo);
    cudaGetSymbolAddress((void**)&ayhi, g_ayhi);
    cudaGetSymbolAddress((void**)&aylo, g_aylo);
    cudaGetSymbolAddress((void**)&x2ahi, g_x2ahi);
    cudaGetSymbolAddress((void**)&x2alo, g_x2alo);
    cudaGetSymbolAddress((void**)&y2ahi, g_y2ahi);
    cudaGetSymbolAddress((void**)&y2alo, g_y2alo);
    cudaGetSymbolAddress((void**)&whi, g_whi);
    cudaGetSymbolAddress((void**)&wlo, g_wlo);

    cudaFuncSetAttribute(mma_gemm, cudaFuncAttributeMaxDynamicSharedMemorySize, SMEM_GEMM_DYN);
    cudaFuncSetAttribute(gemm_ln<0>, cudaFuncAttributeMaxDynamicSharedMemorySize, SMEM_GLN);
    cudaFuncSetAttribute(gemm_ln<1>, cudaFuncAttributeMaxDynamicSharedMemorySize, SMEM_GLN);
    cudaFuncSetAttribute(mma_attn, cudaFuncAttributeMaxDynamicSharedMemorySize, ATT_SMEM);

    const int WSZ = DMODEL * DMODEL;  // 65536
    const float QSCL = 0.125f;        // 1/sqrt(64)

    // 1) fused split + gate
    split_gate_kernel<<<MX / 8, 256>>>(x, xhi, xlo, gWx, gbx, out + OFF_GX, lgx, MX);
    split_gate_kernel<<<MY / 8, 256>>>(y, yhi, ylo, gWy, gby, out + OFF_GY, lgy, MY);
    WSrc ws;
    ws.s[0] = Wqx; ws.s[1] = Wkx; ws.s[2] = Wvx;
    ws.s[3] = Wqy; ws.s[4] = Wky; ws.s[5] = Wvy;
    ws.s[6] = Wox; ws.s[7] = Woy; ws.s[8] = ffxW; ws.s[9] = ffyW;
    wsplit_kernel<<<dim3(WSZ / 4 / 256, 10), 256>>>(ws, whi, wlo);

    // 2) QKV projections (emit bf16 splits; q pre-scaled)
    {
        GemmArgs a = {};
        a.Ahi = xhi; a.Alo = xlo;
        a.Whi[0] = whi + 0 * WSZ; a.Wlo[0] = wlo + 0 * WSZ;
        a.Chi[0] = qxhi; a.Clo[0] = qxlo; a.scl[0] = QSCL;
        a.Whi[1] = whi + 1 * WSZ; a.Wlo[1] = wlo + 1 * WSZ;
        a.Chi[1] = kxhi; a.Clo[1] = kxlo; a.scl[1] = 1.f;
        a.Whi[2] = whi + 2 * WSZ; a.Wlo[2] = wlo + 2 * WSZ;
        a.Chi[2] = vxhi; a.Clo[2] = vxlo; a.scl[2] = 1.f;
        mma_gemm<<<dim3(2, MX / 128, 3), 256, SMEM_GEMM_DYN>>>(a);
    }
    {
        GemmArgs a = {};
        a.Ahi = yhi; a.Alo = ylo;
        a.Whi[0] = whi + 3 * WSZ; a.Wlo[0] = wlo + 3 * WSZ;
        a.Chi[0] = qyhi; a.Clo[0] = qylo; a.scl[0] = QSCL;
        a.Whi[1] = whi + 4 * WSZ; a.Wlo[1] = wlo + 4 * WSZ;
        a.Chi[1] = kyhi; a.Clo[1] = kylo; a.scl[1] = 1.f;
        a.Whi[2] = whi + 5 * WSZ; a.Wlo[2] = wlo + 5 * WSZ;
        a.Chi[2] = vyhi; a.Clo[2] = vylo; a.scl[2] = 1.f;
        mma_gemm<<<dim3(2, MY / 128, 3), 256, SMEM_GEMM_DYN>>>(a);
    }

    // 3) attention (tensor cores)
    mma_attn<<<dim3(NX / 128, NHEAD, BATCH), 256, ATT_SMEM>>>(
        qxhi, qxlo, kyhi, kylo, vyhi, vylo, lgy, axhi, axlo, NX, NY);
    mma_attn<<<dim3(NY / 128, NHEAD, BATCH), 256, ATT_SMEM>>>(
        qyhi, qylo, kxhi, kxlo, vxhi, vxlo, lgx, ayhi, aylo, NY, NX);

    // 4) fused oproj + residual + LN (emits x2a/y2a splits)
    gemm_ln<0><<<MX / 64, 256, SMEM_GLN>>>(
        axhi, axlo, whi + 6 * WSZ, wlo + 6 * WSZ,
        nullptr, x, nullptr, nullptr, lnxg, lnxb,
        nullptr, x2ahi, x2alo);
    gemm_ln<0><<<MY / 64, 256, SMEM_GLN>>>(
        ayhi, aylo, whi + 7 * WSZ, wlo + 7 * WSZ,
        nullptr, y, nullptr, nullptr, lnyg, lnyb,
        nullptr, y2ahi, y2alo);

    // 5) fused FF(silu) + residual + LN -> final output
    gemm_ln<1><<<MX / 64, 256, SMEM_GLN>>>(
        x2ahi, x2alo, whi + 8 * WSZ, wlo + 8 * WSZ,
        ffxb, nullptr, x2ahi, x2alo, lnxg, lnxb,
        out + OFF_X2, nullptr, nullptr);
    gemm_ln<1><<<MY / 64, 256, SMEM_GLN>>>(
        y2ahi, y2alo, whi + 9 * WSZ, wlo + 9 * WSZ,
        ffyb, nullptr, y2ahi, y2alo, lnyg, lnyb,
        out + OFF_Y2, nullptr, nullptr);
}

// round 7
// speedup vs baseline: 5.0406x; 1.7904x over previous
#include <cuda_runtime.h>
#include <cuda_bf16.h>
#include <math.h>
#include <stdint.h>

// ---------------- problem constants ----------------
#define BATCH 16
#define NX 512
#define NY 1024
#define DMODEL 256
#define NHEAD 4
#define DK 64
#define MX (BATCH * NX)   // 8192
#define MY (BATCH * NY)   // 16384

#define OFF_X2 0
#define OFF_Y2 (MX * DMODEL)
#define OFF_GX (OFF_Y2 + MY * DMODEL)
#define OFF_GY (OFF_GX + MX)

// ---------------- scratch ----------------
__device__ float g_lgx[MX];
__device__ float g_lgy[MY];

__device__ __nv_bfloat16 g_xhi[MX * DMODEL];
__device__ __nv_bfloat16 g_yhi[MY * DMODEL];
__device__ __nv_bfloat16 g_qxhi[MX * DMODEL];
__device__ __nv_bfloat16 g_kxhi[MX * DMODEL];
__device__ __nv_bfloat16 g_vxhi[MX * DMODEL];
__device__ __nv_bfloat16 g_qyhi[MY * DMODEL];
__device__ __nv_bfloat16 g_kyhi[MY * DMODEL];
__device__ __nv_bfloat16 g_vyhi[MY * DMODEL];
__device__ __nv_bfloat16 g_axhi[MX * DMODEL];
__device__ __nv_bfloat16 g_ayhi[MY * DMODEL];
__device__ __nv_bfloat16 g_x2ahi[MX * DMODEL];
__device__ __nv_bfloat16 g_x2alo[MX * DMODEL];
__device__ __nv_bfloat16 g_y2ahi[MY * DMODEL];
__device__ __nv_bfloat16 g_y2alo[MY * DMODEL];
__device__ __nv_bfloat16 g_whi[10 * DMODEL * DMODEL];
__device__ __nv_bfloat16 g_wlo[10 * DMODEL * DMODEL];

// ---------------- helpers ----------------
__device__ __forceinline__ uint32_t smem_u32(const void* p) {
    uint32_t a;
    asm("{ .reg .u64 t; cvta.to.shared.u64 t, %1; cvt.u32.u64 %0, t; }"
        : "=r"(a) : "l"(p));
    return a;
}

#define SMEM_SWIZZLE_128B(off) ((off) ^ (((off) >> 3) & 0x70))

__device__ __forceinline__ void ldsm_x4(uint32_t* r, uint32_t addr) {
    asm volatile("ldmatrix.sync.aligned.m8n8.x4.shared.b16 {%0,%1,%2,%3}, [%4];"
                 : "=r"(r[0]), "=r"(r[1]), "=r"(r[2]), "=r"(r[3]) : "r"(addr));
}

__device__ __forceinline__ void ldsm_x4_t(uint32_t* r, uint32_t addr) {
    asm volatile("ldmatrix.sync.aligned.m8n8.x4.trans.shared.b16 {%0,%1,%2,%3}, [%4];"
                 : "=r"(r[0]), "=r"(r[1]), "=r"(r[2]), "=r"(r[3]) : "r"(addr));
}

__device__ __forceinline__ void mma16816(float* d, const uint32_t* a, const uint32_t* b) {
    asm volatile(
        "mma.sync.aligned.m16n8k16.row.col.f32.bf16.bf16.f32 "
        "{%0,%1,%2,%3}, {%4,%5,%6,%7}, {%8,%9}, {%0,%1,%2,%3};"
        : "+f"(d[0]), "+f"(d[1]), "+f"(d[2]), "+f"(d[3])
        : "r"(a[0]), "r"(a[1]), "r"(a[2]), "r"(a[3]), "r"(b[0]), "r"(b[1]));
}

__device__ __forceinline__ void cpa16(uint32_t dst, const void* src) {
    asm volatile("cp.async.cg.shared.global [%0], [%1], 16;" :: "r"(dst), "l"(src));
}
#define CP_COMMIT() asm volatile("cp.async.commit_group;" ::: "memory")
#define CP_WAIT0()  asm volatile("cp.async.wait_group 0;" ::: "memory")
#define CP_WAIT1()  asm volatile("cp.async.wait_group 1;" ::: "memory")

__device__ __forceinline__ uint32_t pack2(float a, float b) {
    __nv_bfloat162 H(__float2bfloat16(a), __float2bfloat16(b));
    return *(uint32_t*)&H;
}

__device__ __forceinline__ uint32_t pack_split(float a, float b, uint32_t& lo) {
    __nv_bfloat16 ha = __float2bfloat16(a), hb = __float2bfloat16(b);
    __nv_bfloat16 la = __float2bfloat16(a - __bfloat162float(ha));
    __nv_bfloat16 lb = __float2bfloat16(b - __bfloat162float(hb));
    __nv_bfloat162 H(ha, hb), L(la, lb);
    lo = *(uint32_t*)&L;
    return *(uint32_t*)&H;
}

__device__ __forceinline__ float softplusf(float x) {
    return (x > 20.f) ? x : log1pf(expf(x));
}

// ---------------- fused split(hi) + evidential gate ----------------
__global__ __launch_bounds__(256) void split_gate_kernel(
    const float* __restrict__ src, __nv_bfloat16* __restrict__ hi,
    const float* __restrict__ gW, const float* __restrict__ gb,
    float* __restrict__ g_out, float* __restrict__ lg_out, int ntok)
{
    const int wid = threadIdx.x >> 5;
    const int lane = threadIdx.x & 31;
    const int token = blockIdx.x * 8 + wid;
    if (token >= ntok) return;

    const float4* row = (const float4*)(src + (size_t)token * DMODEL);
    float4 v0 = row[lane];
    float4 v1 = row[lane + 32];

    uint32_t* hp = (uint32_t*)(hi + (size_t)token * DMODEL);
    hp[2 * lane]          = pack2(v0.x, v0.y);
    hp[2 * lane + 1]      = pack2(v0.z, v0.w);
    hp[64 + 2 * lane]     = pack2(v1.x, v1.y);
    hp[64 + 2 * lane + 1] = pack2(v1.z, v1.w);

    float p[4];
    #pragma unroll
    for (int j = 0; j < 4; j++) {
        float4 w0 = ((const float4*)gW)[j * 64 + lane];
        float4 w1 = ((const float4*)gW)[j * 64 + 32 + lane];
        p[j] = v0.x * w0.x + v0.y * w0.y + v0.z * w0.z + v0.w * w0.w
             + v1.x * w1.x + v1.y * w1.y + v1.z * w1.z + v1.w * w1.w;
    }
    #pragma unroll
    for (int o = 16; o > 0; o >>= 1) {
        p[0] += __shfl_xor_sync(0xffffffffu, p[0], o);
        p[1] += __shfl_xor_sync(0xffffffffu, p[1], o);
        p[2] += __shfl_xor_sync(0xffffffffu, p[2], o);
        p[3] += __shfl_xor_sync(0xffffffffu, p[3], o);
    }
    if (lane == 0) {
        float mu    = p[0] + gb[0];
        float v     = softplusf(p[1] + gb[1]) + 1e-6f;
        float alpha = softplusf(p[2] + gb[2]) + 1.0f + 1e-6f;
        float beta  = softplusf(p[3] + gb[3]) + 1e-6f;
        float var_ep = beta / (v * (alpha - 1.0f));
        float g = (1.0f / (1.0f + expf(-mu))) * expf(-2.0f * var_ep);
        g = fmaxf(g, 1e-6f);
        g_out[token]  = g;
        lg_out[token] = logf(g);
    }
}

// ---------------- weight split (hi for all; lo only for FF weights m>=8) ----------------
struct WSrc { const float* s[10]; };

__global__ __launch_bounds__(256) void wsplit_kernel(
    WSrc ws, __nv_bfloat16* __restrict__ hi, __nv_bfloat16* __restrict__ lo)
{
    int m = blockIdx.y;
    int i = blockIdx.x * 256 + threadIdx.x;
    float4 v = ((const float4*)ws.s[m])[i];
    size_t base = (size_t)m * DMODEL * DMODEL / 2 + 2 * i;
    if (m >= 8) {
        uint32_t l0, l1;
        uint32_t h0 = pack_split(v.x, v.y, l0);
        uint32_t h1 = pack_split(v.z, v.w, l1);
        ((uint32_t*)hi)[base]     = h0;
        ((uint32_t*)hi)[base + 1] = h1;
        ((uint32_t*)lo)[base]     = l0;
        ((uint32_t*)lo)[base + 1] = l1;
    } else {
        ((uint32_t*)hi)[base]     = pack2(v.x, v.y);
        ((uint32_t*)hi)[base + 1] = pack2(v.z, v.w);
    }
}

// ---------------- QKV HMMA GEMM (1-term bf16, cp.async double-buffered) ----------------
// CTA tile 128x128, K-chunks of 64, 8 warps (2x4), warp tile 64x32.
#define QK_TILE_B 16384
#define QK_STAGE (2 * QK_TILE_B)        // 32KB
#define SMEM_GEMM_DYN (2 * QK_STAGE)    // 64KB

struct GemmArgs {
    const __nv_bfloat16* Ahi;
    const __nv_bfloat16* Whi[3];
    __nv_bfloat16* Chi[3];
    float scl[3];
};

__global__ __launch_bounds__(256) void mma_gemm(GemmArgs args)
{
    extern __shared__ char smem[];
    const uint32_t sb = smem_u32(smem);

    const int tid = threadIdx.x;
    const int wid = tid >> 5;
    const int lane = tid & 31;
    const int z = blockIdx.z;
    const int bm = blockIdx.y * 128;
    const int bn = blockIdx.x * 128;
    const int wm = (wid & 1) * 64;
    const int wn = (wid >> 1) * 32;

    const __nv_bfloat16* __restrict__ Ahi = args.Ahi;
    const __nv_bfloat16* __restrict__ Whi = args.Whi[z];

    float acc[4][4][4];
    #pragma unroll
    for (int i = 0; i < 4; i++)
        #pragma unroll
        for (int j = 0; j < 4; j++)
            #pragma unroll
            for (int c = 0; c < 4; c++) acc[i][j][c] = 0.f;

    const int rofs = ((lane >> 3) & 1) * 8 + (lane & 7);
    const int kofs = ((lane >> 4) & 1) * 16;

    auto load_stage = [&](int stage, int k0) {
        const __nv_bfloat16* srcs[2] = {Ahi, Whi};
        const int rb[2] = {bm, bn};
        const uint32_t base = sb + stage * QK_STAGE;
        #pragma unroll
        for (int i = 0; i < 8; i++) {
            int idx = tid + i * 256;      // 0..2047
            int arr = idx >> 10;
            int rem = idx & 1023;
            int r = rem >> 3, f = rem & 7;
            uint32_t dst = base + arr * QK_TILE_B + SMEM_SWIZZLE_128B((uint32_t)(r * 128 + f * 16));
            cpa16(dst, srcs[arr] + (size_t)(rb[arr] + r) * DMODEL + k0 + f * 8);
        }
    };

    load_stage(0, 0);
    CP_COMMIT();

    for (int kc = 0; kc < 4; kc++) {
        const int s = kc & 1;
        if (kc + 1 < 4) {
            load_stage(s ^ 1, (kc + 1) * 64);
            CP_COMMIT();
            CP_WAIT1();
        } else {
            CP_WAIT0();
        }
        __syncthreads();

        const uint32_t sA = sb + s * QK_STAGE;
        const uint32_t sB = sA + QK_TILE_B;

        #pragma unroll
        for (int ks = 0; ks < 4; ks++) {
            const int kb = ks * 32 + kofs;
            uint32_t ah[4][4], bh[4][2];
            #pragma unroll
            for (int mt = 0; mt < 4; mt++) {
                int row = wm + mt * 16 + rofs;
                ldsm_x4(ah[mt], sA + SMEM_SWIZZLE_128B((uint32_t)(row * 128 + kb)));
            }
            #pragma unroll
            for (int p = 0; p < 2; p++) {
                int row = wn + p * 16 + rofs;
                uint32_t t[4];
                ldsm_x4(t, sB + SMEM_SWIZZLE_128B((uint32_t)(row * 128 + kb)));
                bh[2 * p][0] = t[0]; bh[2 * p][1] = t[2];
                bh[2 * p + 1][0] = t[1]; bh[2 * p + 1][1] = t[3];
            }
            #pragma unroll
            for (int mt = 0; mt < 4; mt++)
                #pragma unroll
                for (int nt = 0; nt < 4; nt++)
                    mma16816(acc[mt][nt], ah[mt], bh[nt]);
        }
        __syncthreads();
    }

    const int rbase = bm + wm + (lane >> 2);
    const int cbase = bn + wn + (lane & 3) * 2;
    const float s = args.scl[z];
    __nv_bfloat16* __restrict__ Chi = args.Chi[z];
    #pragma unroll
    for (int mt = 0; mt < 4; mt++) {
        #pragma unroll
        for (int nt = 0; nt < 4; nt++) {
            int col = cbase + nt * 8;
            int r0 = rbase + mt * 16;
            *(uint32_t*)&Chi[(size_t)r0 * DMODEL + col] =
                pack2(acc[mt][nt][0] * s, acc[mt][nt][1] * s);
            *(uint32_t*)&Chi[(size_t)(r0 + 8) * DMODEL + col] =
                pack2(acc[mt][nt][2] * s, acc[mt][nt][3] * s);
        }
    }
}

// ---------------- fused GEMM + residual + LayerNorm ----------------
// Tile 64 rows x 256 cols, 8 warps (2x4), warp tile 32x64, K-chunks 64, double-buffered.
// PATH 0 (oproj): 1-term bf16; resid fp32; emit bf16 hi/lo splits.
// PATH 1 (FF): 3-term split; bias+silu; resid = hi+lo; write fp32 out.
template <int PATH>
__global__ __launch_bounds__(256) void gemm_ln(
    const __nv_bfloat16* __restrict__ Ahi, const __nv_bfloat16* __restrict__ Alo,
    const __nv_bfloat16* __restrict__ Whi, const __nv_bfloat16* __restrict__ Wlo,
    const float* __restrict__ bias,
    const float* __restrict__ resid_f32,
    const __nv_bfloat16* __restrict__ rhi, const __nv_bfloat16* __restrict__ rlo,
    const float* __restrict__ gamma, const float* __restrict__ beta,
    float* __restrict__ out_f32,
    __nv_bfloat16* __restrict__ ohi, __nv_bfloat16* __restrict__ olo)
{
    constexpr int A_B   = 8192;                          // 64 rows * 128B
    constexpr int STAGE = (PATH == 0) ? (A_B + 32768) : (2 * A_B + 2 * 32768);
    constexpr int BHI   = (PATH == 0) ? A_B : 2 * A_B;
    constexpr int STATS = 2 * STAGE;

    extern __shared__ char smem[];
    const uint32_t sb = smem_u32(smem);
    float* stat_sum = (float*)(smem + STATS);
    float* stat_sq  = (float*)(smem + STATS + 1024);

    const int tid = threadIdx.x;
    const int wid = tid >> 5;
    const int lane = tid & 31;
    const int bm = blockIdx.x * 64;
    const int wm = (wid >> 2) * 32;
    const int wn = (wid & 3) * 64;
    const int nw = wid & 3;

    const int rofs = ((lane >> 3) & 1) * 8 + (lane & 7);
    const int kofs = ((lane >> 4) & 1) * 16;

    float acc[2][8][4];
    #pragma unroll
    for (int i = 0; i < 2; i++)
        #pragma unroll
        for (int j = 0; j < 8; j++)
            #pragma unroll
            for (int c = 0; c < 4; c++) acc[i][j][c] = 0.f;

    auto load_stage = [&](int stage, int k0) {
        const uint32_t base = sb + stage * STAGE;
        if (PATH == 0) {
            #pragma unroll
            for (int i = 0; i < 10; i++) {
                int idx = tid + i * 256;      // 0..2559
                uint32_t dst;
                const __nv_bfloat16* src;
                if (idx < 512) {
                    int r = idx >> 3, f = idx & 7;
                    dst = base + SMEM_SWIZZLE_128B((uint32_t)(r * 128 + f * 16));
                    src = Ahi + (size_t)(bm + r) * DMODEL + k0 + f * 8;
                } else {
                    int j = idx - 512;
                    int r = j >> 3, f = j & 7;
                    dst = base + BHI + SMEM_SWIZZLE_128B((uint32_t)(r * 128 + f * 16));
                    src = Whi + (size_t)r * DMODEL + k0 + f * 8;
                }
                cpa16(dst, src);
            }
        } else {
            #pragma unroll
            for (int i = 0; i < 20; i++) {
                int idx = tid + i * 256;      // 0..5119
                uint32_t dst;
                const __nv_bfloat16* src;
                if (idx < 512) {
                    int r = idx >> 3, f = idx & 7;
                    dst = base + SMEM_SWIZZLE_128B((uint32_t)(r * 128 + f * 16));
                    src = Ahi + (size_t)(bm + r) * DMODEL + k0 + f * 8;
                } else if (idx < 1024) {
                    int j = idx - 512;
                    int r = j >> 3, f = j & 7;
                    dst = base + A_B + SMEM_SWIZZLE_128B((uint32_t)(r * 128 + f * 16));
                    src = Alo + (size_t)(bm + r) * DMODEL + k0 + f * 8;
                } else if (idx < 3072) {
                    int j = idx - 1024;
                    int r = j >> 3, f = j & 7;
                    dst = base + BHI + SMEM_SWIZZLE_128B((uint32_t)(r * 128 + f * 16));
                    src = Whi + (size_t)r * DMODEL + k0 + f * 8;
                } else {
                    int j = idx - 3072;
                    int r = j >> 3, f = j & 7;
                    dst = base + BHI + 32768 + SMEM_SWIZZLE_128B((uint32_t)(r * 128 + f * 16));
                    src = Wlo + (size_t)r * DMODEL + k0 + f * 8;
                }
                cpa16(dst, src);
            }
        }
    };

    load_stage(0, 0);
    CP_COMMIT();

    for (int kc = 0; kc < 4; kc++) {
        const int s = kc & 1;
        if (kc + 1 < 4) {
            load_stage(s ^ 1, (kc + 1) * 64);
            CP_COMMIT();
            CP_WAIT1();
        } else {
            CP_WAIT0();
        }
        __syncthreads();

        const uint32_t sAhi = sb + s * STAGE;
        const uint32_t sAlo = sAhi + A_B;
        const uint32_t sBhi = sAhi + BHI;
        const uint32_t sBlo = sBhi + 32768;

        #pragma unroll
        for (int ks = 0; ks < 4; ks++) {
            const int kb = ks * 32 + kofs;
            uint32_t ah[2][4], al[2][4], bh[8][2], bl[8][2];
            #pragma unroll
            for (int mt = 0; mt < 2; mt++) {
                int row = wm + mt * 16 + rofs;
                uint32_t so = SMEM_SWIZZLE_128B((uint32_t)(row * 128 + kb));
                ldsm_x4(ah[mt], sAhi + so);
                if (PATH == 1) ldsm_x4(al[mt], sAlo + so);
            }
            #pragma unroll
            for (int p = 0; p < 4; p++) {
                int row = wn + p * 16 + rofs;
                uint32_t so = SMEM_SWIZZLE_128B((uint32_t)(row * 128 + kb));
                uint32_t t[4];
                ldsm_x4(t, sBhi + so);
                bh[2 * p][0] = t[0]; bh[2 * p][1] = t[2];
                bh[2 * p + 1][0] = t[1]; bh[2 * p + 1][1] = t[3];
                if (PATH == 1) {
                    ldsm_x4(t, sBlo + so);
                    bl[2 * p][0] = t[0]; bl[2 * p][1] = t[2];
                    bl[2 * p + 1][0] = t[1]; bl[2 * p + 1][1] = t[3];
                }
            }
            #pragma unroll
            for (int mt = 0; mt < 2; mt++)
                #pragma unroll
                for (int nt = 0; nt < 8; nt++)
                    mma16816(acc[mt][nt], ah[mt], bh[nt]);
            if (PATH == 1) {
                #pragma unroll
                for (int mt = 0; mt < 2; mt++)
                    #pragma unroll
                    for (int nt = 0; nt < 8; nt++)
                        mma16816(acc[mt][nt], ah[mt], bl[nt]);
                #pragma unroll
                for (int mt = 0; mt < 2; mt++)
                    #pragma unroll
                    for (int nt = 0; nt < 8; nt++)
                        mma16816(acc[mt][nt], al[mt], bh[nt]);
            }
        }
        __syncthreads();
    }

    // ---- epilogue ----
    const int lr = lane >> 2;
    const int lc = (lane & 3) * 2;
    float rsum[2][2] = {}, rsq[2][2] = {};

    #pragma unroll
    for (int mt = 0; mt < 2; mt++) {
        #pragma unroll
        for (int nt = 0; nt < 8; nt++) {
            int c = wn + nt * 8 + lc;
            int gr0 = bm + wm + mt * 16 + lr;
            float v0 = acc[mt][nt][0], v1 = acc[mt][nt][1];
            float v2 = acc[mt][nt][2], v3 = acc[mt][nt][3];
            if (PATH == 1) {
                float b0 = bias[c], b1 = bias[c + 1];
                v0 += b0; v1 += b1; v2 += b0; v3 += b1;
                v0 = v0 / (1.0f + __expf(-v0));
                v1 = v1 / (1.0f + __expf(-v1));
                v2 = v2 / (1.0f + __expf(-v2));
                v3 = v3 / (1.0f + __expf(-v3));
                uint32_t rh0 = *(const uint32_t*)&rhi[(size_t)gr0 * DMODEL + c];
                uint32_t rl0 = *(const uint32_t*)&rlo[(size_t)gr0 * DMODEL + c];
                uint32_t rh1 = *(const uint32_t*)&rhi[(size_t)(gr0 + 8) * DMODEL + c];
                uint32_t rl1 = *(const uint32_t*)&rlo[(size_t)(gr0 + 8) * DMODEL + c];
                __nv_bfloat162 H0 = *(__nv_bfloat162*)&rh0, L0 = *(__nv_bfloat162*)&rl0;
                __nv_bfloat162 H1 = *(__nv_bfloat162*)&rh1, L1 = *(__nv_bfloat162*)&rl1;
                v0 += __bfloat162float(H0.x) + __bfloat162float(L0.x);
                v1 += __bfloat162float(H0.y) + __bfloat162float(L0.y);
                v2 += __bfloat162float(H1.x) + __bfloat162float(L1.x);
                v3 += __bfloat162float(H1.y) + __bfloat162float(L1.y);
            } else {
                float2 rA = *(const float2*)&resid_f32[(size_t)gr0 * DMODEL + c];
                float2 rB = *(const float2*)&resid_f32[(size_t)(gr0 + 8) * DMODEL + c];
                v0 += rA.x; v1 += rA.y; v2 += rB.x; v3 += rB.y;
            }
            acc[mt][nt][0] = v0; acc[mt][nt][1] = v1;
            acc[mt][nt][2] = v2; acc[mt][nt][3] = v3;
            rsum[mt][0] += v0 + v1; rsq[mt][0] += v0 * v0 + v1 * v1;
            rsum[mt][1] += v2 + v3; rsq[mt][1] += v2 * v2 + v3 * v3;
        }
    }

    #pragma unroll
    for (int mt = 0; mt < 2; mt++)
        #pragma unroll
        for (int hf = 0; hf < 2; hf++) {
            rsum[mt][hf] += __shfl_xor_sync(0xffffffffu, rsum[mt][hf], 1);
            rsum[mt][hf] += __shfl_xor_sync(0xffffffffu, rsum[mt][hf], 2);
            rsq[mt][hf]  += __shfl_xor_sync(0xffffffffu, rsq[mt][hf], 1);
            rsq[mt][hf]  += __shfl_xor_sync(0xffffffffu, rsq[mt][hf], 2);
        }
    if ((lane & 3) == 0) {
        #pragma unroll
        for (int mt = 0; mt < 2; mt++)
            #pragma unroll
            for (int hf = 0; hf < 2; hf++) {
                int row = wm + mt * 16 + lr + hf * 8;
                stat_sum[row * 4 + nw] = rsum[mt][hf];
                stat_sq[row * 4 + nw]  = rsq[mt][hf];
            }
    }
    __syncthreads();

    float mean[2][2], rstd[2][2];
    #pragma unroll
    for (int mt = 0; mt < 2; mt++)
        #pragma unroll
        for (int hf = 0; hf < 2; hf++) {
            int row = wm + mt * 16 + lr + hf * 8;
            float ts = stat_sum[row * 4 + 0] + stat_sum[row * 4 + 1]
                     + stat_sum[row * 4 + 2] + stat_sum[row * 4 + 3];
            float tq = stat_sq[row * 4 + 0] + stat_sq[row * 4 + 1]
                     + stat_sq[row * 4 + 2] + stat_sq[row * 4 + 3];
            float mu = ts * (1.0f / DMODEL);
            float var = tq * (1.0f / DMODEL) - mu * mu;
            mean[mt][hf] = mu;
            rstd[mt][hf] = rsqrtf(var + 1e-5f);
        }

    #pragma unroll
    for (int mt = 0; mt < 2; mt++) {
        #pragma unroll
        for (int nt = 0; nt < 8; nt++) {
            int c = wn + nt * 8 + lc;
            int gr0 = bm + wm + mt * 16 + lr;
            float g0 = gamma[c], g1 = gamma[c + 1];
            float b0 = beta[c],  b1 = beta[c + 1];
            float o0 = (acc[mt][nt][0] - mean[mt][0]) * rstd[mt][0] * g0 + b0;
            float o1 = (acc[mt][nt][1] - mean[mt][0]) * rstd[mt][0] * g1 + b1;
            float o2 = (acc[mt][nt][2] - mean[mt][1]) * rstd[mt][1] * g0 + b0;
            float o3 = (acc[mt][nt][3] - mean[mt][1]) * rstd[mt][1] * g1 + b1;
            if (PATH == 0) {
                uint32_t l0, l1;
                uint32_t h0 = pack_split(o0, o1, l0);
                uint32_t h1 = pack_split(o2, o3, l1);
                *(uint32_t*)&ohi[(size_t)gr0 * DMODEL + c]       = h0;
                *(uint32_t*)&olo[(size_t)gr0 * DMODEL + c]       = l0;
                *(uint32_t*)&ohi[(size_t)(gr0 + 8) * DMODEL + c] = h1;
                *(uint32_t*)&olo[(size_t)(gr0 + 8) * DMODEL + c] = l1;
            } else {
                *(float2*)&out_f32[(size_t)gr0 * DMODEL + c]       = make_float2(o0, o1);
                *(float2*)&out_f32[(size_t)(gr0 + 8) * DMODEL + c] = make_float2(o2, o3);
            }
        }
    }
}

#define SMEM_GLN0 (2 * (8192 + 32768) + 2048)            // 83968
#define SMEM_GLN1 (2 * (2 * 8192 + 2 * 32768) + 2048)    // 165888

// ---------------- HMMA flash attention (1-term bf16) ----------------
// CTA: 128 queries per (b,h), 8 warps x 16 rows. K/V tiles 64 keys, double-buffered.
// smem: Q 0..16K; stage s at 16K + s*16K (K +0, V +8K); lg at 48K + s*256.
#define ATT_SMEM (49152 + 512)

__device__ __forceinline__ void att_load_kv(
    uint32_t sb, int stage, int kt, int b, int h, int Tk,
    const __nv_bfloat16* kh, const __nv_bfloat16* vh,
    const float* lg, int tid)
{
    const __nv_bfloat16* srcs[2] = {kh, vh};
    uint32_t base = sb + 16384 + stage * 16384;
    #pragma unroll
    for (int i = 0; i < 4; i++) {
        int idx = tid + i * 256;
        int arr = idx >> 9;
        int rem = idx & 511;
        int r = rem >> 3, f = rem & 7;
        uint32_t dst = base + arr * 8192 + SMEM_SWIZZLE_128B((uint32_t)(r * 128 + f * 16));
        cpa16(dst, srcs[arr] + ((size_t)(b * Tk + kt * 64 + r) * DMODEL + h * DK) + f * 8);
    }
    if (tid < 16)
        cpa16(sb + 49152 + stage * 256 + tid * 16, lg + b * Tk + kt * 64 + tid * 4);
}

__global__ __launch_bounds__(256) void mma_attn(
    const __nv_bfloat16* __restrict__ qhi,
    const __nv_bfloat16* __restrict__ khi,
    const __nv_bfloat16* __restrict__ vhi,
    const float* __restrict__ lgk,
    __nv_bfloat16* __restrict__ ohi,
    int Tq, int Tk)
{
    extern __shared__ char smem[];
    const uint32_t sb = smem_u32(smem);
    const int tid = threadIdx.x;
    const int wid = tid >> 5;
    const int lane = tid & 31;
    const int b = blockIdx.z;
    const int h = blockIdx.y;
    const int bq = blockIdx.x * 128;
    const int wm = wid * 16;
    const int rofs = ((lane >> 3) & 1) * 8 + (lane & 7);
    const int kofs = ((lane >> 4) & 1) * 16;

    // stage Q (sync), prefetch tile 0 (async)
    #pragma unroll
    for (int i = 0; i < 4; i++) {
        int idx = tid + i * 256;
        int r = idx >> 3, f = idx & 7;
        uint32_t so = SMEM_SWIZZLE_128B((uint32_t)(r * 128 + f * 16));
        size_t g = (size_t)(b * Tq + bq + r) * DMODEL + h * DK;
        *(uint4*)(smem + so) = ((const uint4*)(qhi + g))[f];
    }
    att_load_kv(sb, 0, 0, b, h, Tk, khi, vhi, lgk, tid);
    CP_COMMIT();
    __syncthreads();

    uint32_t qfh[4][4];
    #pragma unroll
    for (int ks = 0; ks < 4; ks++)
        ldsm_x4(qfh[ks], sb + SMEM_SWIZZLE_128B((uint32_t)((wm + rofs) * 128 + ks * 32 + kofs)));

    float o[8][4];
    #pragma unroll
    for (int t = 0; t < 8; t++)
        #pragma unroll
        for (int c = 0; c < 4; c++) o[t][c] = 0.f;
    float m0 = -INFINITY, m1 = -INFINITY, l0 = 0.f, l1 = 0.f;

    const int ntile = Tk / 64;
    for (int kt = 0; kt < ntile; kt++) {
        const int s = kt & 1;
        CP_WAIT0();
        __syncthreads();
        if (kt + 1 < ntile) {
            att_load_kv(sb, s ^ 1, kt + 1, b, h, Tk, khi, vhi, lgk, tid);
            CP_COMMIT();
        }
        const uint32_t sK = sb + 16384 + s * 16384;
        const uint32_t sV = sK + 8192;
        const float* lgs = (const float*)(smem + 49152 + s * 256);

        // ---- S = Q K^T ----
        float sd[8][4];
        #pragma unroll
        for (int nt = 0; nt < 8; nt++)
            #pragma unroll
            for (int c = 0; c < 4; c++) sd[nt][c] = 0.f;

        #pragma unroll
        for (int ks = 0; ks < 4; ks++) {
            uint32_t bh[8][2];
            #pragma unroll
            for (int p = 0; p < 4; p++) {
                uint32_t t[4];
                ldsm_x4(t, sK + SMEM_SWIZZLE_128B((uint32_t)((p * 16 + rofs) * 128 + ks * 32 + kofs)));
                bh[2 * p][0] = t[0]; bh[2 * p][1] = t[2];
                bh[2 * p + 1][0] = t[1]; bh[2 * p + 1][1] = t[3];
            }
            #pragma unroll
            for (int nt = 0; nt < 8; nt++)
                mma16816(sd[nt], qfh[ks], bh[nt]);
        }

        // ---- bias + online softmax ----
        float mt0 = m0, mt1 = m1;
        #pragma unroll
        for (int nt = 0; nt < 8; nt++) {
            int col = nt * 8 + (lane & 3) * 2;
            float lg0 = lgs[col], lg1 = lgs[col + 1];
            sd[nt][0] += lg0; sd[nt][1] += lg1;
            sd[nt][2] += lg0; sd[nt][3] += lg1;
            mt0 = fmaxf(mt0, fmaxf(sd[nt][0], sd[nt][1]));
            mt1 = fmaxf(mt1, fmaxf(sd[nt][2], sd[nt][3]));
        }
        mt0 = fmaxf(mt0, __shfl_xor_sync(0xffffffffu, mt0, 1));
        mt0 = fmaxf(mt0, __shfl_xor_sync(0xffffffffu, mt0, 2));
        mt1 = fmaxf(mt1, __shfl_xor_sync(0xffffffffu, mt1, 1));
        mt1 = fmaxf(mt1, __shfl_xor_sync(0xffffffffu, mt1, 2));
        float c0 = __expf(m0 - mt0);
        float c1 = __expf(m1 - mt1);
        m0 = mt0; m1 = mt1;
        l0 *= c0; l1 *= c1;
        #pragma unroll
        for (int t = 0; t < 8; t++) {
            o[t][0] *= c0; o[t][1] *= c0; o[t][2] *= c1; o[t][3] *= c1;
        }
        #pragma unroll
        for (int nt = 0; nt < 8; nt++) {
            sd[nt][0] = __expf(sd[nt][0] - m0);
            sd[nt][1] = __expf(sd[nt][1] - m0);
            sd[nt][2] = __expf(sd[nt][2] - m1);
            sd[nt][3] = __expf(sd[nt][3] - m1);
            l0 += sd[nt][0] + sd[nt][1];
            l1 += sd[nt][2] + sd[nt][3];
        }

        // ---- O += P V ----
        #pragma unroll
        for (int kb = 0; kb < 4; kb++) {
            uint32_t pah[4];
            pah[0] = pack2(sd[2 * kb][0],     sd[2 * kb][1]);
            pah[1] = pack2(sd[2 * kb][2],     sd[2 * kb][3]);
            pah[2] = pack2(sd[2 * kb + 1][0], sd[2 * kb + 1][1]);
            pah[3] = pack2(sd[2 * kb + 1][2], sd[2 * kb + 1][3]);
            const int t4 = lane >> 3;
            #pragma unroll
            for (int dp = 0; dp < 4; dp++) {
                uint32_t so = SMEM_SWIZZLE_128B((uint32_t)(
                    (kb * 16 + (t4 & 1) * 8 + (lane & 7)) * 128 +
                    (dp * 16 + (t4 >> 1) * 8) * 2));
                uint32_t vh4[4];
                ldsm_x4_t(vh4, sV + so);
                uint32_t b0h[2] = {vh4[0], vh4[1]}, b1h[2] = {vh4[2], vh4[3]};
                mma16816(o[2 * dp],     pah, b0h);
                mma16816(o[2 * dp + 1], pah, b1h);
            }
        }
    }

    // ---- finalize ----
    float fl0 = l0 + __shfl_xor_sync(0xffffffffu, l0, 1);
    fl0 += __shfl_xor_sync(0xffffffffu, fl0, 2);
    float fl1 = l1 + __shfl_xor_sync(0xffffffffu, l1, 1);
    fl1 += __shfl_xor_sync(0xffffffffu, fl1, 2);
    float inv0 = 1.0f / fl0, inv1 = 1.0f / fl1;

    const int r0 = bq + wm + (lane >> 2);
    size_t base0 = (size_t)(b * Tq + r0) * DMODEL + h * DK;
    size_t base1 = base0 + (size_t)8 * DMODEL;
    #pragma unroll
    for (int t = 0; t < 8; t++) {
        int col = t * 8 + (lane & 3) * 2;
        *(uint32_t*)&ohi[base0 + col] = pack2(o[t][0] * inv0, o[t][1] * inv0);
        *(uint32_t*)&ohi[base1 + col] = pack2(o[t][2] * inv1, o[t][3] * inv1);
    }
}

// ---------------- launch ----------------
extern "C" void kernel_launch(void* const* d_in, const int* in_sizes, int n_in,
                              void* d_out, int out_size)
{
    const float* x    = (const float*)d_in[0];
    const float* y    = (const float*)d_in[1];
    const float* Wqx  = (const float*)d_in[4];
    const float* Wkx  = (const float*)d_in[5];
    const float* Wvx  = (const float*)d_in[6];
    const float* Wqy  = (const float*)d_in[7];
    const float* Wky  = (const float*)d_in[8];
    const float* Wvy  = (const float*)d_in[9];
    const float* gWx  = (const float*)d_in[10];
    const float* gbx  = (const float*)d_in[11];
    const float* gWy  = (const float*)d_in[12];
    const float* gby  = (const float*)d_in[13];
    const float* Wox  = (const float*)d_in[14];
    const float* Woy  = (const float*)d_in[15];
    const float* lnxg = (const float*)d_in[16];
    const float* lnxb = (const float*)d_in[17];
    const float* lnyg = (const float*)d_in[18];
    const float* lnyb = (const float*)d_in[19];
    const float* ffxW = (const float*)d_in[20];
    const float* ffxb = (const float*)d_in[21];
    const float* ffyW = (const float*)d_in[22];
    const float* ffyb = (const float*)d_in[23];
    float* out = (float*)d_out;

    float *lgx, *lgy;
    __nv_bfloat16 *xhi, *yhi;
    __nv_bfloat16 *qxhi, *kxhi, *vxhi, *qyhi, *kyhi, *vyhi;
    __nv_bfloat16 *axhi, *ayhi;
    __nv_bfloat16 *x2ahi, *x2alo, *y2ahi, *y2alo, *whi, *wlo;
    cudaGetSymbolAddress((void**)&lgx, g_lgx);
    cudaGetSymbolAddress((void**)&lgy, g_lgy);
    cudaGetSymbolAddress((void**)&xhi, g_xhi);
    cudaGetSymbolAddress((void**)&yhi, g_yhi);
    cudaGetSymbolAddress((void**)&qxhi, g_qxhi);
    cudaGetSymbolAddress((void**)&kxhi, g_kxhi);
    cudaGetSymbolAddress((void**)&vxhi, g_vxhi);
    cudaGetSymbolAddress((void**)&qyhi, g_qyhi);
    cudaGetSymbolAddress((void**)&kyhi, g_kyhi);
    cudaGetSymbolAddress((void**)&vyhi, g_vyhi);
    cudaGetSymbolAddress((void**)&axhi, g_axhi);
    cudaGetSymbolAddress((void**)&ayhi, g_ayhi);
    cudaGetSymbolAddress((void**)&x2ahi, g_x2ahi);
    cudaGetSymbolAddress((void**)&x2alo, g_x2alo);
    cudaGetSymbolAddress((void**)&y2ahi, g_y2ahi);
    cudaGetSymbolAddress((void**)&y2alo, g_y2alo);
    cudaGetSymbolAddress((void**)&whi, g_whi);
    cudaGetSymbolAddress((void**)&wlo, g_wlo);

    cudaFuncSetAttribute(mma_gemm, cudaFuncAttributeMaxDynamicSharedMemorySize, SMEM_GEMM_DYN);
    cudaFuncSetAttribute(gemm_ln<0>, cudaFuncAttributeMaxDynamicSharedMemorySize, SMEM_GLN0);
    cudaFuncSetAttribute(gemm_ln<1>, cudaFuncAttributeMaxDynamicSharedMemorySize, SMEM_GLN1);
    cudaFuncSetAttribute(mma_attn, cudaFuncAttributeMaxDynamicSharedMemorySize, ATT_SMEM);

    const int WSZ = DMODEL * DMODEL;  // 65536
    const float QSCL = 0.125f;        // 1/sqrt(64)

    // 1) fused split(hi) + gate; weight split
    split_gate_kernel<<<MX / 8, 256>>>(x, xhi, gWx, gbx, out + OFF_GX, lgx, MX);
    split_gate_kernel<<<MY / 8, 256>>>(y, yhi, gWy, gby, out + OFF_GY, lgy, MY);
    WSrc ws;
    ws.s[0] = Wqx; ws.s[1] = Wkx; ws.s[2] = Wvx;
    ws.s[3] = Wqy; ws.s[4] = Wky; ws.s[5] = Wvy;
    ws.s[6] = Wox; ws.s[7] = Woy; ws.s[8] = ffxW; ws.s[9] = ffyW;
    wsplit_kernel<<<dim3(WSZ / 4 / 256, 10), 256>>>(ws, whi, wlo);

    // 2) QKV projections (1-term bf16; q pre-scaled)
    {
        GemmArgs a = {};
        a.Ahi = xhi;
        a.Whi[0] = whi + 0 * WSZ; a.Chi[0] = qxhi; a.scl[0] = QSCL;
        a.Whi[1] = whi + 1 * WSZ; a.Chi[1] = kxhi; a.scl[1] = 1.f;
        a.Whi[2] = whi + 2 * WSZ; a.Chi[2] = vxhi; a.scl[2] = 1.f;
        mma_gemm<<<dim3(2, MX / 128, 3), 256, SMEM_GEMM_DYN>>>(a);
    }
    {
        GemmArgs a = {};
        a.Ahi = yhi;
        a.Whi[0] = whi + 3 * WSZ; a.Chi[0] = qyhi; a.scl[0] = QSCL;
        a.Whi[1] = whi + 4 * WSZ; a.Chi[1] = kyhi; a.scl[1] = 1.f;
        a.Whi[2] = whi + 5 * WSZ; a.Chi[2] = vyhi; a.scl[2] = 1.f;
        mma_gemm<<<dim3(2, MY / 128, 3), 256, SMEM_GEMM_DYN>>>(a);
    }

    // 3) attention (1-term bf16 tensor cores)
    mma_attn<<<dim3(NX / 128, NHEAD, BATCH), 256, ATT_SMEM>>>(
        qxhi, kyhi, vyhi, lgy, axhi, NX, NY);
    mma_attn<<<dim3(NY / 128, NHEAD, BATCH), 256, ATT_SMEM>>>(
        qyhi, kxhi, vxhi, lgx, ayhi, NY, NX);

    // 4) fused oproj(1-term) + residual + LN (emits x2a/y2a splits)
    gemm_ln<0><<<MX / 64, 256, SMEM_GLN0>>>(
        axhi, nullptr, whi + 6 * WSZ, nullptr,
        nullptr, x, nullptr, nullptr, lnxg, lnxb,
        nullptr, x2ahi, x2alo);
    gemm_ln<0><<<MY / 64, 256, SMEM_GLN0>>>(
        ayhi, nullptr, whi + 7 * WSZ, nullptr,
        nullptr, y, nullptr, nullptr, lnyg, lnyb,
        nullptr, y2ahi, y2alo);

    // 5) fused FF(3-term, silu) + residual + LN -> final output
    gemm_ln<1><<<MX / 64, 256, SMEM_GLN1>>>(
        x2ahi, x2alo, whi + 8 * WSZ, wlo + 8 * WSZ,
        ffxb, nullptr, x2ahi, x2alo, lnxg, lnxb,
        out + OFF_X2, nullptr, nullptr);
    gemm_ln<1><<<MY / 64, 256, SMEM_GLN1>>>(
        y2ahi, y2alo, whi + 9 * WSZ, wlo + 9 * WSZ,
        ffyb, nullptr, y2ahi, y2alo, lnyg, lnyb,
        out + OFF_Y2, nullptr, nullptr);
}

// round 8
// speedup vs baseline: 5.8201x; 1.1547x over previous
#include <cuda_runtime.h>
#include <cuda_bf16.h>
#include <math.h>
#include <stdint.h>

// ---------------- problem constants ----------------
#define BATCH 16
#define NX 512
#define NY 1024
#define DMODEL 256
#define NHEAD 4
#define DK 64
#define MX (BATCH * NX)   // 8192
#define MY (BATCH * NY)   // 16384

#define OFF_X2 0
#define OFF_Y2 (MX * DMODEL)
#define OFF_GX (OFF_Y2 + MY * DMODEL)
#define OFF_GY (OFF_GX + MX)

// ---------------- scratch ----------------
__device__ float g_lgx[MX];
__device__ float g_lgy[MY];

__device__ __nv_bfloat16 g_xhi[MX * DMODEL];
__device__ __nv_bfloat16 g_yhi[MY * DMODEL];
__device__ __nv_bfloat16 g_qxhi[MX * DMODEL];
__device__ __nv_bfloat16 g_kxhi[MX * DMODEL];
__device__ __nv_bfloat16 g_vxhi[MX * DMODEL];
__device__ __nv_bfloat16 g_qyhi[MY * DMODEL];
__device__ __nv_bfloat16 g_kyhi[MY * DMODEL];
__device__ __nv_bfloat16 g_vyhi[MY * DMODEL];
__device__ __nv_bfloat16 g_axhi[MX * DMODEL];
__device__ __nv_bfloat16 g_ayhi[MY * DMODEL];
__device__ __nv_bfloat16 g_x2ahi[MX * DMODEL];
__device__ __nv_bfloat16 g_x2alo[MX * DMODEL];
__device__ __nv_bfloat16 g_y2ahi[MY * DMODEL];
__device__ __nv_bfloat16 g_y2alo[MY * DMODEL];
__device__ __nv_bfloat16 g_whi[10 * DMODEL * DMODEL];
__device__ __nv_bfloat16 g_wlo[10 * DMODEL * DMODEL];

// ---------------- helpers ----------------
__device__ __forceinline__ uint32_t smem_u32(const void* p) {
    uint32_t a;
    asm("{ .reg .u64 t; cvta.to.shared.u64 t, %1; cvt.u32.u64 %0, t; }"
        : "=r"(a) : "l"(p));
    return a;
}

#define SMEM_SWIZZLE_128B(off) ((off) ^ (((off) >> 3) & 0x70))

__device__ __forceinline__ void ldsm_x4(uint32_t* r, uint32_t addr) {
    asm volatile("ldmatrix.sync.aligned.m8n8.x4.shared.b16 {%0,%1,%2,%3}, [%4];"
                 : "=r"(r[0]), "=r"(r[1]), "=r"(r[2]), "=r"(r[3]) : "r"(addr));
}

__device__ __forceinline__ void ldsm_x4_t(uint32_t* r, uint32_t addr) {
    asm volatile("ldmatrix.sync.aligned.m8n8.x4.trans.shared.b16 {%0,%1,%2,%3}, [%4];"
                 : "=r"(r[0]), "=r"(r[1]), "=r"(r[2]), "=r"(r[3]) : "r"(addr));
}

__device__ __forceinline__ void mma16816(float* d, const uint32_t* a, const uint32_t* b) {
    asm volatile(
        "mma.sync.aligned.m16n8k16.row.col.f32.bf16.bf16.f32 "
        "{%0,%1,%2,%3}, {%4,%5,%6,%7}, {%8,%9}, {%0,%1,%2,%3};"
        : "+f"(d[0]), "+f"(d[1]), "+f"(d[2]), "+f"(d[3])
        : "r"(a[0]), "r"(a[1]), "r"(a[2]), "r"(a[3]), "r"(b[0]), "r"(b[1]));
}

__device__ __forceinline__ void cpa16(uint32_t dst, const void* src) {
    asm volatile("cp.async.cg.shared.global [%0], [%1], 16;" :: "r"(dst), "l"(src));
}
#define CP_COMMIT() asm volatile("cp.async.commit_group;" ::: "memory")
#define CP_WAIT0()  asm volatile("cp.async.wait_group 0;" ::: "memory")
#define CP_WAIT1()  asm volatile("cp.async.wait_group 1;" ::: "memory")

__device__ __forceinline__ uint32_t pack2(float a, float b) {
    __nv_bfloat162 H(__float2bfloat16(a), __float2bfloat16(b));
    return *(uint32_t*)&H;
}

__device__ __forceinline__ uint32_t pack_split(float a, float b, uint32_t& lo) {
    __nv_bfloat16 ha = __float2bfloat16(a), hb = __float2bfloat16(b);
    __nv_bfloat16 la = __float2bfloat16(a - __bfloat162float(ha));
    __nv_bfloat16 lb = __float2bfloat16(b - __bfloat162float(hb));
    __nv_bfloat162 H(ha, hb), L(la, lb);
    lo = *(uint32_t*)&L;
    return *(uint32_t*)&H;
}

__device__ __forceinline__ float softplusf(float x) {
    return (x > 20.f) ? x : log1pf(expf(x));
}

// ---------------- fused split(hi) + evidential gate (x and y in one launch) ----------------
__global__ __launch_bounds__(256) void split_gate2(
    const float* __restrict__ x, const float* __restrict__ y,
    __nv_bfloat16* __restrict__ xhi, __nv_bfloat16* __restrict__ yhi,
    const float* __restrict__ gWx, const float* __restrict__ gbx,
    const float* __restrict__ gWy, const float* __restrict__ gby,
    float* __restrict__ gx_out, float* __restrict__ lgx,
    float* __restrict__ gy_out, float* __restrict__ lgy)
{
    const int wid = threadIdx.x >> 5;
    const int lane = threadIdx.x & 31;
    int token = blockIdx.x * 8 + wid;

    const float* src; __nv_bfloat16* hi; const float *gW, *gb;
    float *g_out, *lg_out;
    if (token < MX) {
        src = x; hi = xhi; gW = gWx; gb = gbx; g_out = gx_out; lg_out = lgx;
    } else {
        token -= MX;
        src = y; hi = yhi; gW = gWy; gb = gby; g_out = gy_out; lg_out = lgy;
    }

    const float4* row = (const float4*)(src + (size_t)token * DMODEL);
    float4 v0 = row[lane];
    float4 v1 = row[lane + 32];

    uint32_t* hp = (uint32_t*)(hi + (size_t)token * DMODEL);
    hp[2 * lane]          = pack2(v0.x, v0.y);
    hp[2 * lane + 1]      = pack2(v0.z, v0.w);
    hp[64 + 2 * lane]     = pack2(v1.x, v1.y);
    hp[64 + 2 * lane + 1] = pack2(v1.z, v1.w);

    float p[4];
    #pragma unroll
    for (int j = 0; j < 4; j++) {
        float4 w0 = ((const float4*)gW)[j * 64 + lane];
        float4 w1 = ((const float4*)gW)[j * 64 + 32 + lane];
        p[j] = v0.x * w0.x + v0.y * w0.y + v0.z * w0.z + v0.w * w0.w
             + v1.x * w1.x + v1.y * w1.y + v1.z * w1.z + v1.w * w1.w;
    }
    #pragma unroll
    for (int o = 16; o > 0; o >>= 1) {
        p[0] += __shfl_xor_sync(0xffffffffu, p[0], o);
        p[1] += __shfl_xor_sync(0xffffffffu, p[1], o);
        p[2] += __shfl_xor_sync(0xffffffffu, p[2], o);
        p[3] += __shfl_xor_sync(0xffffffffu, p[3], o);
    }
    if (lane == 0) {
        float mu    = p[0] + gb[0];
        float v     = softplusf(p[1] + gb[1]) + 1e-6f;
        float alpha = softplusf(p[2] + gb[2]) + 1.0f + 1e-6f;
        float beta  = softplusf(p[3] + gb[3]) + 1e-6f;
        float var_ep = beta / (v * (alpha - 1.0f));
        float g = (1.0f / (1.0f + expf(-mu))) * expf(-2.0f * var_ep);
        g = fmaxf(g, 1e-6f);
        g_out[token]  = g;
        lg_out[token] = logf(g);
    }
}

// ---------------- weight split (hi for all; lo only for FF weights m>=8) ----------------
struct WSrc { const float* s[10]; };

__global__ __launch_bounds__(256) void wsplit_kernel(
    WSrc ws, __nv_bfloat16* __restrict__ hi, __nv_bfloat16* __restrict__ lo)
{
    int m = blockIdx.y;
    int i = blockIdx.x * 256 + threadIdx.x;
    float4 v = ((const float4*)ws.s[m])[i];
    size_t base = (size_t)m * DMODEL * DMODEL / 2 + 2 * i;
    if (m >= 8) {
        uint32_t l0, l1;
        uint32_t h0 = pack_split(v.x, v.y, l0);
        uint32_t h1 = pack_split(v.z, v.w, l1);
        ((uint32_t*)hi)[base]     = h0;
        ((uint32_t*)hi)[base + 1] = h1;
        ((uint32_t*)lo)[base]     = l0;
        ((uint32_t*)lo)[base + 1] = l1;
    } else {
        ((uint32_t*)hi)[base]     = pack2(v.x, v.y);
        ((uint32_t*)hi)[base + 1] = pack2(v.z, v.w);
    }
}

// ---------------- QKV HMMA GEMM (x+y combined, 1-term bf16, double-buffered) ----------------
// CTA tile 128x128, K-chunks of 64, 8 warps (2x4), warp tile 64x32. 2 CTAs/SM.
#define QK_TILE_B 16384
#define QK_STAGE (2 * QK_TILE_B)        // 32KB
#define SMEM_GEMM_DYN (2 * QK_STAGE)    // 64KB

struct GemmArgs6 {
    const __nv_bfloat16* Ax;
    const __nv_bfloat16* Ay;
    const __nv_bfloat16* Whi[6];
    __nv_bfloat16* Chi[6];
    float scl[6];
};

__global__ __launch_bounds__(256, 2) void mma_gemm(GemmArgs6 args)
{
    const int z = blockIdx.z;
    const __nv_bfloat16* __restrict__ Ahi;
    if (z < 3) {
        if (blockIdx.y >= MX / 128) return;
        Ahi = args.Ax;
    } else {
        Ahi = args.Ay;
    }
    const __nv_bfloat16* __restrict__ Whi = args.Whi[z];

    extern __shared__ char smem[];
    const uint32_t sb = smem_u32(smem);

    const int tid = threadIdx.x;
    const int wid = tid >> 5;
    const int lane = tid & 31;
    const int bm = blockIdx.y * 128;
    const int bn = blockIdx.x * 128;
    const int wm = (wid & 1) * 64;
    const int wn = (wid >> 1) * 32;

    float acc[4][4][4];
    #pragma unroll
    for (int i = 0; i < 4; i++)
        #pragma unroll
        for (int j = 0; j < 4; j++)
            #pragma unroll
            for (int c = 0; c < 4; c++) acc[i][j][c] = 0.f;

    const int rofs = ((lane >> 3) & 1) * 8 + (lane & 7);
    const int kofs = ((lane >> 4) & 1) * 16;

    auto load_stage = [&](int stage, int k0) {
        const __nv_bfloat16* srcs[2] = {Ahi, Whi};
        const int rb[2] = {bm, bn};
        const uint32_t base = sb + stage * QK_STAGE;
        #pragma unroll
        for (int i = 0; i < 8; i++) {
            int idx = tid + i * 256;
            int arr = idx >> 10;
            int rem = idx & 1023;
            int r = rem >> 3, f = rem & 7;
            uint32_t dst = base + arr * QK_TILE_B + SMEM_SWIZZLE_128B((uint32_t)(r * 128 + f * 16));
            cpa16(dst, srcs[arr] + (size_t)(rb[arr] + r) * DMODEL + k0 + f * 8);
        }
    };

    load_stage(0, 0);
    CP_COMMIT();

    for (int kc = 0; kc < 4; kc++) {
        const int s = kc & 1;
        if (kc + 1 < 4) {
            load_stage(s ^ 1, (kc + 1) * 64);
            CP_COMMIT();
            CP_WAIT1();
        } else {
            CP_WAIT0();
        }
        __syncthreads();

        const uint32_t sA = sb + s * QK_STAGE;
        const uint32_t sB = sA + QK_TILE_B;

        #pragma unroll
        for (int ks = 0; ks < 4; ks++) {
            const int kb = ks * 32 + kofs;
            uint32_t ah[4][4], bh[4][2];
            #pragma unroll
            for (int mt = 0; mt < 4; mt++) {
                int row = wm + mt * 16 + rofs;
                ldsm_x4(ah[mt], sA + SMEM_SWIZZLE_128B((uint32_t)(row * 128 + kb)));
            }
            #pragma unroll
            for (int p = 0; p < 2; p++) {
                int row = wn + p * 16 + rofs;
                uint32_t t[4];
                ldsm_x4(t, sB + SMEM_SWIZZLE_128B((uint32_t)(row * 128 + kb)));
                bh[2 * p][0] = t[0]; bh[2 * p][1] = t[2];
                bh[2 * p + 1][0] = t[1]; bh[2 * p + 1][1] = t[3];
            }
            #pragma unroll
            for (int mt = 0; mt < 4; mt++)
                #pragma unroll
                for (int nt = 0; nt < 4; nt++)
                    mma16816(acc[mt][nt], ah[mt], bh[nt]);
        }
        __syncthreads();
    }

    const int rbase = bm + wm + (lane >> 2);
    const int cbase = bn + wn + (lane & 3) * 2;
    const float s = args.scl[z];
    __nv_bfloat16* __restrict__ Chi = args.Chi[z];
    #pragma unroll
    for (int mt = 0; mt < 4; mt++) {
        #pragma unroll
        for (int nt = 0; nt < 4; nt++) {
            int col = cbase + nt * 8;
            int r0 = rbase + mt * 16;
            *(uint32_t*)&Chi[(size_t)r0 * DMODEL + col] =
                pack2(acc[mt][nt][0] * s, acc[mt][nt][1] * s);
            *(uint32_t*)&Chi[(size_t)(r0 + 8) * DMODEL + col] =
                pack2(acc[mt][nt][2] * s, acc[mt][nt][3] * s);
        }
    }
}

// ---------------- fused GEMM + residual + LayerNorm (x+y combined) ----------------
// Tile 64 rows x 256 cols, 8 warps (2x4), warp tile 32x64, double-buffered.
// PATH 0 (oproj): 1-term; resid fp32; emit bf16 hi/lo splits. 2 CTAs/SM.
// PATH 1 (FF): 3-term; bias+silu; resid hi+lo; fp32 out. 1 CTA/SM.
struct LNArgs {
    const __nv_bfloat16* Ahi[2];
    const __nv_bfloat16* Alo[2];
    const __nv_bfloat16* Whi[2];
    const __nv_bfloat16* Wlo[2];
    const float* bias[2];
    const float* resid_f32[2];
    const __nv_bfloat16* rhi[2];
    const __nv_bfloat16* rlo[2];
    const float* gamma[2];
    const float* beta[2];
    float* out_f32[2];
    __nv_bfloat16* ohi[2];
    __nv_bfloat16* olo[2];
    int nblk0;   // MX/64
};

template <int PATH, int MINB>
__global__ __launch_bounds__(256, MINB) void gemm_ln(LNArgs args)
{
    constexpr int A_B   = 8192;
    constexpr int STAGE = (PATH == 0) ? (A_B + 32768) : (2 * A_B + 2 * 32768);
    constexpr int BHI   = (PATH == 0) ? A_B : 2 * A_B;
    constexpr int STATS = 2 * STAGE;

    const int side = (blockIdx.x >= args.nblk0) ? 1 : 0;
    const int bm = (side ? (blockIdx.x - args.nblk0) : blockIdx.x) * 64;

    const __nv_bfloat16* __restrict__ Ahi = args.Ahi[side];
    const __nv_bfloat16* __restrict__ Alo = args.Alo[side];
    const __nv_bfloat16* __restrict__ Whi = args.Whi[side];
    const __nv_bfloat16* __restrict__ Wlo = args.Wlo[side];
    const float* __restrict__ bias = args.bias[side];
    const float* __restrict__ resid_f32 = args.resid_f32[side];
    const __nv_bfloat16* __restrict__ rhi = args.rhi[side];
    const __nv_bfloat16* __restrict__ rlo = args.rlo[side];
    const float* __restrict__ gamma = args.gamma[side];
    const float* __restrict__ beta = args.beta[side];

    extern __shared__ char smem[];
    const uint32_t sb = smem_u32(smem);
    float* stat_sum = (float*)(smem + STATS);
    float* stat_sq  = (float*)(smem + STATS + 1024);

    const int tid = threadIdx.x;
    const int wid = tid >> 5;
    const int lane = tid & 31;
    const int wm = (wid >> 2) * 32;
    const int wn = (wid & 3) * 64;
    const int nw = wid & 3;

    const int rofs = ((lane >> 3) & 1) * 8 + (lane & 7);
    const int kofs = ((lane >> 4) & 1) * 16;

    float acc[2][8][4];
    #pragma unroll
    for (int i = 0; i < 2; i++)
        #pragma unroll
        for (int j = 0; j < 8; j++)
            #pragma unroll
            for (int c = 0; c < 4; c++) acc[i][j][c] = 0.f;

    auto load_stage = [&](int stage, int k0) {
        const uint32_t base = sb + stage * STAGE;
        if (PATH == 0) {
            #pragma unroll
            for (int i = 0; i < 10; i++) {
                int idx = tid + i * 256;
                uint32_t dst;
                const __nv_bfloat16* src;
                if (idx < 512) {
                    int r = idx >> 3, f = idx & 7;
                    dst = base + SMEM_SWIZZLE_128B((uint32_t)(r * 128 + f * 16));
                    src = Ahi + (size_t)(bm + r) * DMODEL + k0 + f * 8;
                } else {
                    int j = idx - 512;
                    int r = j >> 3, f = j & 7;
                    dst = base + BHI + SMEM_SWIZZLE_128B((uint32_t)(r * 128 + f * 16));
                    src = Whi + (size_t)r * DMODEL + k0 + f * 8;
                }
                cpa16(dst, src);
            }
        } else {
            #pragma unroll
            for (int i = 0; i < 20; i++) {
                int idx = tid + i * 256;
                uint32_t dst;
                const __nv_bfloat16* src;
                if (idx < 512) {
                    int r = idx >> 3, f = idx & 7;
                    dst = base + SMEM_SWIZZLE_128B((uint32_t)(r * 128 + f * 16));
                    src = Ahi + (size_t)(bm + r) * DMODEL + k0 + f * 8;
                } else if (idx < 1024) {
                    int j = idx - 512;
                    int r = j >> 3, f = j & 7;
                    dst = base + A_B + SMEM_SWIZZLE_128B((uint32_t)(r * 128 + f * 16));
                    src = Alo + (size_t)(bm + r) * DMODEL + k0 + f * 8;
                } else if (idx < 3072) {
                    int j = idx - 1024;
                    int r = j >> 3, f = j & 7;
                    dst = base + BHI + SMEM_SWIZZLE_128B((uint32_t)(r * 128 + f * 16));
                    src = Whi + (size_t)r * DMODEL + k0 + f * 8;
                } else {
                    int j = idx - 3072;
                    int r = j >> 3, f = j & 7;
                    dst = base + BHI + 32768 + SMEM_SWIZZLE_128B((uint32_t)(r * 128 + f * 16));
                    src = Wlo + (size_t)r * DMODEL + k0 + f * 8;
                }
                cpa16(dst, src);
            }
        }
    };

    load_stage(0, 0);
    CP_COMMIT();

    for (int kc = 0; kc < 4; kc++) {
        const int s = kc & 1;
        if (kc + 1 < 4) {
            load_stage(s ^ 1, (kc + 1) * 64);
            CP_COMMIT();
            CP_WAIT1();
        } else {
            CP_WAIT0();
        }
        __syncthreads();

        const uint32_t sAhi = sb + s * STAGE;
        const uint32_t sAlo = sAhi + A_B;
        const uint32_t sBhi = sAhi + BHI;
        const uint32_t sBlo = sBhi + 32768;

        #pragma unroll
        for (int ks = 0; ks < 4; ks++) {
            const int kb = ks * 32 + kofs;
            uint32_t ah[2][4], al[2][4], bh[8][2], bl[8][2];
            #pragma unroll
            for (int mt = 0; mt < 2; mt++) {
                int row = wm + mt * 16 + rofs;
                uint32_t so = SMEM_SWIZZLE_128B((uint32_t)(row * 128 + kb));
                ldsm_x4(ah[mt], sAhi + so);
                if (PATH == 1) ldsm_x4(al[mt], sAlo + so);
            }
            #pragma unroll
            for (int p = 0; p < 4; p++) {
                int row = wn + p * 16 + rofs;
                uint32_t so = SMEM_SWIZZLE_128B((uint32_t)(row * 128 + kb));
                uint32_t t[4];
                ldsm_x4(t, sBhi + so);
                bh[2 * p][0] = t[0]; bh[2 * p][1] = t[2];
                bh[2 * p + 1][0] = t[1]; bh[2 * p + 1][1] = t[3];
                if (PATH == 1) {
                    ldsm_x4(t, sBlo + so);
                    bl[2 * p][0] = t[0]; bl[2 * p][1] = t[2];
                    bl[2 * p + 1][0] = t[1]; bl[2 * p + 1][1] = t[3];
                }
            }
            #pragma unroll
            for (int mt = 0; mt < 2; mt++)
                #pragma unroll
                for (int nt = 0; nt < 8; nt++)
                    mma16816(acc[mt][nt], ah[mt], bh[nt]);
            if (PATH == 1) {
                #pragma unroll
                for (int mt = 0; mt < 2; mt++)
                    #pragma unroll
                    for (int nt = 0; nt < 8; nt++)
                        mma16816(acc[mt][nt], ah[mt], bl[nt]);
                #pragma unroll
                for (int mt = 0; mt < 2; mt++)
                    #pragma unroll
                    for (int nt = 0; nt < 8; nt++)
                        mma16816(acc[mt][nt], al[mt], bh[nt]);
            }
        }
        __syncthreads();
    }

    // ---- epilogue ----
    const int lr = lane >> 2;
    const int lc = (lane & 3) * 2;
    float rsum[2][2] = {}, rsq[2][2] = {};

    #pragma unroll
    for (int mt = 0; mt < 2; mt++) {
        #pragma unroll
        for (int nt = 0; nt < 8; nt++) {
            int c = wn + nt * 8 + lc;
            int gr0 = bm + wm + mt * 16 + lr;
            float v0 = acc[mt][nt][0], v1 = acc[mt][nt][1];
            float v2 = acc[mt][nt][2], v3 = acc[mt][nt][3];
            if (PATH == 1) {
                float b0 = bias[c], b1 = bias[c + 1];
                v0 += b0; v1 += b1; v2 += b0; v3 += b1;
                v0 = v0 / (1.0f + __expf(-v0));
                v1 = v1 / (1.0f + __expf(-v1));
                v2 = v2 / (1.0f + __expf(-v2));
                v3 = v3 / (1.0f + __expf(-v3));
                uint32_t rh0 = *(const uint32_t*)&rhi[(size_t)gr0 * DMODEL + c];
                uint32_t rl0 = *(const uint32_t*)&rlo[(size_t)gr0 * DMODEL + c];
                uint32_t rh1 = *(const uint32_t*)&rhi[(size_t)(gr0 + 8) * DMODEL + c];
                uint32_t rl1 = *(const uint32_t*)&rlo[(size_t)(gr0 + 8) * DMODEL + c];
                __nv_bfloat162 H0 = *(__nv_bfloat162*)&rh0, L0 = *(__nv_bfloat162*)&rl0;
                __nv_bfloat162 H1 = *(__nv_bfloat162*)&rh1, L1 = *(__nv_bfloat162*)&rl1;
                v0 += __bfloat162float(H0.x) + __bfloat162float(L0.x);
                v1 += __bfloat162float(H0.y) + __bfloat162float(L0.y);
                v2 += __bfloat162float(H1.x) + __bfloat162float(L1.x);
                v3 += __bfloat162float(H1.y) + __bfloat162float(L1.y);
            } else {
                float2 rA = *(const float2*)&resid_f32[(size_t)gr0 * DMODEL + c];
                float2 rB = *(const float2*)&resid_f32[(size_t)(gr0 + 8) * DMODEL + c];
                v0 += rA.x; v1 += rA.y; v2 += rB.x; v3 += rB.y;
            }
            acc[mt][nt][0] = v0; acc[mt][nt][1] = v1;
            acc[mt][nt][2] = v2; acc[mt][nt][3] = v3;
            rsum[mt][0] += v0 + v1; rsq[mt][0] += v0 * v0 + v1 * v1;
            rsum[mt][1] += v2 + v3; rsq[mt][1] += v2 * v2 + v3 * v3;
        }
    }

    #pragma unroll
    for (int mt = 0; mt < 2; mt++)
        #pragma unroll
        for (int hf = 0; hf < 2; hf++) {
            rsum[mt][hf] += __shfl_xor_sync(0xffffffffu, rsum[mt][hf], 1);
            rsum[mt][hf] += __shfl_xor_sync(0xffffffffu, rsum[mt][hf], 2);
            rsq[mt][hf]  += __shfl_xor_sync(0xffffffffu, rsq[mt][hf], 1);
            rsq[mt][hf]  += __shfl_xor_sync(0xffffffffu, rsq[mt][hf], 2);
        }
    if ((lane & 3) == 0) {
        #pragma unroll
        for (int mt = 0; mt < 2; mt++)
            #pragma unroll
            for (int hf = 0; hf < 2; hf++) {
                int row = wm + mt * 16 + lr + hf * 8;
                stat_sum[row * 4 + nw] = rsum[mt][hf];
                stat_sq[row * 4 + nw]  = rsq[mt][hf];
            }
    }
    __syncthreads();

    float mean[2][2], rstd[2][2];
    #pragma unroll
    for (int mt = 0; mt < 2; mt++)
        #pragma unroll
        for (int hf = 0; hf < 2; hf++) {
            int row = wm + mt * 16 + lr + hf * 8;
            float ts = stat_sum[row * 4 + 0] + stat_sum[row * 4 + 1]
                     + stat_sum[row * 4 + 2] + stat_sum[row * 4 + 3];
            float tq = stat_sq[row * 4 + 0] + stat_sq[row * 4 + 1]
                     + stat_sq[row * 4 + 2] + stat_sq[row * 4 + 3];
            float mu = ts * (1.0f / DMODEL);
            float var = tq * (1.0f / DMODEL) - mu * mu;
            mean[mt][hf] = mu;
            rstd[mt][hf] = rsqrtf(var + 1e-5f);
        }

    #pragma unroll
    for (int mt = 0; mt < 2; mt++) {
        #pragma unroll
        for (int nt = 0; nt < 8; nt++) {
            int c = wn + nt * 8 + lc;
            int gr0 = bm + wm + mt * 16 + lr;
            float g0 = gamma[c], g1 = gamma[c + 1];
            float b0 = beta[c],  b1 = beta[c + 1];
            float o0 = (acc[mt][nt][0] - mean[mt][0]) * rstd[mt][0] * g0 + b0;
            float o1 = (acc[mt][nt][1] - mean[mt][0]) * rstd[mt][0] * g1 + b1;
            float o2 = (acc[mt][nt][2] - mean[mt][1]) * rstd[mt][1] * g0 + b0;
            float o3 = (acc[mt][nt][3] - mean[mt][1]) * rstd[mt][1] * g1 + b1;
            if (PATH == 0) {
                __nv_bfloat16* __restrict__ ohi = args.ohi[side];
                __nv_bfloat16* __restrict__ olo = args.olo[side];
                uint32_t l0, l1;
                uint32_t h0 = pack_split(o0, o1, l0);
                uint32_t h1 = pack_split(o2, o3, l1);
                *(uint32_t*)&ohi[(size_t)gr0 * DMODEL + c]       = h0;
                *(uint32_t*)&olo[(size_t)gr0 * DMODEL + c]       = l0;
                *(uint32_t*)&ohi[(size_t)(gr0 + 8) * DMODEL + c] = h1;
                *(uint32_t*)&olo[(size_t)(gr0 + 8) * DMODEL + c] = l1;
            } else {
                float* __restrict__ out_f32 = args.out_f32[side];
                *(float2*)&out_f32[(size_t)gr0 * DMODEL + c]       = make_float2(o0, o1);
                *(float2*)&out_f32[(size_t)(gr0 + 8) * DMODEL + c] = make_float2(o2, o3);
            }
        }
    }
}

#define SMEM_GLN0 (2 * (8192 + 32768) + 2048)            // 83968
#define SMEM_GLN1 (2 * (2 * 8192 + 2 * 32768) + 2048)    // 165888

// ---------------- HMMA flash attention (x+y combined, 1-term bf16) ----------------
// CTA: 128 queries per (b,h,side), 8 warps x 16 rows. K/V tiles 64 keys, double-buffered.
// smem: Q 0..16K; stage s at 16K + s*16K (K +0, V +8K); lg at 48K + s*256. 2 CTAs/SM.
#define ATT_SMEM (49152 + 512)

__device__ __forceinline__ void att_load_kv(
    uint32_t sb, int stage, int kt, int b, int h, int Tk,
    const __nv_bfloat16* kh, const __nv_bfloat16* vh,
    const float* lg, int tid)
{
    const __nv_bfloat16* srcs[2] = {kh, vh};
    uint32_t base = sb + 16384 + stage * 16384;
    #pragma unroll
    for (int i = 0; i < 4; i++) {
        int idx = tid + i * 256;
        int arr = idx >> 9;
        int rem = idx & 511;
        int r = rem >> 3, f = rem & 7;
        uint32_t dst = base + arr * 8192 + SMEM_SWIZZLE_128B((uint32_t)(r * 128 + f * 16));
        cpa16(dst, srcs[arr] + ((size_t)(b * Tk + kt * 64 + r) * DMODEL + h * DK) + f * 8);
    }
    if (tid < 16)
        cpa16(sb + 49152 + stage * 256 + tid * 16, lg + b * Tk + kt * 64 + tid * 4);
}

__global__ __launch_bounds__(256, 2) void mma_attn(
    const __nv_bfloat16* __restrict__ qx, const __nv_bfloat16* __restrict__ kyv,
    const __nv_bfloat16* __restrict__ vyv, const float* __restrict__ lgy_,
    __nv_bfloat16* __restrict__ ax,
    const __nv_bfloat16* __restrict__ qy, const __nv_bfloat16* __restrict__ kxv,
    const __nv_bfloat16* __restrict__ vxv, const float* __restrict__ lgx_,
    __nv_bfloat16* __restrict__ ay)
{
    const int z = blockIdx.z;
    const __nv_bfloat16 *qhi, *khi, *vhi;
    const float* lgk;
    __nv_bfloat16* ohi;
    int Tq, Tk, b;
    if (z < BATCH) {
        if (blockIdx.x >= NX / 128) return;
        b = z; qhi = qx; khi = kyv; vhi = vyv; lgk = lgy_; ohi = ax; Tq = NX; Tk = NY;
    } else {
        b = z - BATCH; qhi = qy; khi = kxv; vhi = vxv; lgk = lgx_; ohi = ay; Tq = NY; Tk = NX;
    }

    extern __shared__ char smem[];
    const uint32_t sb = smem_u32(smem);
    const int tid = threadIdx.x;
    const int wid = tid >> 5;
    const int lane = tid & 31;
    const int h = blockIdx.y;
    const int bq = blockIdx.x * 128;
    const int wm = wid * 16;
    const int rofs = ((lane >> 3) & 1) * 8 + (lane & 7);
    const int kofs = ((lane >> 4) & 1) * 16;

    #pragma unroll
    for (int i = 0; i < 4; i++) {
        int idx = tid + i * 256;
        int r = idx >> 3, f = idx & 7;
        uint32_t so = SMEM_SWIZZLE_128B((uint32_t)(r * 128 + f * 16));
        size_t g = (size_t)(b * Tq + bq + r) * DMODEL + h * DK;
        *(uint4*)(smem + so) = ((const uint4*)(qhi + g))[f];
    }
    att_load_kv(sb, 0, 0, b, h, Tk, khi, vhi, lgk, tid);
    CP_COMMIT();
    __syncthreads();

    uint32_t qfh[4][4];
    #pragma unroll
    for (int ks = 0; ks < 4; ks++)
        ldsm_x4(qfh[ks], sb + SMEM_SWIZZLE_128B((uint32_t)((wm + rofs) * 128 + ks * 32 + kofs)));

    float o[8][4];
    #pragma unroll
    for (int t = 0; t < 8; t++)
        #pragma unroll
        for (int c = 0; c < 4; c++) o[t][c] = 0.f;
    float m0 = -INFINITY, m1 = -INFINITY, l0 = 0.f, l1 = 0.f;

    const int ntile = Tk / 64;
    for (int kt = 0; kt < ntile; kt++) {
        const int s = kt & 1;
        CP_WAIT0();
        __syncthreads();
        if (kt + 1 < ntile) {
            att_load_kv(sb, s ^ 1, kt + 1, b, h, Tk, khi, vhi, lgk, tid);
            CP_COMMIT();
        }
        const uint32_t sK = sb + 16384 + s * 16384;
        const uint32_t sV = sK + 8192;
        const float* lgs = (const float*)(smem + 49152 + s * 256);

        float sd[8][4];
        #pragma unroll
        for (int nt = 0; nt < 8; nt++)
            #pragma unroll
            for (int c = 0; c < 4; c++) sd[nt][c] = 0.f;

        #pragma unroll
        for (int ks = 0; ks < 4; ks++) {
            uint32_t bh[8][2];
            #pragma unroll
            for (int p = 0; p < 4; p++) {
                uint32_t t[4];
                ldsm_x4(t, sK + SMEM_SWIZZLE_128B((uint32_t)((p * 16 + rofs) * 128 + ks * 32 + kofs)));
                bh[2 * p][0] = t[0]; bh[2 * p][1] = t[2];
                bh[2 * p + 1][0] = t[1]; bh[2 * p + 1][1] = t[3];
            }
            #pragma unroll
            for (int nt = 0; nt < 8; nt++)
                mma16816(sd[nt], qfh[ks], bh[nt]);
        }

        float mt0 = m0, mt1 = m1;
        #pragma unroll
        for (int nt = 0; nt < 8; nt++) {
            int col = nt * 8 + (lane & 3) * 2;
            float lg0 = lgs[col], lg1 = lgs[col + 1];
            sd[nt][0] += lg0; sd[nt][1] += lg1;
            sd[nt][2] += lg0; sd[nt][3] += lg1;
            mt0 = fmaxf(mt0, fmaxf(sd[nt][0], sd[nt][1]));
            mt1 = fmaxf(mt1, fmaxf(sd[nt][2], sd[nt][3]));
        }
        mt0 = fmaxf(mt0, __shfl_xor_sync(0xffffffffu, mt0, 1));
        mt0 = fmaxf(mt0, __shfl_xor_sync(0xffffffffu, mt0, 2));
        mt1 = fmaxf(mt1, __shfl_xor_sync(0xffffffffu, mt1, 1));
        mt1 = fmaxf(mt1, __shfl_xor_sync(0xffffffffu, mt1, 2));
        float c0 = __expf(m0 - mt0);
        float c1 = __expf(m1 - mt1);
        m0 = mt0; m1 = mt1;
        l0 *= c0; l1 *= c1;
        #pragma unroll
        for (int t = 0; t < 8; t++) {
            o[t][0] *= c0; o[t][1] *= c0; o[t][2] *= c1; o[t][3] *= c1;
        }
        #pragma unroll
        for (int nt = 0; nt < 8; nt++) {
            sd[nt][0] = __expf(sd[nt][0] - m0);
            sd[nt][1] = __expf(sd[nt][1] - m0);
            sd[nt][2] = __expf(sd[nt][2] - m1);
            sd[nt][3] = __expf(sd[nt][3] - m1);
            l0 += sd[nt][0] + sd[nt][1];
            l1 += sd[nt][2] + sd[nt][3];
        }

        #pragma unroll
        for (int kb = 0; kb < 4; kb++) {
            uint32_t pah[4];
            pah[0] = pack2(sd[2 * kb][0],     sd[2 * kb][1]);
            pah[1] = pack2(sd[2 * kb][2],     sd[2 * kb][3]);
            pah[2] = pack2(sd[2 * kb + 1][0], sd[2 * kb + 1][1]);
            pah[3] = pack2(sd[2 * kb + 1][2], sd[2 * kb + 1][3]);
            const int t4 = lane >> 3;
            #pragma unroll
            for (int dp = 0; dp < 4; dp++) {
                uint32_t so = SMEM_SWIZZLE_128B((uint32_t)(
                    (kb * 16 + (t4 & 1) * 8 + (lane & 7)) * 128 +
                    (dp * 16 + (t4 >> 1) * 8) * 2));
                uint32_t vh4[4];
                ldsm_x4_t(vh4, sV + so);
                uint32_t b0h[2] = {vh4[0], vh4[1]}, b1h[2] = {vh4[2], vh4[3]};
                mma16816(o[2 * dp],     pah, b0h);
                mma16816(o[2 * dp + 1], pah, b1h);
            }
        }
    }

    float fl0 = l0 + __shfl_xor_sync(0xffffffffu, l0, 1);
    fl0 += __shfl_xor_sync(0xffffffffu, fl0, 2);
    float fl1 = l1 + __shfl_xor_sync(0xffffffffu, l1, 1);
    fl1 += __shfl_xor_sync(0xffffffffu, fl1, 2);
    float inv0 = 1.0f / fl0, inv1 = 1.0f / fl1;

    const int r0 = bq + wm + (lane >> 2);
    size_t base0 = (size_t)(b * Tq + r0) * DMODEL + h * DK;
    size_t base1 = base0 + (size_t)8 * DMODEL;
    #pragma unroll
    for (int t = 0; t < 8; t++) {
        int col = t * 8 + (lane & 3) * 2;
        *(uint32_t*)&ohi[base0 + col] = pack2(o[t][0] * inv0, o[t][1] * inv0);
        *(uint32_t*)&ohi[base1 + col] = pack2(o[t][2] * inv1, o[t][3] * inv1);
    }
}

// ---------------- launch ----------------
extern "C" void kernel_launch(void* const* d_in, const int* in_sizes, int n_in,
                              void* d_out, int out_size)
{
    const float* x    = (const float*)d_in[0];
    const float* y    = (const float*)d_in[1];
    const float* Wqx  = (const float*)d_in[4];
    const float* Wkx  = (const float*)d_in[5];
    const float* Wvx  = (const float*)d_in[6];
    const float* Wqy  = (const float*)d_in[7];
    const float* Wky  = (const float*)d_in[8];
    const float* Wvy  = (const float*)d_in[9];
    const float* gWx  = (const float*)d_in[10];
    const float* gbx  = (const float*)d_in[11];
    const float* gWy  = (const float*)d_in[12];
    const float* gby  = (const float*)d_in[13];
    const float* Wox  = (const float*)d_in[14];
    const float* Woy  = (const float*)d_in[15];
    const float* lnxg = (const float*)d_in[16];
    const float* lnxb = (const float*)d_in[17];
    const float* lnyg = (const float*)d_in[18];
    const float* lnyb = (const float*)d_in[19];
    const float* ffxW = (const float*)d_in[20];
    const float* ffxb = (const float*)d_in[21];
    const float* ffyW = (const float*)d_in[22];
    const float* ffyb = (const float*)d_in[23];
    float* out = (float*)d_out;

    float *lgx, *lgy;
    __nv_bfloat16 *xhi, *yhi;
    __nv_bfloat16 *qxhi, *kxhi, *vxhi, *qyhi, *kyhi, *vyhi;
    __nv_bfloat16 *axhi, *ayhi;
    __nv_bfloat16 *x2ahi, *x2alo, *y2ahi, *y2alo, *whi, *wlo;
    cudaGetSymbolAddress((void**)&lgx, g_lgx);
    cudaGetSymbolAddress((void**)&lgy, g_lgy);
    cudaGetSymbolAddress((void**)&xhi, g_xhi);
    cudaGetSymbolAddress((void**)&yhi, g_yhi);
    cudaGetSymbolAddress((void**)&qxhi, g_qxhi);
    cudaGetSymbolAddress((void**)&kxhi, g_kxhi);
    cudaGetSymbolAddress((void**)&vxhi, g_vxhi);
    cudaGetSymbolAddress((void**)&qyhi, g_qyhi);
    cudaGetSymbolAddress((void**)&kyhi, g_kyhi);
    cudaGetSymbolAddress((void**)&vyhi, g_vyhi);
    cudaGetSymbolAddress((void**)&axhi, g_axhi);
    cudaGetSymbolAddress((void**)&ayhi, g_ayhi);
    cudaGetSymbolAddress((void**)&x2ahi, g_x2ahi);
    cudaGetSymbolAddress((void**)&x2alo, g_x2alo);
    cudaGetSymbolAddress((void**)&y2ahi, g_y2ahi);
    cudaGetSymbolAddress((void**)&y2alo, g_y2alo);
    cudaGetSymbolAddress((void**)&whi, g_whi);
    cudaGetSymbolAddress((void**)&wlo, g_wlo);

    cudaFuncSetAttribute(mma_gemm, cudaFuncAttributeMaxDynamicSharedMemorySize, SMEM_GEMM_DYN);
    cudaFuncSetAttribute((gemm_ln<0, 2>), cudaFuncAttributeMaxDynamicSharedMemorySize, SMEM_GLN0);
    cudaFuncSetAttribute((gemm_ln<1, 1>), cudaFuncAttributeMaxDynamicSharedMemorySize, SMEM_GLN1);
    cudaFuncSetAttribute(mma_attn, cudaFuncAttributeMaxDynamicSharedMemorySize, ATT_SMEM);

    const int WSZ = DMODEL * DMODEL;  // 65536
    const float QSCL = 0.125f;        // 1/sqrt(64)

    // 1) fused split(hi) + gate (x and y in one launch); weight split
    split_gate2<<<(MX + MY) / 8, 256>>>(x, y, xhi, yhi, gWx, gbx, gWy, gby,
                                        out + OFF_GX, lgx, out + OFF_GY, lgy);
    WSrc ws;
    ws.s[0] = Wqx; ws.s[1] = Wkx; ws.s[2] = Wvx;
    ws.s[3] = Wqy; ws.s[4] = Wky; ws.s[5] = Wvy;
    ws.s[6] = Wox; ws.s[7] = Woy; ws.s[8] = ffxW; ws.s[9] = ffyW;
    wsplit_kernel<<<dim3(WSZ / 4 / 256, 10), 256>>>(ws, whi, wlo);

    // 2) QKV projections (x+y combined, 1-term bf16; q pre-scaled)
    {
        GemmArgs6 a = {};
        a.Ax = xhi; a.Ay = yhi;
        a.Whi[0] = whi + 0 * WSZ; a.Chi[0] = qxhi; a.scl[0] = QSCL;
        a.Whi[1] = whi + 1 * WSZ; a.Chi[1] = kxhi; a.scl[1] = 1.f;
        a.Whi[2] = whi + 2 * WSZ; a.Chi[2] = vxhi; a.scl[2] = 1.f;
        a.Whi[3] = whi + 3 * WSZ; a.Chi[3] = qyhi; a.scl[3] = QSCL;
        a.Whi[4] = whi + 4 * WSZ; a.Chi[4] = kyhi; a.scl[4] = 1.f;
        a.Whi[5] = whi + 5 * WSZ; a.Chi[5] = vyhi; a.scl[5] = 1.f;
        mma_gemm<<<dim3(2, MY / 128, 6), 256, SMEM_GEMM_DYN>>>(a);
    }

    // 3) attention (x+y combined)
    mma_attn<<<dim3(NY / 128, NHEAD, 2 * BATCH), 256, ATT_SMEM>>>(
        qxhi, kyhi, vyhi, lgy, axhi,
        qyhi, kxhi, vxhi, lgx, ayhi);

    // 4) fused oproj(1-term) + residual + LN (x+y combined; emits splits)
    {
        LNArgs a = {};
        a.Ahi[0] = axhi;          a.Ahi[1] = ayhi;
        a.Whi[0] = whi + 6 * WSZ; a.Whi[1] = whi + 7 * WSZ;
        a.resid_f32[0] = x;       a.resid_f32[1] = y;
        a.gamma[0] = lnxg;        a.gamma[1] = lnyg;
        a.beta[0] = lnxb;         a.beta[1] = lnyb;
        a.ohi[0] = x2ahi;         a.ohi[1] = y2ahi;
        a.olo[0] = x2alo;         a.olo[1] = y2alo;
        a.nblk0 = MX / 64;
        gemm_ln<0, 2><<<(MX + MY) / 64, 256, SMEM_GLN0>>>(a);
    }

    // 5) fused FF(3-term, silu) + residual + LN -> final output (x+y combined)
    {
        LNArgs a = {};
        a.Ahi[0] = x2ahi;         a.Ahi[1] = y2ahi;
        a.Alo[0] = x2alo;         a.Alo[1] = y2alo;
        a.Whi[0] = whi + 8 * WSZ; a.Whi[1] = whi + 9 * WSZ;
        a.Wlo[0] = wlo + 8 * WSZ; a.Wlo[1] = wlo + 9 * WSZ;
        a.bias[0] = ffxb;         a.bias[1] = ffyb;
        a.rhi[0] = x2ahi;         a.rhi[1] = y2ahi;
        a.rlo[0] = x2alo;         a.rlo[1] = y2alo;
        a.gamma[0] = lnxg;        a.gamma[1] = lnyg;
        a.beta[0] = lnxb;         a.beta[1] = lnyb;
        a.out_f32[0] = out + OFF_X2;
        a.out_f32[1] = out + OFF_Y2;
        a.nblk0 = MX / 64;
        gemm_ln<1, 1><<<(MX + MY) / 64, 256, SMEM_GLN1>>>(a);
    }
}

// round 9
// speedup vs baseline: 6.5551x; 1.1263x over previous
#include <cuda_runtime.h>
#include <cuda_bf16.h>
#include <math.h>
#include <stdint.h>

// ---------------- problem constants ----------------
#define BATCH 16
#define NX 512
#define NY 1024
#define DMODEL 256
#define NHEAD 4
#define DK 64
#define MX (BATCH * NX)   // 8192
#define MY (BATCH * NY)   // 16384

#define OFF_X2 0
#define OFF_Y2 (MX * DMODEL)
#define OFF_GX (OFF_Y2 + MY * DMODEL)
#define OFF_GY (OFF_GX + MX)

// ---------------- scratch ----------------
__device__ float g_lgx[MX];   // log2(gate)
__device__ float g_lgy[MY];

__device__ __nv_bfloat16 g_xhi[MX * DMODEL];
__device__ __nv_bfloat16 g_yhi[MY * DMODEL];
__device__ __nv_bfloat16 g_qxhi[MX * DMODEL];
__device__ __nv_bfloat16 g_kxhi[MX * DMODEL];
__device__ __nv_bfloat16 g_vxhi[MX * DMODEL];
__device__ __nv_bfloat16 g_qyhi[MY * DMODEL];
__device__ __nv_bfloat16 g_kyhi[MY * DMODEL];
__device__ __nv_bfloat16 g_vyhi[MY * DMODEL];
__device__ __nv_bfloat16 g_axhi[MX * DMODEL];
__device__ __nv_bfloat16 g_ayhi[MY * DMODEL];
__device__ __nv_bfloat16 g_x2ahi[MX * DMODEL];
__device__ __nv_bfloat16 g_x2alo[MX * DMODEL];
__device__ __nv_bfloat16 g_y2ahi[MY * DMODEL];
__device__ __nv_bfloat16 g_y2alo[MY * DMODEL];
__device__ __nv_bfloat16 g_whi[10 * DMODEL * DMODEL];
__device__ __nv_bfloat16 g_wlo[10 * DMODEL * DMODEL];

// ---------------- helpers ----------------
__device__ __forceinline__ uint32_t smem_u32(const void* p) {
    uint32_t a;
    asm("{ .reg .u64 t; cvta.to.shared.u64 t, %1; cvt.u32.u64 %0, t; }"
        : "=r"(a) : "l"(p));
    return a;
}

#define SMEM_SWIZZLE_128B(off) ((off) ^ (((off) >> 3) & 0x70))

__device__ __forceinline__ void ldsm_x4(uint32_t* r, uint32_t addr) {
    asm volatile("ldmatrix.sync.aligned.m8n8.x4.shared.b16 {%0,%1,%2,%3}, [%4];"
                 : "=r"(r[0]), "=r"(r[1]), "=r"(r[2]), "=r"(r[3]) : "r"(addr));
}

__device__ __forceinline__ void ldsm_x4_t(uint32_t* r, uint32_t addr) {
    asm volatile("ldmatrix.sync.aligned.m8n8.x4.trans.shared.b16 {%0,%1,%2,%3}, [%4];"
                 : "=r"(r[0]), "=r"(r[1]), "=r"(r[2]), "=r"(r[3]) : "r"(addr));
}

__device__ __forceinline__ void mma16816(float* d, const uint32_t* a, const uint32_t* b) {
    asm volatile(
        "mma.sync.aligned.m16n8k16.row.col.f32.bf16.bf16.f32 "
        "{%0,%1,%2,%3}, {%4,%5,%6,%7}, {%8,%9}, {%0,%1,%2,%3};"
        : "+f"(d[0]), "+f"(d[1]), "+f"(d[2]), "+f"(d[3])
        : "r"(a[0]), "r"(a[1]), "r"(a[2]), "r"(a[3]), "r"(b[0]), "r"(b[1]));
}

__device__ __forceinline__ void cpa16(uint32_t dst, const void* src) {
    asm volatile("cp.async.cg.shared.global [%0], [%1], 16;" :: "r"(dst), "l"(src));
}
#define CP_COMMIT() asm volatile("cp.async.commit_group;" ::: "memory")
#define CP_WAIT0()  asm volatile("cp.async.wait_group 0;" ::: "memory")
#define CP_WAIT1()  asm volatile("cp.async.wait_group 1;" ::: "memory")

__device__ __forceinline__ float ex2f(float x) {
    float r;
    asm("ex2.approx.ftz.f32 %0, %1;" : "=f"(r) : "f"(x));
    return r;
}

// pack (a,b) -> bf16x2 (lo=a, hi=b), single cvt instruction
__device__ __forceinline__ uint32_t packbf(float a, float b) {
    uint32_t r;
    asm("cvt.rn.bf16x2.f32 %0, %1, %2;" : "=r"(r) : "f"(b), "f"(a));
    return r;
}

__device__ __forceinline__ uint32_t pack_split(float a, float b, uint32_t& lo) {
    __nv_bfloat16 ha = __float2bfloat16(a), hb = __float2bfloat16(b);
    __nv_bfloat16 la = __float2bfloat16(a - __bfloat162float(ha));
    __nv_bfloat16 lb = __float2bfloat16(b - __bfloat162float(hb));
    __nv_bfloat162 H(ha, hb), L(la, lb);
    lo = *(uint32_t*)&L;
    return *(uint32_t*)&H;
}

__device__ __forceinline__ float softplusf(float x) {
    return (x > 20.f) ? x : log1pf(expf(x));
}

// ---------------- fused split(hi) + evidential gate (x and y in one launch) ----------------
// Emits log2(g) for the base-2 attention softmax.
__global__ __launch_bounds__(256) void split_gate2(
    const float* __restrict__ x, const float* __restrict__ y,
    __nv_bfloat16* __restrict__ xhi, __nv_bfloat16* __restrict__ yhi,
    const float* __restrict__ gWx, const float* __restrict__ gbx,
    const float* __restrict__ gWy, const float* __restrict__ gby,
    float* __restrict__ gx_out, float* __restrict__ lgx,
    float* __restrict__ gy_out, float* __restrict__ lgy)
{
    const int wid = threadIdx.x >> 5;
    const int lane = threadIdx.x & 31;
    int token = blockIdx.x * 8 + wid;

    const float* src; __nv_bfloat16* hi; const float *gW, *gb;
    float *g_out, *lg_out;
    if (token < MX) {
        src = x; hi = xhi; gW = gWx; gb = gbx; g_out = gx_out; lg_out = lgx;
    } else {
        token -= MX;
        src = y; hi = yhi; gW = gWy; gb = gby; g_out = gy_out; lg_out = lgy;
    }

    const float4* row = (const float4*)(src + (size_t)token * DMODEL);
    float4 v0 = row[lane];
    float4 v1 = row[lane + 32];

    uint32_t* hp = (uint32_t*)(hi + (size_t)token * DMODEL);
    hp[2 * lane]          = packbf(v0.x, v0.y);
    hp[2 * lane + 1]      = packbf(v0.z, v0.w);
    hp[64 + 2 * lane]     = packbf(v1.x, v1.y);
    hp[64 + 2 * lane + 1] = packbf(v1.z, v1.w);

    float p[4];
    #pragma unroll
    for (int j = 0; j < 4; j++) {
        float4 w0 = ((const float4*)gW)[j * 64 + lane];
        float4 w1 = ((const float4*)gW)[j * 64 + 32 + lane];
        p[j] = v0.x * w0.x + v0.y * w0.y + v0.z * w0.z + v0.w * w0.w
             + v1.x * w1.x + v1.y * w1.y + v1.z * w1.z + v1.w * w1.w;
    }
    #pragma unroll
    for (int o = 16; o > 0; o >>= 1) {
        p[0] += __shfl_xor_sync(0xffffffffu, p[0], o);
        p[1] += __shfl_xor_sync(0xffffffffu, p[1], o);
        p[2] += __shfl_xor_sync(0xffffffffu, p[2], o);
        p[3] += __shfl_xor_sync(0xffffffffu, p[3], o);
    }
    if (lane == 0) {
        float mu    = p[0] + gb[0];
        float v     = softplusf(p[1] + gb[1]) + 1e-6f;
        float alpha = softplusf(p[2] + gb[2]) + 1.0f + 1e-6f;
        float beta  = softplusf(p[3] + gb[3]) + 1e-6f;
        float var_ep = beta / (v * (alpha - 1.0f));
        float g = (1.0f / (1.0f + expf(-mu))) * expf(-2.0f * var_ep);
        g = fmaxf(g, 1e-6f);
        g_out[token]  = g;
        lg_out[token] = log2f(g);
    }
}

// ---------------- weight split (hi for all; lo only for FF weights m>=8) ----------------
struct WSrc { const float* s[10]; };

__global__ __launch_bounds__(256) void wsplit_kernel(
    WSrc ws, __nv_bfloat16* __restrict__ hi, __nv_bfloat16* __restrict__ lo)
{
    int m = blockIdx.y;
    int i = blockIdx.x * 256 + threadIdx.x;
    float4 v = ((const float4*)ws.s[m])[i];
    size_t base = (size_t)m * DMODEL * DMODEL / 2 + 2 * i;
    if (m >= 8) {
        uint32_t l0, l1;
        uint32_t h0 = pack_split(v.x, v.y, l0);
        uint32_t h1 = pack_split(v.z, v.w, l1);
        ((uint32_t*)hi)[base]     = h0;
        ((uint32_t*)hi)[base + 1] = h1;
        ((uint32_t*)lo)[base]     = l0;
        ((uint32_t*)lo)[base + 1] = l1;
    } else {
        ((uint32_t*)hi)[base]     = packbf(v.x, v.y);
        ((uint32_t*)hi)[base + 1] = packbf(v.z, v.w);
    }
}

// ---------------- QKV HMMA GEMM (x+y combined, 1-term bf16, double-buffered) ----------------
#define QK_TILE_B 16384
#define QK_STAGE (2 * QK_TILE_B)        // 32KB
#define SMEM_GEMM_DYN (2 * QK_STAGE)    // 64KB

struct GemmArgs6 {
    const __nv_bfloat16* Ax;
    const __nv_bfloat16* Ay;
    const __nv_bfloat16* Whi[6];
    __nv_bfloat16* Chi[6];
    float scl[6];
};

__global__ __launch_bounds__(256, 2) void mma_gemm(GemmArgs6 args)
{
    const int z = blockIdx.z;
    const __nv_bfloat16* __restrict__ Ahi;
    if (z < 3) {
        if (blockIdx.y >= MX / 128) return;
        Ahi = args.Ax;
    } else {
        Ahi = args.Ay;
    }
    const __nv_bfloat16* __restrict__ Whi = args.Whi[z];

    extern __shared__ char smem[];
    const uint32_t sb = smem_u32(smem);

    const int tid = threadIdx.x;
    const int wid = tid >> 5;
    const int lane = tid & 31;
    const int bm = blockIdx.y * 128;
    const int bn = blockIdx.x * 128;
    const int wm = (wid & 1) * 64;
    const int wn = (wid >> 1) * 32;

    float acc[4][4][4];
    #pragma unroll
    for (int i = 0; i < 4; i++)
        #pragma unroll
        for (int j = 0; j < 4; j++)
            #pragma unroll
            for (int c = 0; c < 4; c++) acc[i][j][c] = 0.f;

    const int rofs = ((lane >> 3) & 1) * 8 + (lane & 7);
    const int kofs = ((lane >> 4) & 1) * 16;

    auto load_stage = [&](int stage, int k0) {
        const __nv_bfloat16* srcs[2] = {Ahi, Whi};
        const int rb[2] = {bm, bn};
        const uint32_t base = sb + stage * QK_STAGE;
        #pragma unroll
        for (int i = 0; i < 8; i++) {
            int idx = tid + i * 256;
            int arr = idx >> 10;
            int rem = idx & 1023;
            int r = rem >> 3, f = rem & 7;
            uint32_t dst = base + arr * QK_TILE_B + SMEM_SWIZZLE_128B((uint32_t)(r * 128 + f * 16));
            cpa16(dst, srcs[arr] + (size_t)(rb[arr] + r) * DMODEL + k0 + f * 8);
        }
    };

    load_stage(0, 0);
    CP_COMMIT();

    for (int kc = 0; kc < 4; kc++) {
        const int s = kc & 1;
        if (kc + 1 < 4) {
            load_stage(s ^ 1, (kc + 1) * 64);
            CP_COMMIT();
            CP_WAIT1();
        } else {
            CP_WAIT0();
        }
        __syncthreads();

        const uint32_t sA = sb + s * QK_STAGE;
        const uint32_t sB = sA + QK_TILE_B;

        #pragma unroll
        for (int ks = 0; ks < 4; ks++) {
            const int kb = ks * 32 + kofs;
            uint32_t ah[4][4], bh[4][2];
            #pragma unroll
            for (int mt = 0; mt < 4; mt++) {
                int row = wm + mt * 16 + rofs;
                ldsm_x4(ah[mt], sA + SMEM_SWIZZLE_128B((uint32_t)(row * 128 + kb)));
            }
            #pragma unroll
            for (int p = 0; p < 2; p++) {
                int row = wn + p * 16 + rofs;
                uint32_t t[4];
                ldsm_x4(t, sB + SMEM_SWIZZLE_128B((uint32_t)(row * 128 + kb)));
                bh[2 * p][0] = t[0]; bh[2 * p][1] = t[2];
                bh[2 * p + 1][0] = t[1]; bh[2 * p + 1][1] = t[3];
            }
            #pragma unroll
            for (int mt = 0; mt < 4; mt++)
                #pragma unroll
                for (int nt = 0; nt < 4; nt++)
                    mma16816(acc[mt][nt], ah[mt], bh[nt]);
        }
        __syncthreads();
    }

    const int rbase = bm + wm + (lane >> 2);
    const int cbase = bn + wn + (lane & 3) * 2;
    const float s = args.scl[z];
    __nv_bfloat16* __restrict__ Chi = args.Chi[z];
    #pragma unroll
    for (int mt = 0; mt < 4; mt++) {
        #pragma unroll
        for (int nt = 0; nt < 4; nt++) {
            int col = cbase + nt * 8;
            int r0 = rbase + mt * 16;
            *(uint32_t*)&Chi[(size_t)r0 * DMODEL + col] =
                packbf(acc[mt][nt][0] * s, acc[mt][nt][1] * s);
            *(uint32_t*)&Chi[(size_t)(r0 + 8) * DMODEL + col] =
                packbf(acc[mt][nt][2] * s, acc[mt][nt][3] * s);
        }
    }
}

// ---------------- fused GEMM + residual + LayerNorm (x+y combined) ----------------
// PATH 0 (oproj): 1-term; double-buffered; resid fp32; emit splits. 2 CTAs/SM.
// PATH 1 (FF): 3-term; single-buffered (2 CTAs/SM overlap across CTAs);
//              bias+silu; resid hi+lo; fp32 out.
struct LNArgs {
    const __nv_bfloat16* Ahi[2];
    const __nv_bfloat16* Alo[2];
    const __nv_bfloat16* Whi[2];
    const __nv_bfloat16* Wlo[2];
    const float* bias[2];
    const float* resid_f32[2];
    const __nv_bfloat16* rhi[2];
    const __nv_bfloat16* rlo[2];
    const float* gamma[2];
    const float* beta[2];
    float* out_f32[2];
    __nv_bfloat16* ohi[2];
    __nv_bfloat16* olo[2];
    int nblk0;   // MX/64
};

template <int PATH>
__global__ __launch_bounds__(256, 2) void gemm_ln(LNArgs args)
{
    constexpr int A_B   = 8192;
    constexpr int STAGE = (PATH == 0) ? (A_B + 32768) : (2 * A_B + 2 * 32768);
    constexpr int BHI   = (PATH == 0) ? A_B : 2 * A_B;
    constexpr int NST   = (PATH == 0) ? 2 : 1;
    constexpr int STATS = NST * STAGE;

    const int side = (blockIdx.x >= args.nblk0) ? 1 : 0;
    const int bm = (side ? (blockIdx.x - args.nblk0) : blockIdx.x) * 64;

    const __nv_bfloat16* __restrict__ Ahi = args.Ahi[side];
    const __nv_bfloat16* __restrict__ Alo = args.Alo[side];
    const __nv_bfloat16* __restrict__ Whi = args.Whi[side];
    const __nv_bfloat16* __restrict__ Wlo = args.Wlo[side];
    const float* __restrict__ bias = args.bias[side];
    const float* __restrict__ resid_f32 = args.resid_f32[side];
    const __nv_bfloat16* __restrict__ rhi = args.rhi[side];
    const __nv_bfloat16* __restrict__ rlo = args.rlo[side];
    const float* __restrict__ gamma = args.gamma[side];
    const float* __restrict__ beta = args.beta[side];

    extern __shared__ char smem[];
    const uint32_t sb = smem_u32(smem);
    float* stat_sum = (float*)(smem + STATS);
    float* stat_sq  = (float*)(smem + STATS + 1024);

    const int tid = threadIdx.x;
    const int wid = tid >> 5;
    const int lane = tid & 31;
    const int wm = (wid >> 2) * 32;
    const int wn = (wid & 3) * 64;
    const int nw = wid & 3;

    const int rofs = ((lane >> 3) & 1) * 8 + (lane & 7);
    const int kofs = ((lane >> 4) & 1) * 16;

    float acc[2][8][4];
    #pragma unroll
    for (int i = 0; i < 2; i++)
        #pragma unroll
        for (int j = 0; j < 8; j++)
            #pragma unroll
            for (int c = 0; c < 4; c++) acc[i][j][c] = 0.f;

    auto load_stage = [&](int stage, int k0) {
        const uint32_t base = sb + stage * STAGE;
        if (PATH == 0) {
            #pragma unroll
            for (int i = 0; i < 10; i++) {
                int idx = tid + i * 256;
                uint32_t dst;
                const __nv_bfloat16* src;
                if (idx < 512) {
                    int r = idx >> 3, f = idx & 7;
                    dst = base + SMEM_SWIZZLE_128B((uint32_t)(r * 128 + f * 16));
                    src = Ahi + (size_t)(bm + r) * DMODEL + k0 + f * 8;
                } else {
                    int j = idx - 512;
                    int r = j >> 3, f = j & 7;
                    dst = base + BHI + SMEM_SWIZZLE_128B((uint32_t)(r * 128 + f * 16));
                    src = Whi + (size_t)r * DMODEL + k0 + f * 8;
                }
                cpa16(dst, src);
            }
        } else {
            #pragma unroll
            for (int i = 0; i < 20; i++) {
                int idx = tid + i * 256;
                uint32_t dst;
                const __nv_bfloat16* src;
                if (idx < 512) {
                    int r = idx >> 3, f = idx & 7;
                    dst = base + SMEM_SWIZZLE_128B((uint32_t)(r * 128 + f * 16));
                    src = Ahi + (size_t)(bm + r) * DMODEL + k0 + f * 8;
                } else if (idx < 1024) {
                    int j = idx - 512;
                    int r = j >> 3, f = j & 7;
                    dst = base + A_B + SMEM_SWIZZLE_128B((uint32_t)(r * 128 + f * 16));
                    src = Alo + (size_t)(bm + r) * DMODEL + k0 + f * 8;
                } else if (idx < 3072) {
                    int j = idx - 1024;
                    int r = j >> 3, f = j & 7;
                    dst = base + BHI + SMEM_SWIZZLE_128B((uint32_t)(r * 128 + f * 16));
                    src = Whi + (size_t)r * DMODEL + k0 + f * 8;
                } else {
                    int j = idx - 3072;
                    int r = j >> 3, f = j & 7;
                    dst = base + BHI + 32768 + SMEM_SWIZZLE_128B((uint32_t)(r * 128 + f * 16));
                    src = Wlo + (size_t)r * DMODEL + k0 + f * 8;
                }
                cpa16(dst, src);
            }
        }
    };

    if (PATH == 0) {
        load_stage(0, 0);
        CP_COMMIT();
    }

    for (int kc = 0; kc < 4; kc++) {
        const int s = (PATH == 0) ? (kc & 1) : 0;
        if (PATH == 0) {
            if (kc + 1 < 4) {
                load_stage(s ^ 1, (kc + 1) * 64);
                CP_COMMIT();
                CP_WAIT1();
            } else {
                CP_WAIT0();
            }
            __syncthreads();
        } else {
            load_stage(0, kc * 64);
            CP_COMMIT();
            CP_WAIT0();
            __syncthreads();
        }

        const uint32_t sAhi = sb + s * STAGE;
        const uint32_t sAlo = sAhi + A_B;
        const uint32_t sBhi = sAhi + BHI;
        const uint32_t sBlo = sBhi + 32768;

        #pragma unroll
        for (int ks = 0; ks < 4; ks++) {
            const int kb = ks * 32 + kofs;
            uint32_t ah[2][4], al[2][4];
            #pragma unroll
            for (int mt = 0; mt < 2; mt++) {
                int row = wm + mt * 16 + rofs;
                uint32_t so = SMEM_SWIZZLE_128B((uint32_t)(row * 128 + kb));
                ldsm_x4(ah[mt], sAhi + so);
                if (PATH == 1) ldsm_x4(al[mt], sAlo + so);
            }
            // per-p fragment load + immediate MMA (keeps live B regs at 8)
            #pragma unroll
            for (int p = 0; p < 4; p++) {
                int row = wn + p * 16 + rofs;
                uint32_t so = SMEM_SWIZZLE_128B((uint32_t)(row * 128 + kb));
                uint32_t t[4];
                ldsm_x4(t, sBhi + so);
                uint32_t b0[2] = {t[0], t[2]};
                uint32_t b1[2] = {t[1], t[3]};
                #pragma unroll
                for (int mt = 0; mt < 2; mt++) {
                    mma16816(acc[mt][2 * p],     ah[mt], b0);
                    mma16816(acc[mt][2 * p + 1], ah[mt], b1);
                }
                if (PATH == 1) {
                    #pragma unroll
                    for (int mt = 0; mt < 2; mt++) {
                        mma16816(acc[mt][2 * p],     al[mt], b0);
                        mma16816(acc[mt][2 * p + 1], al[mt], b1);
                    }
                    ldsm_x4(t, sBlo + so);
                    uint32_t c0[2] = {t[0], t[2]};
                    uint32_t c1[2] = {t[1], t[3]};
                    #pragma unroll
                    for (int mt = 0; mt < 2; mt++) {
                        mma16816(acc[mt][2 * p],     ah[mt], c0);
                        mma16816(acc[mt][2 * p + 1], ah[mt], c1);
                    }
                }
            }
        }
        __syncthreads();
    }

    // ---- epilogue ----
    const int lr = lane >> 2;
    const int lc = (lane & 3) * 2;
    float rsum[2][2] = {}, rsq[2][2] = {};

    #pragma unroll
    for (int mt = 0; mt < 2; mt++) {
        #pragma unroll
        for (int nt = 0; nt < 8; nt++) {
            int c = wn + nt * 8 + lc;
            int gr0 = bm + wm + mt * 16 + lr;
            float v0 = acc[mt][nt][0], v1 = acc[mt][nt][1];
            float v2 = acc[mt][nt][2], v3 = acc[mt][nt][3];
            if (PATH == 1) {
                float b0 = bias[c], b1 = bias[c + 1];
                v0 += b0; v1 += b1; v2 += b0; v3 += b1;
                v0 = v0 / (1.0f + __expf(-v0));
                v1 = v1 / (1.0f + __expf(-v1));
                v2 = v2 / (1.0f + __expf(-v2));
                v3 = v3 / (1.0f + __expf(-v3));
                uint32_t rh0 = *(const uint32_t*)&rhi[(size_t)gr0 * DMODEL + c];
                uint32_t rl0 = *(const uint32_t*)&rlo[(size_t)gr0 * DMODEL + c];
                uint32_t rh1 = *(const uint32_t*)&rhi[(size_t)(gr0 + 8) * DMODEL + c];
                uint32_t rl1 = *(const uint32_t*)&rlo[(size_t)(gr0 + 8) * DMODEL + c];
                __nv_bfloat162 H0 = *(__nv_bfloat162*)&rh0, L0 = *(__nv_bfloat162*)&rl0;
                __nv_bfloat162 H1 = *(__nv_bfloat162*)&rh1, L1 = *(__nv_bfloat162*)&rl1;
                v0 += __bfloat162float(H0.x) + __bfloat162float(L0.x);
                v1 += __bfloat162float(H0.y) + __bfloat162float(L0.y);
                v2 += __bfloat162float(H1.x) + __bfloat162float(L1.x);
                v3 += __bfloat162float(H1.y) + __bfloat162float(L1.y);
            } else {
                float2 rA = *(const float2*)&resid_f32[(size_t)gr0 * DMODEL + c];
                float2 rB = *(const float2*)&resid_f32[(size_t)(gr0 + 8) * DMODEL + c];
                v0 += rA.x; v1 += rA.y; v2 += rB.x; v3 += rB.y;
            }
            acc[mt][nt][0] = v0; acc[mt][nt][1] = v1;
            acc[mt][nt][2] = v2; acc[mt][nt][3] = v3;
            rsum[mt][0] += v0 + v1; rsq[mt][0] += v0 * v0 + v1 * v1;
            rsum[mt][1] += v2 + v3; rsq[mt][1] += v2 * v2 + v3 * v3;
        }
    }

    #pragma unroll
    for (int mt = 0; mt < 2; mt++)
        #pragma unroll
        for (int hf = 0; hf < 2; hf++) {
            rsum[mt][hf] += __shfl_xor_sync(0xffffffffu, rsum[mt][hf], 1);
            rsum[mt][hf] += __shfl_xor_sync(0xffffffffu, rsum[mt][hf], 2);
            rsq[mt][hf]  += __shfl_xor_sync(0xffffffffu, rsq[mt][hf], 1);
            rsq[mt][hf]  += __shfl_xor_sync(0xffffffffu, rsq[mt][hf], 2);
        }
    if ((lane & 3) == 0) {
        #pragma unroll
        for (int mt = 0; mt < 2; mt++)
            #pragma unroll
            for (int hf = 0; hf < 2; hf++) {
                int row = wm + mt * 16 + lr + hf * 8;
                stat_sum[row * 4 + nw] = rsum[mt][hf];
                stat_sq[row * 4 + nw]  = rsq[mt][hf];
            }
    }
    __syncthreads();

    float mean[2][2], rstd[2][2];
    #pragma unroll
    for (int mt = 0; mt < 2; mt++)
        #pragma unroll
        for (int hf = 0; hf < 2; hf++) {
            int row = wm + mt * 16 + lr + hf * 8;
            float ts = stat_sum[row * 4 + 0] + stat_sum[row * 4 + 1]
                     + stat_sum[row * 4 + 2] + stat_sum[row * 4 + 3];
            float tq = stat_sq[row * 4 + 0] + stat_sq[row * 4 + 1]
                     + stat_sq[row * 4 + 2] + stat_sq[row * 4 + 3];
            float mu = ts * (1.0f / DMODEL);
            float var = tq * (1.0f / DMODEL) - mu * mu;
            mean[mt][hf] = mu;
            rstd[mt][hf] = rsqrtf(var + 1e-5f);
        }

    #pragma unroll
    for (int mt = 0; mt < 2; mt++) {
        #pragma unroll
        for (int nt = 0; nt < 8; nt++) {
            int c = wn + nt * 8 + lc;
            int gr0 = bm + wm + mt * 16 + lr;
            float g0 = gamma[c], g1 = gamma[c + 1];
            float b0 = beta[c],  b1 = beta[c + 1];
            float o0 = (acc[mt][nt][0] - mean[mt][0]) * rstd[mt][0] * g0 + b0;
            float o1 = (acc[mt][nt][1] - mean[mt][0]) * rstd[mt][0] * g1 + b1;
            float o2 = (acc[mt][nt][2] - mean[mt][1]) * rstd[mt][1] * g0 + b0;
            float o3 = (acc[mt][nt][3] - mean[mt][1]) * rstd[mt][1] * g1 + b1;
            if (PATH == 0) {
                __nv_bfloat16* __restrict__ ohi = args.ohi[side];
                __nv_bfloat16* __restrict__ olo = args.olo[side];
                uint32_t l0, l1;
                uint32_t h0 = pack_split(o0, o1, l0);
                uint32_t h1 = pack_split(o2, o3, l1);
                *(uint32_t*)&ohi[(size_t)gr0 * DMODEL + c]       = h0;
                *(uint32_t*)&olo[(size_t)gr0 * DMODEL + c]       = l0;
                *(uint32_t*)&ohi[(size_t)(gr0 + 8) * DMODEL + c] = h1;
                *(uint32_t*)&olo[(size_t)(gr0 + 8) * DMODEL + c] = l1;
            } else {
                float* __restrict__ out_f32 = args.out_f32[side];
                *(float2*)&out_f32[(size_t)gr0 * DMODEL + c]       = make_float2(o0, o1);
                *(float2*)&out_f32[(size_t)(gr0 + 8) * DMODEL + c] = make_float2(o2, o3);
            }
        }
    }
}

#define SMEM_GLN0 (2 * (8192 + 32768) + 2048)        // 83968
#define SMEM_GLN1 ((2 * 8192 + 2 * 32768) + 2048)    // 83968 (single-buffered)

// ---------------- HMMA flash attention (x+y combined, 1-term bf16, base-2) ----------------
// Scores bounded (|qk*scl| small, lg<=0): no max-stabilization needed.
// q pre-scaled by 0.125*log2(e); lg = log2(gate). p = exp2(s).
#define ATT_SMEM (49152 + 512)

__device__ __forceinline__ void att_load_kv(
    uint32_t sb, int stage, int kt, int b, int h, int Tk,
    const __nv_bfloat16* kh, const __nv_bfloat16* vh,
    const float* lg, int tid)
{
    const __nv_bfloat16* srcs[2] = {kh, vh};
    uint32_t base = sb + 16384 + stage * 16384;
    #pragma unroll
    for (int i = 0; i < 4; i++) {
        int idx = tid + i * 256;
        int arr = idx >> 9;
        int rem = idx & 511;
        int r = rem >> 3, f = rem & 7;
        uint32_t dst = base + arr * 8192 + SMEM_SWIZZLE_128B((uint32_t)(r * 128 + f * 16));
        cpa16(dst, srcs[arr] + ((size_t)(b * Tk + kt * 64 + r) * DMODEL + h * DK) + f * 8);
    }
    if (tid < 16)
        cpa16(sb + 49152 + stage * 256 + tid * 16, lg + b * Tk + kt * 64 + tid * 4);
}

__global__ __launch_bounds__(256, 2) void mma_attn(
    const __nv_bfloat16* __restrict__ qx, const __nv_bfloat16* __restrict__ kyv,
    const __nv_bfloat16* __restrict__ vyv, const float* __restrict__ lgy_,
    __nv_bfloat16* __restrict__ ax,
    const __nv_bfloat16* __restrict__ qy, const __nv_bfloat16* __restrict__ kxv,
    const __nv_bfloat16* __restrict__ vxv, const float* __restrict__ lgx_,
    __nv_bfloat16* __restrict__ ay)
{
    const int z = blockIdx.z;
    const __nv_bfloat16 *qhi, *khi, *vhi;
    const float* lgk;
    __nv_bfloat16* ohi;
    int Tq, Tk, b;
    if (z < BATCH) {
        if (blockIdx.x >= NX / 128) return;
        b = z; qhi = qx; khi = kyv; vhi = vyv; lgk = lgy_; ohi = ax; Tq = NX; Tk = NY;
    } else {
        b = z - BATCH; qhi = qy; khi = kxv; vhi = vxv; lgk = lgx_; ohi = ay; Tq = NY; Tk = NX;
    }

    extern __shared__ char smem[];
    const uint32_t sb = smem_u32(smem);
    const int tid = threadIdx.x;
    const int wid = tid >> 5;
    const int lane = tid & 31;
    const int h = blockIdx.y;
    const int bq = blockIdx.x * 128;
    const int wm = wid * 16;
    const int rofs = ((lane >> 3) & 1) * 8 + (lane & 7);
    const int kofs = ((lane >> 4) & 1) * 16;

    #pragma unroll
    for (int i = 0; i < 4; i++) {
        int idx = tid + i * 256;
        int r = idx >> 3, f = idx & 7;
        uint32_t so = SMEM_SWIZZLE_128B((uint32_t)(r * 128 + f * 16));
        size_t g = (size_t)(b * Tq + bq + r) * DMODEL + h * DK;
        *(uint4*)(smem + so) = ((const uint4*)(qhi + g))[f];
    }
    att_load_kv(sb, 0, 0, b, h, Tk, khi, vhi, lgk, tid);
    CP_COMMIT();
    __syncthreads();

    uint32_t qfh[4][4];
    #pragma unroll
    for (int ks = 0; ks < 4; ks++)
        ldsm_x4(qfh[ks], sb + SMEM_SWIZZLE_128B((uint32_t)((wm + rofs) * 128 + ks * 32 + kofs)));

    float o[8][4];
    #pragma unroll
    for (int t = 0; t < 8; t++)
        #pragma unroll
        for (int c = 0; c < 4; c++) o[t][c] = 0.f;
    float l0 = 0.f, l1 = 0.f;

    const int ntile = Tk / 64;
    for (int kt = 0; kt < ntile; kt++) {
        const int s = kt & 1;
        CP_WAIT0();
        __syncthreads();
        if (kt + 1 < ntile) {
            att_load_kv(sb, s ^ 1, kt + 1, b, h, Tk, khi, vhi, lgk, tid);
            CP_COMMIT();
        }
        const uint32_t sK = sb + 16384 + s * 16384;
        const uint32_t sV = sK + 8192;
        const float* lgs = (const float*)(smem + 49152 + s * 256);

        // ---- S = Q K^T ----
        float sd[8][4];
        #pragma unroll
        for (int nt = 0; nt < 8; nt++)
            #pragma unroll
            for (int c = 0; c < 4; c++) sd[nt][c] = 0.f;

        #pragma unroll
        for (int ks = 0; ks < 4; ks++) {
            uint32_t bh[8][2];
            #pragma unroll
            for (int p = 0; p < 4; p++) {
                uint32_t t[4];
                ldsm_x4(t, sK + SMEM_SWIZZLE_128B((uint32_t)((p * 16 + rofs) * 128 + ks * 32 + kofs)));
                bh[2 * p][0] = t[0]; bh[2 * p][1] = t[2];
                bh[2 * p + 1][0] = t[1]; bh[2 * p + 1][1] = t[3];
            }
            #pragma unroll
            for (int nt = 0; nt < 8; nt++)
                mma16816(sd[nt], qfh[ks], bh[nt]);
        }

        // ---- unnormalized base-2 softmax (no max; scores bounded) ----
        #pragma unroll
        for (int nt = 0; nt < 8; nt++) {
            int col = nt * 8 + (lane & 3) * 2;
            float lg0 = lgs[col], lg1 = lgs[col + 1];
            float p0 = ex2f(sd[nt][0] + lg0);
            float p1 = ex2f(sd[nt][1] + lg1);
            float p2 = ex2f(sd[nt][2] + lg0);
            float p3 = ex2f(sd[nt][3] + lg1);
            sd[nt][0] = p0; sd[nt][1] = p1; sd[nt][2] = p2; sd[nt][3] = p3;
            l0 += p0 + p1;
            l1 += p2 + p3;
        }

        // ---- O += P V ----
        #pragma unroll
        for (int kb = 0; kb < 4; kb++) {
            uint32_t pah[4];
            pah[0] = packbf(sd[2 * kb][0],     sd[2 * kb][1]);
            pah[1] = packbf(sd[2 * kb][2],     sd[2 * kb][3]);
            pah[2] = packbf(sd[2 * kb + 1][0], sd[2 * kb + 1][1]);
            pah[3] = packbf(sd[2 * kb + 1][2], sd[2 * kb + 1][3]);
            const int t4 = lane >> 3;
            #pragma unroll
            for (int dp = 0; dp < 4; dp++) {
                uint32_t so = SMEM_SWIZZLE_128B((uint32_t)(
                    (kb * 16 + (t4 & 1) * 8 + (lane & 7)) * 128 +
                    (dp * 16 + (t4 >> 1) * 8) * 2));
                uint32_t vh4[4];
                ldsm_x4_t(vh4, sV + so);
                uint32_t b0h[2] = {vh4[0], vh4[1]}, b1h[2] = {vh4[2], vh4[3]};
                mma16816(o[2 * dp],     pah, b0h);
                mma16816(o[2 * dp + 1], pah, b1h);
            }
        }
    }

    // ---- finalize ----
    float fl0 = l0 + __shfl_xor_sync(0xffffffffu, l0, 1);
    fl0 += __shfl_xor_sync(0xffffffffu, fl0, 2);
    float fl1 = l1 + __shfl_xor_sync(0xffffffffu, l1, 1);
    fl1 += __shfl_xor_sync(0xffffffffu, fl1, 2);
    float inv0 = 1.0f / fl0, inv1 = 1.0f / fl1;

    const int r0 = bq + wm + (lane >> 2);
    size_t base0 = (size_t)(b * Tq + r0) * DMODEL + h * DK;
    size_t base1 = base0 + (size_t)8 * DMODEL;
    #pragma unroll
    for (int t = 0; t < 8; t++) {
        int col = t * 8 + (lane & 3) * 2;
        *(uint32_t*)&ohi[base0 + col] = packbf(o[t][0] * inv0, o[t][1] * inv0);
        *(uint32_t*)&ohi[base1 + col] = packbf(o[t][2] * inv1, o[t][3] * inv1);
    }
}

// ---------------- launch ----------------
extern "C" void kernel_launch(void* const* d_in, const int* in_sizes, int n_in,
                              void* d_out, int out_size)
{
    const float* x    = (const float*)d_in[0];
    const float* y    = (const float*)d_in[1];
    const float* Wqx  = (const float*)d_in[4];
    const float* Wkx  = (const float*)d_in[5];
    const float* Wvx  = (const float*)d_in[6];
    const float* Wqy  = (const float*)d_in[7];
    const float* Wky  = (const float*)d_in[8];
    const float* Wvy  = (const float*)d_in[9];
    const float* gWx  = (const float*)d_in[10];
    const float* gbx  = (const float*)d_in[11];
    const float* gWy  = (const float*)d_in[12];
    const float* gby  = (const float*)d_in[13];
    const float* Wox  = (const float*)d_in[14];
    const float* Woy  = (const float*)d_in[15];
    const float* lnxg = (const float*)d_in[16];
    const float* lnxb = (const float*)d_in[17];
    const float* lnyg = (const float*)d_in[18];
    const float* lnyb = (const float*)d_in[19];
    const float* ffxW = (const float*)d_in[20];
    const float* ffxb = (const float*)d_in[21];
    const float* ffyW = (const float*)d_in[22];
    const float* ffyb = (const float*)d_in[23];
    float* out = (float*)d_out;

    float *lgx, *lgy;
    __nv_bfloat16 *xhi, *yhi;
    __nv_bfloat16 *qxhi, *kxhi, *vxhi, *qyhi, *kyhi, *vyhi;
    __nv_bfloat16 *axhi, *ayhi;
    __nv_bfloat16 *x2ahi, *x2alo, *y2ahi, *y2alo, *whi, *wlo;
    cudaGetSymbolAddress((void**)&lgx, g_lgx);
    cudaGetSymbolAddress((void**)&lgy, g_lgy);
    cudaGetSymbolAddress((void**)&xhi, g_xhi);
    cudaGetSymbolAddress((void**)&yhi, g_yhi);
    cudaGetSymbolAddress((void**)&qxhi, g_qxhi);
    cudaGetSymbolAddress((void**)&kxhi, g_kxhi);
    cudaGetSymbolAddress((void**)&vxhi, g_vxhi);
    cudaGetSymbolAddress((void**)&qyhi, g_qyhi);
    cudaGetSymbolAddress((void**)&kyhi, g_kyhi);
    cudaGetSymbolAddress((void**)&vyhi, g_vyhi);
    cudaGetSymbolAddress((void**)&axhi, g_axhi);
    cudaGetSymbolAddress((void**)&ayhi, g_ayhi);
    cudaGetSymbolAddress((void**)&x2ahi, g_x2ahi);
    cudaGetSymbolAddress((void**)&x2alo, g_x2alo);
    cudaGetSymbolAddress((void**)&y2ahi, g_y2ahi);
    cudaGetSymbolAddress((void**)&y2alo, g_y2alo);
    cudaGetSymbolAddress((void**)&whi, g_whi);
    cudaGetSymbolAddress((void**)&wlo, g_wlo);

    cudaFuncSetAttribute(mma_gemm, cudaFuncAttributeMaxDynamicSharedMemorySize, SMEM_GEMM_DYN);
    cudaFuncSetAttribute((gemm_ln<0>), cudaFuncAttributeMaxDynamicSharedMemorySize, SMEM_GLN0);
    cudaFuncSetAttribute((gemm_ln<1>), cudaFuncAttributeMaxDynamicSharedMemorySize, SMEM_GLN1);
    cudaFuncSetAttribute(mma_attn, cudaFuncAttributeMaxDynamicSharedMemorySize, ATT_SMEM);

    const int WSZ = DMODEL * DMODEL;  // 65536
    const float QSCL = 0.125f * 1.44269504088896f;   // (1/sqrt(64)) * log2(e)

    // 1) fused split(hi) + gate (emits log2(g)); weight split
    split_gate2<<<(MX + MY) / 8, 256>>>(x, y, xhi, yhi, gWx, gbx, gWy, gby,
                                        out + OFF_GX, lgx, out + OFF_GY, lgy);
    WSrc ws;
    ws.s[0] = Wqx; ws.s[1] = Wkx; ws.s[2] = Wvx;
    ws.s[3] = Wqy; ws.s[4] = Wky; ws.s[5] = Wvy;
    ws.s[6] = Wox; ws.s[7] = Woy; ws.s[8] = ffxW; ws.s[9] = ffyW;
    wsplit_kernel<<<dim3(WSZ / 4 / 256, 10), 256>>>(ws, whi, wlo);

    // 2) QKV projections (x+y combined; q pre-scaled into log2 domain)
    {
        GemmArgs6 a = {};
        a.Ax = xhi; a.Ay = yhi;
        a.Whi[0] = whi + 0 * WSZ; a.Chi[0] = qxhi; a.scl[0] = QSCL;
        a.Whi[1] = whi + 1 * WSZ; a.Chi[1] = kxhi; a.scl[1] = 1.f;
        a.Whi[2] = whi + 2 * WSZ; a.Chi[2] = vxhi; a.scl[2] = 1.f;
        a.Whi[3] = whi + 3 * WSZ; a.Chi[3] = qyhi; a.scl[3] = QSCL;
        a.Whi[4] = whi + 4 * WSZ; a.Chi[4] = kyhi; a.scl[4] = 1.f;
        a.Whi[5] = whi + 5 * WSZ; a.Chi[5] = vyhi; a.scl[5] = 1.f;
        mma_gemm<<<dim3(2, MY / 128, 6), 256, SMEM_GEMM_DYN>>>(a);
    }

    // 3) attention (x+y combined, base-2 softmax)
    mma_attn<<<dim3(NY / 128, NHEAD, 2 * BATCH), 256, ATT_SMEM>>>(
        qxhi, kyhi, vyhi, lgy, axhi,
        qyhi, kxhi, vxhi, lgx, ayhi);

    // 4) fused oproj(1-term) + residual + LN (x+y combined; emits splits)
    {
        LNArgs a = {};
        a.Ahi[0] = axhi;          a.Ahi[1] = ayhi;
        a.Whi[0] = whi + 6 * WSZ; a.Whi[1] = whi + 7 * WSZ;
        a.resid_f32[0] = x;       a.resid_f32[1] = y;
        a.gamma[0] = lnxg;        a.gamma[1] = lnyg;
        a.beta[0] = lnxb;         a.beta[1] = lnyb;
        a.ohi[0] = x2ahi;         a.ohi[1] = y2ahi;
        a.olo[0] = x2alo;         a.olo[1] = y2alo;
        a.nblk0 = MX / 64;
        gemm_ln<0><<<(MX + MY) / 64, 256, SMEM_GLN0>>>(a);
    }

    // 5) fused FF(3-term, silu) + residual + LN -> final output (x+y combined)
    {
        LNArgs a = {};
        a.Ahi[0] = x2ahi;         a.Ahi[1] = y2ahi;
        a.Alo[0] = x2alo;         a.Alo[1] = y2alo;
        a.Whi[0] = whi + 8 * WSZ; a.Whi[1] = whi + 9 * WSZ;
        a.Wlo[0] = wlo + 8 * WSZ; a.Wlo[1] = wlo + 9 * WSZ;
        a.bias[0] = ffxb;         a.bias[1] = ffyb;
        a.rhi[0] = x2ahi;         a.rhi[1] = y2ahi;
        a.rlo[0] = x2alo;         a.rlo[1] = y2alo;
        a.gamma[0] = lnxg;        a.gamma[1] = lnyg;
        a.beta[0] = lnxb;         a.beta[1] = lnyb;
        a.out_f32[0] = out + OFF_X2;
        a.out_f32[1] = out + OFF_Y2;
        a.nblk0 = MX / 64;
        gemm_ln<1><<<(MX + MY) / 64, 256, SMEM_GLN1>>>(a);
    }
}